// round 2
// baseline (speedup 1.0000x reference)
#include <cuda_runtime.h>
#include <cuda_bf16.h>
#include <cstdint>

// Problem constants
#define BATCH 4
#define SEQ   2048
#define DIM   1024
#define HEADS 16
#define HDIM  64
#define MTOK  (BATCH * SEQ)          // 8192 tokens
#define SCALE 0.125f                 // 64^-0.5

// Scratch (no allocations allowed)
__device__ float g_qkv[(size_t)MTOK * 3 * DIM];   // 96 MB
__device__ float g_att[(size_t)MTOK * DIM];       // 32 MB

// ---------------------------------------------------------------------------
// GEMM: C[M,N] = A[M,K] @ W[K,N] + bias[N].   M%128==0, N%128==0, K%16==0
// 128x128x16 register-tiled SGEMM, 256 threads, 8x8 per thread.
// ---------------------------------------------------------------------------
#define GBM 128
#define GBN 128
#define GBK 16

__global__ __launch_bounds__(256) void gemm_bias_kernel(
    const float* __restrict__ A, const float* __restrict__ W,
    const float* __restrict__ bias, float* __restrict__ C,
    int M, int N, int K)
{
    __shared__ float As[GBK][GBM];   // transposed A tile
    __shared__ float Bs[GBK][GBN];

    const int tid  = threadIdx.x;
    const int bm   = blockIdx.y * GBM;
    const int bn   = blockIdx.x * GBN;
    const int trow = (tid >> 4) * 8;     // 0..120
    const int tcol = (tid & 15) * 8;     // 0..120

    // A tile loads: 128 rows x 16 cols = 2048 floats = 256 threads * 2 float4
    const int aRow = tid >> 1;           // 0..127
    const int aCol = (tid & 1) * 8;      // 0 or 8
    // B tile loads: 16 rows x 128 cols = 2048 floats = 256 threads * 2 float4
    const int bRow = tid >> 5;           // 0..7   (and +8)
    const int bCol = (tid & 31) * 4;     // 0..124

    const float* Aptr = A + (size_t)(bm + aRow) * K + aCol;
    const float* Wptr = W + (size_t)bRow * N + bn + bCol;

    float acc[8][8];
#pragma unroll
    for (int i = 0; i < 8; i++)
#pragma unroll
        for (int j = 0; j < 8; j++) acc[i][j] = 0.f;

    for (int k0 = 0; k0 < K; k0 += GBK) {
        float4 av0 = *reinterpret_cast<const float4*>(Aptr + k0);
        float4 av1 = *reinterpret_cast<const float4*>(Aptr + k0 + 4);
        As[aCol + 0][aRow] = av0.x;
        As[aCol + 1][aRow] = av0.y;
        As[aCol + 2][aRow] = av0.z;
        As[aCol + 3][aRow] = av0.w;
        As[aCol + 4][aRow] = av1.x;
        As[aCol + 5][aRow] = av1.y;
        As[aCol + 6][aRow] = av1.z;
        As[aCol + 7][aRow] = av1.w;
        *reinterpret_cast<float4*>(&Bs[bRow][bCol]) =
            *reinterpret_cast<const float4*>(Wptr + (size_t)k0 * N);
        *reinterpret_cast<float4*>(&Bs[bRow + 8][bCol]) =
            *reinterpret_cast<const float4*>(Wptr + (size_t)(k0 + 8) * N);
        __syncthreads();

#pragma unroll
        for (int k = 0; k < GBK; k++) {
            float rm[8], rn[8];
            *reinterpret_cast<float4*>(&rm[0]) = *reinterpret_cast<float4*>(&As[k][trow]);
            *reinterpret_cast<float4*>(&rm[4]) = *reinterpret_cast<float4*>(&As[k][trow + 4]);
            *reinterpret_cast<float4*>(&rn[0]) = *reinterpret_cast<float4*>(&Bs[k][tcol]);
            *reinterpret_cast<float4*>(&rn[4]) = *reinterpret_cast<float4*>(&Bs[k][tcol + 4]);
#pragma unroll
            for (int i = 0; i < 8; i++)
#pragma unroll
                for (int j = 0; j < 8; j++)
                    acc[i][j] += rm[i] * rn[j];
        }
        __syncthreads();
    }

#pragma unroll
    for (int i = 0; i < 8; i++) {
#pragma unroll
        for (int j = 0; j < 8; j += 4) {
            float4 v;
            v.x = acc[i][j + 0] + bias[bn + tcol + j + 0];
            v.y = acc[i][j + 1] + bias[bn + tcol + j + 1];
            v.z = acc[i][j + 2] + bias[bn + tcol + j + 2];
            v.w = acc[i][j + 3] + bias[bn + tcol + j + 3];
            *reinterpret_cast<float4*>(&C[(size_t)(bm + trow + i) * N + bn + tcol + j]) = v;
        }
    }
}

// ---------------------------------------------------------------------------
// Flash attention (fp32). One CTA = 64 query rows of one (batch, head).
// 256 threads, 16x16 thread grid, 4x4 micro-tile per thread.
// Smem tiles (stride 68 to kill bank conflicts):
//   Qt[k][r]  (Q transposed, pre-scaled by SCALE)
//   Kt[k][j]  (K transposed)
//   Vs[j][c]
//   Ps[r][j]  (probabilities for PV)
// ---------------------------------------------------------------------------
#define ASTR 68
#define ATTN_SMEM (4 * 64 * ASTR * 4)

__global__ __launch_bounds__(256) void attn_kernel(
    const float* __restrict__ qkv, float* __restrict__ out)
{
    extern __shared__ float sm[];
    float* Qt = sm;
    float* Kt = sm + 64 * ASTR;
    float* Vs = sm + 2 * 64 * ASTR;
    float* Ps = sm + 3 * 64 * ASTR;

    const int tid = threadIdx.x;
    const int tx  = tid & 15;        // col group
    const int ty  = tid >> 4;        // row group
    const int qb  = blockIdx.x;      // query block (0..31)
    const int h   = blockIdx.y;      // head
    const int b   = blockIdx.z;      // batch
    const int q0  = qb * 64;

    const float* base = qkv + (size_t)b * SEQ * (3 * DIM) + h * HDIM;

    // Load Q transposed, pre-scaled
    for (int idx = tid; idx < 64 * 64; idx += 256) {
        int kd = idx & 63, r = idx >> 6;
        Qt[kd * ASTR + r] = base[(size_t)(q0 + r) * (3 * DIM) + kd] * SCALE;
    }

    float m[4], l[4], o[4][4];
#pragma unroll
    for (int i = 0; i < 4; i++) {
        m[i] = -1e30f; l[i] = 0.f;
#pragma unroll
        for (int j = 0; j < 4; j++) o[i][j] = 0.f;
    }

    for (int kb = 0; kb < SEQ; kb += 64) {
        // Load K transposed and V
        for (int idx = tid; idx < 64 * 64; idx += 256) {
            int kd = idx & 63, j = idx >> 6;
            Kt[kd * ASTR + j] = base[(size_t)(kb + j) * (3 * DIM) + DIM + kd];
        }
        for (int idx = tid; idx < 64 * 64; idx += 256) {
            int c = idx & 63, j = idx >> 6;
            Vs[j * ASTR + c] = base[(size_t)(kb + j) * (3 * DIM) + 2 * DIM + c];
        }
        __syncthreads();

        // S = (Q*SCALE) @ K^T  (4x4 per thread)
        float s[4][4];
#pragma unroll
        for (int i = 0; i < 4; i++)
#pragma unroll
            for (int j = 0; j < 4; j++) s[i][j] = 0.f;

#pragma unroll 4
        for (int k = 0; k < 64; k++) {
            float4 qv = *reinterpret_cast<const float4*>(&Qt[k * ASTR + ty * 4]);
            float4 kv = *reinterpret_cast<const float4*>(&Kt[k * ASTR + tx * 4]);
            float rq[4] = {qv.x, qv.y, qv.z, qv.w};
            float rk[4] = {kv.x, kv.y, kv.z, kv.w};
#pragma unroll
            for (int i = 0; i < 4; i++)
#pragma unroll
                for (int j = 0; j < 4; j++)
                    s[i][j] += rq[i] * rk[j];
        }

        // Online softmax, per row (reduce across the 16 threads of a row group)
#pragma unroll
        for (int i = 0; i < 4; i++) {
            float mloc = fmaxf(fmaxf(s[i][0], s[i][1]), fmaxf(s[i][2], s[i][3]));
#pragma unroll
            for (int d = 8; d >= 1; d >>= 1)
                mloc = fmaxf(mloc, __shfl_xor_sync(0xffffffffu, mloc, d));
            float mnew  = fmaxf(m[i], mloc);
            float alpha = __expf(m[i] - mnew);
            m[i] = mnew;
            float p0 = __expf(s[i][0] - mnew);
            float p1 = __expf(s[i][1] - mnew);
            float p2 = __expf(s[i][2] - mnew);
            float p3 = __expf(s[i][3] - mnew);
            float rs = p0 + p1 + p2 + p3;
#pragma unroll
            for (int d = 8; d >= 1; d >>= 1)
                rs += __shfl_xor_sync(0xffffffffu, rs, d);
            l[i] = l[i] * alpha + rs;
#pragma unroll
            for (int j = 0; j < 4; j++) o[i][j] *= alpha;
            float4 pv = make_float4(p0, p1, p2, p3);
            *reinterpret_cast<float4*>(&Ps[(ty * 4 + i) * ASTR + tx * 4]) = pv;
        }
        __syncwarp();   // Ps rows are produced & consumed within the same warp

        // O += P @ V
#pragma unroll 4
        for (int j = 0; j < 64; j++) {
            float4 vv = *reinterpret_cast<const float4*>(&Vs[j * ASTR + tx * 4]);
            float pr0 = Ps[(ty * 4 + 0) * ASTR + j];
            float pr1 = Ps[(ty * 4 + 1) * ASTR + j];
            float pr2 = Ps[(ty * 4 + 2) * ASTR + j];
            float pr3 = Ps[(ty * 4 + 3) * ASTR + j];
            o[0][0] += pr0 * vv.x; o[0][1] += pr0 * vv.y; o[0][2] += pr0 * vv.z; o[0][3] += pr0 * vv.w;
            o[1][0] += pr1 * vv.x; o[1][1] += pr1 * vv.y; o[1][2] += pr1 * vv.z; o[1][3] += pr1 * vv.w;
            o[2][0] += pr2 * vv.x; o[2][1] += pr2 * vv.y; o[2][2] += pr2 * vv.z; o[2][3] += pr2 * vv.w;
            o[3][0] += pr3 * vv.x; o[3][1] += pr3 * vv.y; o[3][2] += pr3 * vv.z; o[3][3] += pr3 * vv.w;
        }
        __syncthreads();   // protect Kt/Vs reuse in next iteration
    }

    // Write O / l  to g_att[b, q0+r, h*64 + c]
#pragma unroll
    for (int i = 0; i < 4; i++) {
        float inv = 1.0f / l[i];
        float4 v = make_float4(o[i][0] * inv, o[i][1] * inv, o[i][2] * inv, o[i][3] * inv);
        *reinterpret_cast<float4*>(
            &out[(size_t)(b * SEQ + q0 + ty * 4 + i) * DIM + h * HDIM + tx * 4]) = v;
    }
}

// ---------------------------------------------------------------------------
// Launch
// ---------------------------------------------------------------------------
extern "C" void kernel_launch(void* const* d_in, const int* in_sizes, int n_in,
                              void* d_out, int out_size)
{
    const float* x     = (const float*)d_in[0];
    const float* W_qkv = (const float*)d_in[1];
    const float* b_qkv = (const float*)d_in[2];
    const float* W_out = (const float*)d_in[3];
    const float* b_out = (const float*)d_in[4];
    float* out = (float*)d_out;

    float* qkv; cudaGetSymbolAddress((void**)&qkv, g_qkv);
    float* att; cudaGetSymbolAddress((void**)&att, g_att);

    cudaFuncSetAttribute(attn_kernel, cudaFuncAttributeMaxDynamicSharedMemorySize, ATTN_SMEM);

    // 1. qkv = x @ W_qkv + b_qkv       (8192 x 3072 x 1024)
    gemm_bias_kernel<<<dim3(3 * DIM / GBN, MTOK / GBM), 256>>>(
        x, W_qkv, b_qkv, qkv, MTOK, 3 * DIM, DIM);

    // 2. attention
    attn_kernel<<<dim3(SEQ / 64, HEADS, BATCH), 256, ATTN_SMEM>>>(qkv, att);

    // 3. out = att @ W_out + b_out     (8192 x 1024 x 1024)
    gemm_bias_kernel<<<dim3(DIM / GBN, MTOK / GBM), 256>>>(
        att, W_out, b_out, out, MTOK, DIM, DIM);
}

// round 4
// speedup vs baseline: 2.3849x; 2.3849x over previous
#include <cuda_runtime.h>
#include <cuda_bf16.h>
#include <cuda_fp16.h>
#include <cstdint>

// ---------------------------------------------------------------------------
// Problem constants
// ---------------------------------------------------------------------------
#define BATCH 4
#define SEQ   2048
#define NHEAD 16
#define HDIM  64
#define DMODEL 1024
#define MTOK  (BATCH * SEQ)              // 8192
#define NBH   (BATCH * NHEAD)            // 64
#define ATTN_SCALE 0.125f

typedef unsigned short ushort_t;

// ---------------------------------------------------------------------------
// Scratch (static device globals; no allocations allowed)
// ---------------------------------------------------------------------------
__device__ float          g_qkv[(size_t)MTOK * 3 * DMODEL];          // 96 MB
__device__ __nv_bfloat16  g_xh[(size_t)MTOK * DMODEL];
__device__ __nv_bfloat16  g_xl[(size_t)MTOK * DMODEL];
__device__ __nv_bfloat16  g_wqt_h[(size_t)3 * DMODEL * DMODEL];      // W_qkv^T hi
__device__ __nv_bfloat16  g_wqt_l[(size_t)3 * DMODEL * DMODEL];      // W_qkv^T lo
__device__ __nv_bfloat16  g_wot_h[(size_t)DMODEL * DMODEL];          // W_out^T hi
__device__ __nv_bfloat16  g_wot_l[(size_t)DMODEL * DMODEL];          // W_out^T lo
__device__ __half         g_q16[(size_t)NBH * SEQ * HDIM];           // Q fp16 per head
__device__ __half         g_k16[(size_t)NBH * SEQ * HDIM];           // K fp16 per head
__device__ __half         g_vt[(size_t)NBH * HDIM * SEQ];            // V^T fp16 per head
__device__ float          g_s[(size_t)NBH * SEQ * SEQ];              // 1 GB scores fp32
__device__ __half         g_p[(size_t)NBH * SEQ * SEQ];              // 512 MB probs fp16
__device__ float          g_att[(size_t)MTOK * DMODEL];              // 32 MB
__device__ __nv_bfloat16  g_ah[(size_t)MTOK * DMODEL];
__device__ __nv_bfloat16  g_al[(size_t)MTOK * DMODEL];

// ---------------------------------------------------------------------------
// PTX helpers (all baseline-PTX: cp.async / ldmatrix / mma.sync)
// ---------------------------------------------------------------------------
__device__ __forceinline__ uint32_t smem_u32(const void* p) {
    uint32_t a;
    asm("{ .reg .u64 t; cvta.to.shared.u64 t, %1; cvt.u32.u64 %0, t; }" : "=r"(a) : "l"(p));
    return a;
}
__device__ __forceinline__ void cp16(uint32_t dst, const void* src) {
    asm volatile("cp.async.cg.shared.global [%0], [%1], 16;" :: "r"(dst), "l"(src) : "memory");
}
#define CP_COMMIT() asm volatile("cp.async.commit_group;" ::: "memory")
#define CP_WAIT0()  asm volatile("cp.async.wait_group 0;" ::: "memory")

__device__ __forceinline__ void ldm4(uint32_t a, uint32_t& r0, uint32_t& r1,
                                     uint32_t& r2, uint32_t& r3) {
    asm volatile("ldmatrix.sync.aligned.m8n8.x4.shared.b16 {%0,%1,%2,%3}, [%4];"
                 : "=r"(r0), "=r"(r1), "=r"(r2), "=r"(r3) : "r"(a));
}

template<bool FP16>
__device__ __forceinline__ void mma16816(float* c, const uint32_t* a,
                                         uint32_t b0, uint32_t b1) {
    if (FP16) {
        asm volatile(
            "mma.sync.aligned.m16n8k16.row.col.f32.f16.f16.f32 "
            "{%0,%1,%2,%3},{%4,%5,%6,%7},{%8,%9},{%0,%1,%2,%3};"
            : "+f"(c[0]), "+f"(c[1]), "+f"(c[2]), "+f"(c[3])
            : "r"(a[0]), "r"(a[1]), "r"(a[2]), "r"(a[3]), "r"(b0), "r"(b1));
    } else {
        asm volatile(
            "mma.sync.aligned.m16n8k16.row.col.f32.bf16.bf16.f32 "
            "{%0,%1,%2,%3},{%4,%5,%6,%7},{%8,%9},{%0,%1,%2,%3};"
            : "+f"(c[0]), "+f"(c[1]), "+f"(c[2]), "+f"(c[3])
            : "r"(a[0]), "r"(a[1]), "r"(a[2]), "r"(a[3]), "r"(b0), "r"(b1));
    }
}

// ---------------------------------------------------------------------------
// mma.sync GEMM:  C[M][N] = scale * (sum over NPASS of Ap · Bp^T) + bias
//   A[*][K], B[*][K] 2-byte k-major.  CTA tile 128(M) x 64(N), K-stage 32,
//   8 warps in 4(m) x 2(n), each 32x32, mma m16n8k16, cp.async double buffer.
//   Batched over blockIdx.z; C offset = zb*CzbStr + zl*CzlStr (zb=z/ZLO).
// ---------------------------------------------------------------------------
#define STR 40   // halves per smem row (32 data + 8 pad) -> conflict-free ldmatrix

template<bool FP16, int NPASS>
__global__ __launch_bounds__(256) void mma_gemm(
    const ushort_t* __restrict__ A0, const ushort_t* __restrict__ A1,
    const ushort_t* __restrict__ A2,
    const ushort_t* __restrict__ B0, const ushort_t* __restrict__ B1,
    const ushort_t* __restrict__ B2,
    float* __restrict__ C, const float* __restrict__ bias, float scale,
    int K, long long AzStr, long long BzStr,
    long long CzbStr, long long CzlStr, int ZLO, int ldc)
{
    __shared__ __align__(16) ushort_t As[2][128 * STR];
    __shared__ __align__(16) ushort_t Bs[2][64 * STR];

    const int tid = threadIdx.x, lane = tid & 31, wid = tid >> 5;
    const int wm = wid & 3, wn = wid >> 2;
    const int m0 = blockIdx.y * 128, n0 = blockIdx.x * 64, z = blockIdx.z;
    const int zb = z / ZLO, zl = z % ZLO;
    const size_t az = (size_t)z * AzStr, bz = (size_t)z * BzStr;
    const int CPP = K / 32;
    const int NC  = NPASS * CPP;

    const uint32_t asb = smem_u32(As), bsb = smem_u32(Bs);

    float acc[2][4][4];
#pragma unroll
    for (int mi = 0; mi < 2; mi++)
#pragma unroll
        for (int j = 0; j < 4; j++)
#pragma unroll
            for (int r = 0; r < 4; r++) acc[mi][j][r] = 0.f;

    // cp.async addressing: A 512 chunks (2/thread), B 256 chunks (1/thread)
    const int arow = tid >> 2, ach = tid & 3;     // rows 0..63 (+64), 16B chunk id

    auto load_stage = [&](int s, int buf) {
        int p = s / CPP, kc = s - p * CPP, k0 = kc * 32;
        const ushort_t* Ap = (p == 0 ? A0 : (p == 1 ? A1 : A2)) + az;
        const ushort_t* Bp = (p == 0 ? B0 : (p == 1 ? B1 : B2)) + bz;
        uint32_t ad = asb + buf * (128 * STR * 2);
        uint32_t bd = bsb + buf * (64 * STR * 2);
        cp16(ad + (arow * STR + ach * 8) * 2,
             Ap + (size_t)(m0 + arow) * K + k0 + ach * 8);
        cp16(ad + ((arow + 64) * STR + ach * 8) * 2,
             Ap + (size_t)(m0 + arow + 64) * K + k0 + ach * 8);
        cp16(bd + (arow * STR + ach * 8) * 2,
             Bp + (size_t)(n0 + arow) * K + k0 + ach * 8);
        CP_COMMIT();
    };

    load_stage(0, 0);

    // ldmatrix lane->tile decomposition (x4: tiles [m/n +0/+8] x [k +0/+8])
    const int lr = (lane & 7) + (((lane >> 3) & 1) << 3);  // row within 16
    const int lc = ((lane >> 4) & 1) << 3;                 // col (k) offset

    for (int c = 0; c < NC; ++c) {
        const int buf = c & 1;
        CP_WAIT0();
        __syncthreads();
        if (c + 1 < NC) load_stage(c + 1, buf ^ 1);

        const uint32_t ab = asb + buf * (128 * STR * 2);
        const uint32_t bb = bsb + buf * (64 * STR * 2);

#pragma unroll
        for (int kk = 0; kk < 32; kk += 16) {
            uint32_t a[2][4], b[2][4];
#pragma unroll
            for (int mi = 0; mi < 2; mi++) {
                uint32_t adr = ab + ((wm * 32 + mi * 16 + lr) * STR + kk + lc) * 2;
                ldm4(adr, a[mi][0], a[mi][1], a[mi][2], a[mi][3]);
            }
#pragma unroll
            for (int nb = 0; nb < 2; nb++) {
                uint32_t bdr = bb + ((wn * 32 + nb * 16 + lr) * STR + kk + lc) * 2;
                ldm4(bdr, b[nb][0], b[nb][1], b[nb][2], b[nb][3]);
            }
            // b regs: r0=(n+0,klo) r1=(n+8,klo) r2=(n+0,khi) r3=(n+8,khi)
#pragma unroll
            for (int mi = 0; mi < 2; mi++)
#pragma unroll
                for (int j = 0; j < 4; j++) {
                    int nb = j >> 1, hi = j & 1;
                    mma16816<FP16>(acc[mi][j], a[mi], b[nb][hi], b[nb][2 + hi]);
                }
        }
        __syncthreads();
    }

    // epilogue: frag (mi,j): rows m0+wm*32+mi*16+(lane>>2)(+8), cols +2*(lane&3)
    const int rq = lane >> 2, cq = (lane & 3) * 2;
    float* Cz = C + (size_t)zb * CzbStr + (size_t)zl * CzlStr;
#pragma unroll
    for (int mi = 0; mi < 2; mi++)
#pragma unroll
        for (int j = 0; j < 4; j++) {
            int row = m0 + wm * 32 + mi * 16 + rq;
            int col = n0 + wn * 32 + j * 8 + cq;
            float bx = 0.f, by = 0.f;
            if (bias) { bx = bias[col]; by = bias[col + 1]; }
            float2 v0 = make_float2(acc[mi][j][0] * scale + bx,
                                    acc[mi][j][1] * scale + by);
            float2 v1 = make_float2(acc[mi][j][2] * scale + bx,
                                    acc[mi][j][3] * scale + by);
            *(float2*)(Cz + (size_t)row * ldc + col) = v0;
            *(float2*)(Cz + (size_t)(row + 8) * ldc + col) = v1;
        }
}

// ---------------------------------------------------------------------------
// Conversion kernels
// ---------------------------------------------------------------------------
__global__ void split_pair_kernel(const float* __restrict__ x,
                                  __nv_bfloat16* __restrict__ h,
                                  __nv_bfloat16* __restrict__ l, size_t n)
{
    for (size_t i = (size_t)blockIdx.x * blockDim.x + threadIdx.x; i < n;
         i += (size_t)gridDim.x * blockDim.x) {
        float v = x[i];
        __nv_bfloat16 hi = __float2bfloat16(v);
        h[i] = hi;
        l[i] = __float2bfloat16(v - __bfloat162float(hi));
    }
}

// W[K][N] -> Wt hi/lo [N][K]
__global__ void wtrans_split_kernel(const float* __restrict__ W,
                                    __nv_bfloat16* __restrict__ Th,
                                    __nv_bfloat16* __restrict__ Tl, int K, int N)
{
    __shared__ float t[32][33];
    int kx = blockIdx.y * 32, nx = blockIdx.x * 32;
    int tx = threadIdx.x, ty = threadIdx.y;   // (32, 8)
#pragma unroll
    for (int i = 0; i < 4; i++)
        t[ty + 8 * i][tx] = W[(size_t)(kx + ty + 8 * i) * N + nx + tx];
    __syncthreads();
#pragma unroll
    for (int i = 0; i < 4; i++) {
        int nl = ty + 8 * i;
        float v = t[tx][nl];
        __nv_bfloat16 hi = __float2bfloat16(v);
        size_t o = (size_t)(nx + nl) * K + kx + tx;
        Th[o] = hi;
        Tl[o] = __float2bfloat16(v - __bfloat162float(hi));
    }
}

// qkv[8192][3072] -> per (b,h): q/k fp16 [z][2048][64], v fp16 transposed [z][64][2048]
__global__ void split_qkv_kernel(const float* __restrict__ qkv,
                                 __half* __restrict__ q16, __half* __restrict__ k16,
                                 __half* __restrict__ vt)
{
    __shared__ float vs[64][65];
    const int z = blockIdx.y;
    const int b = z >> 4, h = z & 15;
    const int q0 = blockIdx.x * 64;
    const int tid = threadIdx.x;
    const float* src = qkv + (size_t)(b * SEQ + q0) * (3 * DMODEL) + h * HDIM;
    const size_t zoff = (size_t)z * SEQ * HDIM;

    for (int idx = tid; idx < 64 * 64; idx += 256) {
        int q = idx >> 6, d = idx & 63;
        size_t so = (size_t)q * (3 * DMODEL) + d;
        size_t oo = zoff + (size_t)(q0 + q) * HDIM + d;
        q16[oo] = __float2half(src[so]);
        k16[oo] = __float2half(src[so + DMODEL]);
        vs[q][d] = src[so + 2 * DMODEL];
    }
    __syncthreads();
    for (int idx = tid; idx < 64 * 64; idx += 256) {
        int d = idx >> 6, q = idx & 63;
        vt[(size_t)z * HDIM * SEQ + (size_t)d * SEQ + q0 + q] = __float2half(vs[q][d]);
    }
}

// row softmax: S fp32 [rows][2048] -> P fp16; 1 warp per row
__global__ __launch_bounds__(128) void softmax_kernel(const float* __restrict__ S,
                                                      __half* __restrict__ P)
{
    const int row = blockIdx.x * 4 + (threadIdx.x >> 5);
    const int lane = threadIdx.x & 31;
    const float* srow = S + (size_t)row * SEQ;
    float v[64];
    float mx = -1e30f;
#pragma unroll
    for (int i = 0; i < 16; i++) {
        float4 f = *(const float4*)(srow + i * 128 + lane * 4);
        v[4 * i] = f.x; v[4 * i + 1] = f.y; v[4 * i + 2] = f.z; v[4 * i + 3] = f.w;
        mx = fmaxf(mx, fmaxf(fmaxf(f.x, f.y), fmaxf(f.z, f.w)));
    }
#pragma unroll
    for (int d = 16; d >= 1; d >>= 1)
        mx = fmaxf(mx, __shfl_xor_sync(0xffffffffu, mx, d));
    float sum = 0.f;
#pragma unroll
    for (int i = 0; i < 64; i++) { v[i] = __expf(v[i] - mx); sum += v[i]; }
#pragma unroll
    for (int d = 16; d >= 1; d >>= 1)
        sum += __shfl_xor_sync(0xffffffffu, sum, d);
    float inv = 1.0f / sum;
    __half* prow = P + (size_t)row * SEQ;
#pragma unroll
    for (int i = 0; i < 16; i++) {
        __half2 a = __floats2half2_rn(v[4 * i] * inv, v[4 * i + 1] * inv);
        __half2 b = __floats2half2_rn(v[4 * i + 2] * inv, v[4 * i + 3] * inv);
        uint2 pk;
        pk.x = *(uint32_t*)&a; pk.y = *(uint32_t*)&b;
        *(uint2*)(prow + i * 128 + lane * 4) = pk;
    }
}

// ---------------------------------------------------------------------------
// Launch
// ---------------------------------------------------------------------------
extern "C" void kernel_launch(void* const* d_in, const int* in_sizes, int n_in,
                              void* d_out, int out_size)
{
    const float* x     = (const float*)d_in[0];
    const float* W_qkv = (const float*)d_in[1];
    const float* b_qkv = (const float*)d_in[2];
    const float* W_out = (const float*)d_in[3];
    const float* b_out = (const float*)d_in[4];
    float* out = (float*)d_out;

    float *qkv, *s, *att;
    __nv_bfloat16 *xh, *xl, *wqh, *wql, *woh, *wol, *ah, *al;
    __half *q16, *k16, *vt, *p;
    cudaGetSymbolAddress((void**)&qkv, g_qkv);
    cudaGetSymbolAddress((void**)&xh, g_xh);     cudaGetSymbolAddress((void**)&xl, g_xl);
    cudaGetSymbolAddress((void**)&wqh, g_wqt_h); cudaGetSymbolAddress((void**)&wql, g_wqt_l);
    cudaGetSymbolAddress((void**)&woh, g_wot_h); cudaGetSymbolAddress((void**)&wol, g_wot_l);
    cudaGetSymbolAddress((void**)&q16, g_q16);   cudaGetSymbolAddress((void**)&k16, g_k16);
    cudaGetSymbolAddress((void**)&vt, g_vt);
    cudaGetSymbolAddress((void**)&s, g_s);       cudaGetSymbolAddress((void**)&p, g_p);
    cudaGetSymbolAddress((void**)&att, g_att);
    cudaGetSymbolAddress((void**)&ah, g_ah);     cudaGetSymbolAddress((void**)&al, g_al);

    // 1. split x into bf16 hi/lo
    split_pair_kernel<<<4096, 256>>>(x, xh, xl, (size_t)MTOK * DMODEL);
    // 2. transpose+split weights
    wtrans_split_kernel<<<dim3(3 * DMODEL / 32, DMODEL / 32), dim3(32, 8)>>>(
        W_qkv, wqh, wql, DMODEL, 3 * DMODEL);
    wtrans_split_kernel<<<dim3(DMODEL / 32, DMODEL / 32), dim3(32, 8)>>>(
        W_out, woh, wol, DMODEL, DMODEL);
    // 3. QKV projection (bf16 x3): qkv = x @ W_qkv + b_qkv
    mma_gemm<false, 3><<<dim3(3 * DMODEL / 64, MTOK / 128, 1), 256>>>(
        (const ushort_t*)xh, (const ushort_t*)xl, (const ushort_t*)xh,
        (const ushort_t*)wqh, (const ushort_t*)wqh, (const ushort_t*)wql,
        qkv, b_qkv, 1.0f, DMODEL, 0, 0, 0, 0, 1, 3 * DMODEL);
    // 4. split qkv into per-head fp16 operand tensors
    split_qkv_kernel<<<dim3(SEQ / 64, NBH), 256>>>(qkv, q16, k16, vt);
    // 5. scores: S = scale * Q @ K^T  (fp16, batched over 64 bh)
    mma_gemm<true, 1><<<dim3(SEQ / 64, SEQ / 128, NBH), 256>>>(
        (const ushort_t*)q16, (const ushort_t*)q16, (const ushort_t*)q16,
        (const ushort_t*)k16, (const ushort_t*)k16, (const ushort_t*)k16,
        s, nullptr, ATTN_SCALE, HDIM,
        (long long)SEQ * HDIM, (long long)SEQ * HDIM,
        (long long)SEQ * SEQ, 0, 1, SEQ);
    // 6. softmax rows -> P fp16
    softmax_kernel<<<(NBH * SEQ) / 4, 128>>>(s, p);
    // 7. O = P @ V  (fp16) -> att[token][h*64+d]
    mma_gemm<true, 1><<<dim3(1, SEQ / 128, NBH), 256>>>(
        (const ushort_t*)p, (const ushort_t*)p, (const ushort_t*)p,
        (const ushort_t*)vt, (const ushort_t*)vt, (const ushort_t*)vt,
        att, nullptr, 1.0f, SEQ,
        (long long)SEQ * SEQ, (long long)HDIM * SEQ,
        (long long)SEQ * DMODEL, HDIM, NHEAD, DMODEL);
    // 8. split att into bf16 hi/lo
    split_pair_kernel<<<4096, 256>>>(att, ah, al, (size_t)MTOK * DMODEL);
    // 9. out = att @ W_out + b_out (bf16 x3)
    mma_gemm<false, 3><<<dim3(DMODEL / 64, MTOK / 128, 1), 256>>>(
        (const ushort_t*)ah, (const ushort_t*)al, (const ushort_t*)ah,
        (const ushort_t*)woh, (const ushort_t*)woh, (const ushort_t*)wol,
        out, b_out, 1.0f, DMODEL, 0, 0, 0, 0, 1, DMODEL);
}

// round 6
// speedup vs baseline: 2.9495x; 1.2368x over previous
#include <cuda_runtime.h>
#include <cuda_bf16.h>
#include <cuda_fp16.h>
#include <cstdint>

// ---------------------------------------------------------------------------
// Problem constants
// ---------------------------------------------------------------------------
#define BATCH 4
#define SEQ   2048
#define NHEAD 16
#define HDIM  64
#define DMODEL 1024
#define MTOK  (BATCH * SEQ)              // 8192
#define NBH   (BATCH * NHEAD)            // 64
#define ATTN_SCALE 0.125f

typedef unsigned short ushort_t;

// ---------------------------------------------------------------------------
// Scratch (static device globals; no allocations allowed)
// ---------------------------------------------------------------------------
__device__ __nv_bfloat16  g_xh[(size_t)MTOK * DMODEL];
__device__ __nv_bfloat16  g_xl[(size_t)MTOK * DMODEL];
__device__ __nv_bfloat16  g_wqt_h[(size_t)3 * DMODEL * DMODEL];      // W_qkv^T hi
__device__ __nv_bfloat16  g_wqt_l[(size_t)3 * DMODEL * DMODEL];      // W_qkv^T lo
__device__ __nv_bfloat16  g_wot_h[(size_t)DMODEL * DMODEL];          // W_out^T hi
__device__ __nv_bfloat16  g_wot_l[(size_t)DMODEL * DMODEL];          // W_out^T lo
__device__ __half         g_q16[(size_t)NBH * SEQ * HDIM];           // Q*scale fp16
__device__ __half         g_k16[(size_t)NBH * SEQ * HDIM];           // K fp16
__device__ __half         g_v16[(size_t)NBH * SEQ * HDIM];           // V fp16
__device__ __nv_bfloat16  g_ah[(size_t)MTOK * DMODEL];               // att hi
__device__ __nv_bfloat16  g_al[(size_t)MTOK * DMODEL];               // att lo

// ---------------------------------------------------------------------------
// PTX helpers (baseline PTX only: cp.async / ldmatrix / mma.sync)
// ---------------------------------------------------------------------------
__device__ __forceinline__ uint32_t smem_u32(const void* p) {
    uint32_t a;
    asm("{ .reg .u64 t; cvta.to.shared.u64 t, %1; cvt.u32.u64 %0, t; }" : "=r"(a) : "l"(p));
    return a;
}
__device__ __forceinline__ void cp16(uint32_t dst, const void* src) {
    asm volatile("cp.async.cg.shared.global [%0], [%1], 16;" :: "r"(dst), "l"(src) : "memory");
}
#define CP_COMMIT() asm volatile("cp.async.commit_group;" ::: "memory")
#define CP_WAIT1()  asm volatile("cp.async.wait_group 1;" ::: "memory")
#define CP_WAIT2()  asm volatile("cp.async.wait_group 2;" ::: "memory")

__device__ __forceinline__ void ldm4(uint32_t a, uint32_t& r0, uint32_t& r1,
                                     uint32_t& r2, uint32_t& r3) {
    asm volatile("ldmatrix.sync.aligned.m8n8.x4.shared.b16 {%0,%1,%2,%3}, [%4];"
                 : "=r"(r0), "=r"(r1), "=r"(r2), "=r"(r3) : "r"(a));
}
__device__ __forceinline__ void ldm4t(uint32_t a, uint32_t& r0, uint32_t& r1,
                                      uint32_t& r2, uint32_t& r3) {
    asm volatile("ldmatrix.sync.aligned.m8n8.x4.trans.shared.b16 {%0,%1,%2,%3}, [%4];"
                 : "=r"(r0), "=r"(r1), "=r"(r2), "=r"(r3) : "r"(a));
}

template<bool FP16>
__device__ __forceinline__ void mma16816(float* c, const uint32_t* a,
                                         uint32_t b0, uint32_t b1) {
    if (FP16) {
        asm volatile(
            "mma.sync.aligned.m16n8k16.row.col.f32.f16.f16.f32 "
            "{%0,%1,%2,%3},{%4,%5,%6,%7},{%8,%9},{%0,%1,%2,%3};"
            : "+f"(c[0]), "+f"(c[1]), "+f"(c[2]), "+f"(c[3])
            : "r"(a[0]), "r"(a[1]), "r"(a[2]), "r"(a[3]), "r"(b0), "r"(b1));
    } else {
        asm volatile(
            "mma.sync.aligned.m16n8k16.row.col.f32.bf16.bf16.f32 "
            "{%0,%1,%2,%3},{%4,%5,%6,%7},{%8,%9},{%0,%1,%2,%3};"
            : "+f"(c[0]), "+f"(c[1]), "+f"(c[2]), "+f"(c[3])
            : "r"(a[0]), "r"(a[1]), "r"(a[2]), "r"(a[3]), "r"(b0), "r"(b1));
    }
}

// ---------------------------------------------------------------------------
// mma.sync GEMM: 128x128 CTA tile, 8 warps 4(m)x2(n), warp tile 32x64.
// K-stage 32, 3-stage cp.async pipeline.
//   C[M][N] = sum over NPASS of Ap·Bp^T  (A,B 2-byte k-major)
//   EPI 0: C fp32 = acc + bias
//   EPI 1: qkv scatter -> q16 (scaled), k16, v16 per-head fp16
// ---------------------------------------------------------------------------
#define STR 40                  // halves per smem row (32 data + 8 pad)
#define GSTAGE_BYTES (2 * 128 * STR * 2)   // A + B per stage = 20480
#define GEMM_SMEM (3 * GSTAGE_BYTES)

template<int EPI, int NPASS>
__global__ __launch_bounds__(256) void mma_gemm(
    const ushort_t* __restrict__ A0, const ushort_t* __restrict__ A1,
    const ushort_t* __restrict__ A2,
    const ushort_t* __restrict__ B0, const ushort_t* __restrict__ B1,
    const ushort_t* __restrict__ B2,
    float* __restrict__ C, const float* __restrict__ bias,
    __half* __restrict__ oq, __half* __restrict__ ok, __half* __restrict__ ov,
    int K, int ldc)
{
    extern __shared__ __align__(16) ushort_t smg[];

    const int tid = threadIdx.x, lane = tid & 31, wid = tid >> 5;
    const int wm = wid & 3, wn = wid >> 2;            // 4 x 2 warps
    const int m0 = blockIdx.y * 128, n0 = blockIdx.x * 128;
    const int CPP = K / 32;
    const int NC  = NPASS * CPP;

    const uint32_t sbase = smem_u32(smg);

    float acc[2][8][4];
#pragma unroll
    for (int mi = 0; mi < 2; mi++)
#pragma unroll
        for (int j = 0; j < 8; j++)
#pragma unroll
            for (int r = 0; r < 4; r++) acc[mi][j][r] = 0.f;

    // cp.async: A/B each 128 rows x 32h; thread t loads 32B of one row each
    const int ldrow = tid >> 1;             // 0..127
    const int ldch  = (tid & 1) * 2;        // chunk 0/2 (+1)

    auto load_stage = [&](int s, int buf) {
        int p = s / CPP, kc = s - p * CPP, k0 = kc * 32;
        const ushort_t* Ap = (p == 0 ? A0 : (p == 1 ? A1 : A2));
        const ushort_t* Bp = (p == 0 ? B0 : (p == 1 ? B1 : B2));
        uint32_t ad = sbase + buf * GSTAGE_BYTES;
        uint32_t bd = ad + 128 * STR * 2;
        const ushort_t* ag = Ap + (size_t)(m0 + ldrow) * K + k0 + ldch * 8;
        const ushort_t* bg = Bp + (size_t)(n0 + ldrow) * K + k0 + ldch * 8;
        uint32_t as_ = ad + (ldrow * STR + ldch * 8) * 2;
        uint32_t bs_ = bd + (ldrow * STR + ldch * 8) * 2;
        cp16(as_, ag);          cp16(as_ + 16, ag + 8);
        cp16(bs_, bg);          cp16(bs_ + 16, bg + 8);
    };

    load_stage(0, 0); CP_COMMIT();
    load_stage(1, 1); CP_COMMIT();

    const int lr = (lane & 7) + (((lane >> 3) & 1) << 3);
    const int lc = ((lane >> 4) & 1) << 3;

    for (int c = 0; c < NC; ++c) {
        if (c + 2 < NC) load_stage(c + 2, (c + 2) % 3);
        CP_COMMIT();
        CP_WAIT2();
        __syncthreads();

        const uint32_t ab = sbase + (c % 3) * GSTAGE_BYTES;
        const uint32_t bb = ab + 128 * STR * 2;

#pragma unroll
        for (int kk = 0; kk < 32; kk += 16) {
            uint32_t a[2][4], b[4][4];
#pragma unroll
            for (int mi = 0; mi < 2; mi++)
                ldm4(ab + ((wm * 32 + mi * 16 + lr) * STR + kk + lc) * 2,
                     a[mi][0], a[mi][1], a[mi][2], a[mi][3]);
#pragma unroll
            for (int nb = 0; nb < 4; nb++)
                ldm4(bb + ((wn * 64 + nb * 16 + lr) * STR + kk + lc) * 2,
                     b[nb][0], b[nb][1], b[nb][2], b[nb][3]);
#pragma unroll
            for (int mi = 0; mi < 2; mi++)
#pragma unroll
                for (int j = 0; j < 8; j++) {
                    int nb = j >> 1, hi = j & 1;
                    mma16816<false>(acc[mi][j], a[mi], b[nb][hi], b[nb][2 + hi]);
                }
        }
        __syncthreads();
    }

    // epilogue
    const int rq = lane >> 2, cq = (lane & 3) * 2;
#pragma unroll
    for (int mi = 0; mi < 2; mi++)
#pragma unroll
        for (int j = 0; j < 8; j++)
#pragma unroll
            for (int half = 0; half < 2; half++) {
                int row = m0 + wm * 32 + mi * 16 + rq + half * 8;
                int col = n0 + wn * 64 + j * 8 + cq;
                float v0 = acc[mi][j][half * 2 + 0] + bias[col];
                float v1 = acc[mi][j][half * 2 + 1] + bias[col + 1];
                if (EPI == 0) {
                    *(float2*)(C + (size_t)row * ldc + col) = make_float2(v0, v1);
                } else {
                    int seg = col >> 10;            // 0=q 1=k 2=v
                    int ch  = col & 1023;
                    int z   = ((row >> 11) << 4) + (ch >> 6);
                    size_t dst = ((size_t)z * SEQ + (row & 2047)) * HDIM + (ch & 63);
                    if (seg == 0) { v0 *= ATTN_SCALE; v1 *= ATTN_SCALE; }
                    __half2 h = __floats2half2_rn(v0, v1);
                    __half* o = (seg == 0 ? oq : (seg == 1 ? ok : ov));
                    *(__half2*)(o + dst) = h;
                }
            }
}

// ---------------------------------------------------------------------------
// Flash attention (fp16 mma, fp32 accum/softmax).
// CTA = 128 q rows of one (b,h); 8 warps x 16 rows; loop key blocks of 64.
// Writes O split into bf16 hi/lo (for out-proj x3 GEMM).
// ---------------------------------------------------------------------------
#define STRF 72                 // halves per smem row (64 data + 8 pad)
#define FQ_BYTES (128 * STRF * 2)
#define FT_BYTES (64 * STRF * 2)
#define FLASH_SMEM (FQ_BYTES + 2 * 2 * FT_BYTES)   // Q + 2 stages x (K,V)

__global__ __launch_bounds__(256) void flash_kernel(
    const __half* __restrict__ q16, const __half* __restrict__ k16,
    const __half* __restrict__ v16,
    __nv_bfloat16* __restrict__ ah, __nv_bfloat16* __restrict__ al)
{
    extern __shared__ __align__(16) ushort_t smf[];
    const uint32_t qs = smem_u32(smf);
    const uint32_t kv0 = qs + FQ_BYTES;            // stage s: K at kv0+s*2*FT, V next

    const int tid = threadIdx.x, lane = tid & 31, wid = tid >> 5;
    const int q0 = blockIdx.x * 128;
    const int z  = blockIdx.y;
    const __half* Qg = q16 + (size_t)z * SEQ * HDIM;
    const __half* Kg = k16 + (size_t)z * SEQ * HDIM;
    const __half* Vg = v16 + (size_t)z * SEQ * HDIM;

    // ---- prologue: Q (4 chunks/thread) + KV block 0, one group
    {
#pragma unroll
        for (int i = 0; i < 4; i++) {
            int cid = tid + i * 256;                 // 1024 chunks
            int r = cid >> 3, ccol = cid & 7;
            cp16(qs + (r * STRF + ccol * 8) * 2, Qg + (size_t)(q0 + r) * HDIM + ccol * 8);
        }
        int r = tid >> 2, ccol = (tid & 3) * 2;      // 64 rows x 8 chunks, 2/thread
        uint32_t kd = kv0, vd = kv0 + FT_BYTES;
        cp16(kd + (r * STRF + ccol * 8) * 2, Kg + (size_t)r * HDIM + ccol * 8);
        cp16(kd + (r * STRF + (ccol + 1) * 8) * 2, Kg + (size_t)r * HDIM + (ccol + 1) * 8);
        cp16(vd + (r * STRF + ccol * 8) * 2, Vg + (size_t)r * HDIM + ccol * 8);
        cp16(vd + (r * STRF + (ccol + 1) * 8) * 2, Vg + (size_t)r * HDIM + (ccol + 1) * 8);
        CP_COMMIT();
    }

    float o[8][4];
#pragma unroll
    for (int j = 0; j < 8; j++)
#pragma unroll
        for (int r = 0; r < 4; r++) o[j][r] = 0.f;
    float m0 = -1e30f, m1 = -1e30f, l0 = 0.f, l1 = 0.f;

    const int lr = (lane & 7) + (((lane >> 3) & 1) << 3);
    const int lc = ((lane >> 4) & 1) << 3;
    const int qrow = wid * 16;                       // warp's 16 q rows

    const int NKB = SEQ / 64;
    for (int kb = 0; kb < NKB; ++kb) {
        // prefetch next KV block
        if (kb + 1 < NKB) {
            int r = tid >> 2, ccol = (tid & 3) * 2;
            uint32_t kd = kv0 + ((kb + 1) & 1) * 2 * FT_BYTES;
            uint32_t vd = kd + FT_BYTES;
            const __half* Kn = Kg + (size_t)((kb + 1) * 64 + r) * HDIM;
            const __half* Vn = Vg + (size_t)((kb + 1) * 64 + r) * HDIM;
            cp16(kd + (r * STRF + ccol * 8) * 2, Kn + ccol * 8);
            cp16(kd + (r * STRF + (ccol + 1) * 8) * 2, Kn + (ccol + 1) * 8);
            cp16(vd + (r * STRF + ccol * 8) * 2, Vn + ccol * 8);
            cp16(vd + (r * STRF + (ccol + 1) * 8) * 2, Vn + (ccol + 1) * 8);
        }
        CP_COMMIT();
        CP_WAIT1();
        __syncthreads();

        const uint32_t kbuf = kv0 + (kb & 1) * 2 * FT_BYTES;
        const uint32_t vbuf = kbuf + FT_BYTES;

        // ---- S = Q @ K^T (16 x 64 per warp)
        float s[8][4];
#pragma unroll
        for (int j = 0; j < 8; j++)
#pragma unroll
            for (int r = 0; r < 4; r++) s[j][r] = 0.f;
#pragma unroll
        for (int t = 0; t < 4; t++) {                // k-steps over d
            uint32_t a[4], b[4][4];
            ldm4(qs + ((qrow + lr) * STRF + t * 16 + lc) * 2, a[0], a[1], a[2], a[3]);
#pragma unroll
            for (int nb = 0; nb < 4; nb++)
                ldm4(kbuf + ((nb * 16 + lr) * STRF + t * 16 + lc) * 2,
                     b[nb][0], b[nb][1], b[nb][2], b[nb][3]);
#pragma unroll
            for (int j = 0; j < 8; j++) {
                int nb = j >> 1, hi = j & 1;
                mma16816<true>(s[j], a, b[nb][hi], b[nb][2 + hi]);
            }
        }

        // ---- online softmax (rows r0 = lane>>2, r1 = r0+8)
        float mx0 = -1e30f, mx1 = -1e30f;
#pragma unroll
        for (int j = 0; j < 8; j++) {
            mx0 = fmaxf(mx0, fmaxf(s[j][0], s[j][1]));
            mx1 = fmaxf(mx1, fmaxf(s[j][2], s[j][3]));
        }
        mx0 = fmaxf(mx0, __shfl_xor_sync(0xffffffffu, mx0, 1));
        mx0 = fmaxf(mx0, __shfl_xor_sync(0xffffffffu, mx0, 2));
        mx1 = fmaxf(mx1, __shfl_xor_sync(0xffffffffu, mx1, 1));
        mx1 = fmaxf(mx1, __shfl_xor_sync(0xffffffffu, mx1, 2));
        float mn0 = fmaxf(m0, mx0), mn1 = fmaxf(m1, mx1);
        float al0 = __expf(m0 - mn0), al1 = __expf(m1 - mn1);
        m0 = mn0; m1 = mn1;
        float sum0 = 0.f, sum1 = 0.f;
#pragma unroll
        for (int j = 0; j < 8; j++) {
            s[j][0] = __expf(s[j][0] - mn0);
            s[j][1] = __expf(s[j][1] - mn0);
            s[j][2] = __expf(s[j][2] - mn1);
            s[j][3] = __expf(s[j][3] - mn1);
            sum0 += s[j][0] + s[j][1];
            sum1 += s[j][2] + s[j][3];
        }
        sum0 += __shfl_xor_sync(0xffffffffu, sum0, 1);
        sum0 += __shfl_xor_sync(0xffffffffu, sum0, 2);
        sum1 += __shfl_xor_sync(0xffffffffu, sum1, 1);
        sum1 += __shfl_xor_sync(0xffffffffu, sum1, 2);
        l0 = l0 * al0 + sum0;
        l1 = l1 * al1 + sum1;
#pragma unroll
        for (int j = 0; j < 8; j++) {
            o[j][0] *= al0; o[j][1] *= al0;
            o[j][2] *= al1; o[j][3] *= al1;
        }

        // ---- O += P @ V  (P from S frags, V via ldmatrix.trans)
#pragma unroll
        for (int t = 0; t < 4; t++) {                // k-steps over keys
            uint32_t a[4];
            {
                __half2 p0 = __floats2half2_rn(s[2 * t][0], s[2 * t][1]);
                __half2 p1 = __floats2half2_rn(s[2 * t][2], s[2 * t][3]);
                __half2 p2 = __floats2half2_rn(s[2 * t + 1][0], s[2 * t + 1][1]);
                __half2 p3 = __floats2half2_rn(s[2 * t + 1][2], s[2 * t + 1][3]);
                a[0] = *(uint32_t*)&p0; a[1] = *(uint32_t*)&p1;
                a[2] = *(uint32_t*)&p2; a[3] = *(uint32_t*)&p3;
            }
#pragma unroll
            for (int db = 0; db < 4; db++) {
                uint32_t r0, r1, r2, r3;
                ldm4t(vbuf + ((t * 16 + (lane & 15)) * STRF +
                              db * 16 + ((lane >> 4) & 1) * 8) * 2,
                      r0, r1, r2, r3);
                mma16816<true>(o[2 * db],     a, r0, r1);
                mma16816<true>(o[2 * db + 1], a, r2, r3);
            }
        }
        __syncthreads();
    }

    // ---- epilogue: O/l -> bf16 hi/lo split, att[token][h*64+d]
    const float inv0 = 1.0f / l0, inv1 = 1.0f / l1;
    const int b = z >> 4, h = z & 15;
    const int row0 = b * SEQ + q0 + qrow + (lane >> 2);
    const int colb = h * HDIM + (lane & 3) * 2;
#pragma unroll
    for (int j = 0; j < 8; j++) {
        float v00 = o[j][0] * inv0, v01 = o[j][1] * inv0;
        float v10 = o[j][2] * inv1, v11 = o[j][3] * inv1;
        __nv_bfloat16 h00 = __float2bfloat16(v00), h01 = __float2bfloat16(v01);
        __nv_bfloat16 h10 = __float2bfloat16(v10), h11 = __float2bfloat16(v11);
        __nv_bfloat162 hh0; hh0.x = h00; hh0.y = h01;
        __nv_bfloat162 hh1; hh1.x = h10; hh1.y = h11;
        __nv_bfloat162 ll0;
        ll0.x = __float2bfloat16(v00 - __bfloat162float(h00));
        ll0.y = __float2bfloat16(v01 - __bfloat162float(h01));
        __nv_bfloat162 ll1;
        ll1.x = __float2bfloat16(v10 - __bfloat162float(h10));
        ll1.y = __float2bfloat16(v11 - __bfloat162float(h11));
        size_t o0 = (size_t)row0 * DMODEL + colb + j * 8;
        size_t o1 = (size_t)(row0 + 8) * DMODEL + colb + j * 8;
        *(__nv_bfloat162*)(ah + o0) = hh0;
        *(__nv_bfloat162*)(al + o0) = ll0;
        *(__nv_bfloat162*)(ah + o1) = hh1;
        *(__nv_bfloat162*)(al + o1) = ll1;
    }
}

// ---------------------------------------------------------------------------
// Conversion kernels
// ---------------------------------------------------------------------------
__global__ void split_pair_kernel(const float* __restrict__ x,
                                  __nv_bfloat16* __restrict__ h,
                                  __nv_bfloat16* __restrict__ l, size_t n)
{
    for (size_t i = (size_t)blockIdx.x * blockDim.x + threadIdx.x; i < n;
         i += (size_t)gridDim.x * blockDim.x) {
        float v = x[i];
        __nv_bfloat16 hi = __float2bfloat16(v);
        h[i] = hi;
        l[i] = __float2bfloat16(v - __bfloat162float(hi));
    }
}

// W[K][N] -> Wt hi/lo [N][K]
__global__ void wtrans_split_kernel(const float* __restrict__ W,
                                    __nv_bfloat16* __restrict__ Th,
                                    __nv_bfloat16* __restrict__ Tl, int K, int N)
{
    __shared__ float t[32][33];
    int kx = blockIdx.y * 32, nx = blockIdx.x * 32;
    int tx = threadIdx.x, ty = threadIdx.y;   // (32, 8)
#pragma unroll
    for (int i = 0; i < 4; i++)
        t[ty + 8 * i][tx] = W[(size_t)(kx + ty + 8 * i) * N + nx + tx];
    __syncthreads();
#pragma unroll
    for (int i = 0; i < 4; i++) {
        int nl = ty + 8 * i;
        float v = t[tx][nl];
        __nv_bfloat16 hi = __float2bfloat16(v);
        size_t o = (size_t)(nx + nl) * K + kx + tx;
        Th[o] = hi;
        Tl[o] = __float2bfloat16(v - __bfloat162float(hi));
    }
}

// ---------------------------------------------------------------------------
// Launch
// ---------------------------------------------------------------------------
extern "C" void kernel_launch(void* const* d_in, const int* in_sizes, int n_in,
                              void* d_out, int out_size)
{
    const float* x     = (const float*)d_in[0];
    const float* W_qkv = (const float*)d_in[1];
    const float* b_qkv = (const float*)d_in[2];
    const float* W_out = (const float*)d_in[3];
    const float* b_out = (const float*)d_in[4];
    float* out = (float*)d_out;

    __nv_bfloat16 *xh, *xl, *wqh, *wql, *woh, *wol, *ah, *al;
    __half *q16, *k16, *v16;
    cudaGetSymbolAddress((void**)&xh, g_xh);     cudaGetSymbolAddress((void**)&xl, g_xl);
    cudaGetSymbolAddress((void**)&wqh, g_wqt_h); cudaGetSymbolAddress((void**)&wql, g_wqt_l);
    cudaGetSymbolAddress((void**)&woh, g_wot_h); cudaGetSymbolAddress((void**)&wol, g_wot_l);
    cudaGetSymbolAddress((void**)&q16, g_q16);   cudaGetSymbolAddress((void**)&k16, g_k16);
    cudaGetSymbolAddress((void**)&v16, g_v16);
    cudaGetSymbolAddress((void**)&ah, g_ah);     cudaGetSymbolAddress((void**)&al, g_al);

    cudaFuncSetAttribute(mma_gemm<1, 3>,
                         cudaFuncAttributeMaxDynamicSharedMemorySize, GEMM_SMEM);
    cudaFuncSetAttribute(mma_gemm<0, 3>,
                         cudaFuncAttributeMaxDynamicSharedMemorySize, GEMM_SMEM);
    cudaFuncSetAttribute(flash_kernel,
                         cudaFuncAttributeMaxDynamicSharedMemorySize, FLASH_SMEM);

    // 1. split x into bf16 hi/lo
    split_pair_kernel<<<4096, 256>>>(x, xh, xl, (size_t)MTOK * DMODEL);
    // 2. transpose+split weights
    wtrans_split_kernel<<<dim3(3 * DMODEL / 32, DMODEL / 32), dim3(32, 8)>>>(
        W_qkv, wqh, wql, DMODEL, 3 * DMODEL);
    wtrans_split_kernel<<<dim3(DMODEL / 32, DMODEL / 32), dim3(32, 8)>>>(
        W_out, woh, wol, DMODEL, DMODEL);
    // 3. QKV projection (bf16 x3) with fused per-head fp16 scatter epilogue
    mma_gemm<1, 3><<<dim3(3 * DMODEL / 128, MTOK / 128), 256, GEMM_SMEM>>>(
        (const ushort_t*)xh, (const ushort_t*)xl, (const ushort_t*)xh,
        (const ushort_t*)wqh, (const ushort_t*)wqh, (const ushort_t*)wql,
        nullptr, b_qkv, q16, k16, v16, DMODEL, 0);
    // 4. flash attention -> att bf16 hi/lo
    flash_kernel<<<dim3(SEQ / 128, NBH), 256, FLASH_SMEM>>>(q16, k16, v16, ah, al);
    // 5. out = att @ W_out + b_out (bf16 x3)
    mma_gemm<0, 3><<<dim3(DMODEL / 128, MTOK / 128), 256, GEMM_SMEM>>>(
        (const ushort_t*)ah, (const ushort_t*)al, (const ushort_t*)ah,
        (const ushort_t*)woh, (const ushort_t*)woh, (const ushort_t*)wol,
        out, b_out, nullptr, nullptr, nullptr, DMODEL, DMODEL);
}

// round 7
// speedup vs baseline: 4.7387x; 1.6066x over previous
#include <cuda_runtime.h>
#include <cuda_bf16.h>
#include <cuda_fp16.h>
#include <cstdint>

// ---------------------------------------------------------------------------
// Problem constants
// ---------------------------------------------------------------------------
#define BATCH 4
#define SEQ   2048
#define NHEAD 16
#define HDIM  64
#define DMODEL 1024
#define MTOK  (BATCH * SEQ)              // 8192
#define NBH   (BATCH * NHEAD)            // 64
#define ATTN_SCALE 0.125f

typedef unsigned short ushort_t;

// ---------------------------------------------------------------------------
// Scratch (static device globals; no allocations allowed)
// ---------------------------------------------------------------------------
__device__ __half         g_x16[(size_t)MTOK * DMODEL];              // x fp16
__device__ __half         g_wq16[(size_t)3 * DMODEL * DMODEL];       // W_qkv^T fp16
__device__ __nv_bfloat16  g_wot_h[(size_t)DMODEL * DMODEL];          // W_out^T hi
__device__ __nv_bfloat16  g_wot_l[(size_t)DMODEL * DMODEL];          // W_out^T lo
__device__ __half         g_q16[(size_t)NBH * SEQ * HDIM];           // Q*scale fp16
__device__ __half         g_k16[(size_t)NBH * SEQ * HDIM];           // K fp16
__device__ __half         g_v16[(size_t)NBH * SEQ * HDIM];           // V fp16
__device__ __nv_bfloat16  g_ah[(size_t)MTOK * DMODEL];               // att hi
__device__ __nv_bfloat16  g_al[(size_t)MTOK * DMODEL];               // att lo

// ---------------------------------------------------------------------------
// PTX helpers (baseline PTX only: cp.async / ldmatrix / mma.sync)
// ---------------------------------------------------------------------------
__device__ __forceinline__ uint32_t smem_u32(const void* p) {
    uint32_t a;
    asm("{ .reg .u64 t; cvta.to.shared.u64 t, %1; cvt.u32.u64 %0, t; }" : "=r"(a) : "l"(p));
    return a;
}
__device__ __forceinline__ void cp16(uint32_t dst, const void* src) {
    asm volatile("cp.async.cg.shared.global [%0], [%1], 16;" :: "r"(dst), "l"(src) : "memory");
}
#define CP_COMMIT() asm volatile("cp.async.commit_group;" ::: "memory")
#define CP_WAIT0()  asm volatile("cp.async.wait_group 0;" ::: "memory")
#define CP_WAIT1()  asm volatile("cp.async.wait_group 1;" ::: "memory")

__device__ __forceinline__ void ldm4(uint32_t a, uint32_t& r0, uint32_t& r1,
                                     uint32_t& r2, uint32_t& r3) {
    asm volatile("ldmatrix.sync.aligned.m8n8.x4.shared.b16 {%0,%1,%2,%3}, [%4];"
                 : "=r"(r0), "=r"(r1), "=r"(r2), "=r"(r3) : "r"(a));
}
__device__ __forceinline__ void ldm4t(uint32_t a, uint32_t& r0, uint32_t& r1,
                                      uint32_t& r2, uint32_t& r3) {
    asm volatile("ldmatrix.sync.aligned.m8n8.x4.trans.shared.b16 {%0,%1,%2,%3}, [%4];"
                 : "=r"(r0), "=r"(r1), "=r"(r2), "=r"(r3) : "r"(a));
}

template<bool FP16>
__device__ __forceinline__ void mma16816(float* c, const uint32_t* a,
                                         uint32_t b0, uint32_t b1) {
    if (FP16) {
        asm volatile(
            "mma.sync.aligned.m16n8k16.row.col.f32.f16.f16.f32 "
            "{%0,%1,%2,%3},{%4,%5,%6,%7},{%8,%9},{%0,%1,%2,%3};"
            : "+f"(c[0]), "+f"(c[1]), "+f"(c[2]), "+f"(c[3])
            : "r"(a[0]), "r"(a[1]), "r"(a[2]), "r"(a[3]), "r"(b0), "r"(b1));
    } else {
        asm volatile(
            "mma.sync.aligned.m16n8k16.row.col.f32.bf16.bf16.f32 "
            "{%0,%1,%2,%3},{%4,%5,%6,%7},{%8,%9},{%0,%1,%2,%3};"
            : "+f"(c[0]), "+f"(c[1]), "+f"(c[2]), "+f"(c[3])
            : "r"(a[0]), "r"(a[1]), "r"(a[2]), "r"(a[3]), "r"(b0), "r"(b1));
    }
}

// ---------------------------------------------------------------------------
// mma.sync GEMM: 128x128 CTA tile, 8 warps 4(m)x2(n), warp tile 32x64.
// K-stage 32, 3-stage cp.async pipeline, ONE barrier per iteration
// (order: wait -> sync -> issue next loads -> compute).
//   C[M][N] = sum over NPASS of Ap·Bp^T  (A,B 2-byte k-major)
//   EPI 0: C fp32 = acc + bias
//   EPI 1: qkv scatter -> q16 (scaled), k16, v16 per-head fp16
// ---------------------------------------------------------------------------
#define STR 40                  // halves per smem row (32 data + 8 pad)
#define GSTAGE_BYTES (2 * 128 * STR * 2)   // A + B per stage = 20480
#define GEMM_SMEM (3 * GSTAGE_BYTES)

template<bool FP16, int EPI, int NPASS>
__global__ __launch_bounds__(256) void mma_gemm(
    const ushort_t* __restrict__ A0, const ushort_t* __restrict__ A1,
    const ushort_t* __restrict__ A2,
    const ushort_t* __restrict__ B0, const ushort_t* __restrict__ B1,
    const ushort_t* __restrict__ B2,
    float* __restrict__ C, const float* __restrict__ bias,
    __half* __restrict__ oq, __half* __restrict__ ok, __half* __restrict__ ov,
    int K, int ldc)
{
    extern __shared__ __align__(16) ushort_t smg[];

    const int tid = threadIdx.x, lane = tid & 31, wid = tid >> 5;
    const int wm = wid & 3, wn = wid >> 2;            // 4 x 2 warps
    const int m0 = blockIdx.y * 128, n0 = blockIdx.x * 128;
    const int CPP = K / 32;
    const int NC  = NPASS * CPP;

    const uint32_t sbase = smem_u32(smg);

    float acc[2][8][4];
#pragma unroll
    for (int mi = 0; mi < 2; mi++)
#pragma unroll
        for (int j = 0; j < 8; j++)
#pragma unroll
            for (int r = 0; r < 4; r++) acc[mi][j][r] = 0.f;

    // cp.async: A/B each 128 rows x 32h; thread t loads 32B of one row each
    const int ldrow = tid >> 1;             // 0..127
    const int ldch  = (tid & 1) * 2;        // chunk 0/2 (+1)

    auto load_stage = [&](int s, int buf) {
        int p = s / CPP, kc = s - p * CPP, k0 = kc * 32;
        const ushort_t* Ap = (p == 0 ? A0 : (p == 1 ? A1 : A2));
        const ushort_t* Bp = (p == 0 ? B0 : (p == 1 ? B1 : B2));
        uint32_t ad = sbase + buf * GSTAGE_BYTES;
        uint32_t bd = ad + 128 * STR * 2;
        const ushort_t* ag = Ap + (size_t)(m0 + ldrow) * K + k0 + ldch * 8;
        const ushort_t* bg = Bp + (size_t)(n0 + ldrow) * K + k0 + ldch * 8;
        uint32_t as_ = ad + (ldrow * STR + ldch * 8) * 2;
        uint32_t bs_ = bd + (ldrow * STR + ldch * 8) * 2;
        cp16(as_, ag);          cp16(as_ + 16, ag + 8);
        cp16(bs_, bg);          cp16(bs_ + 16, bg + 8);
    };

    load_stage(0, 0); CP_COMMIT();
    load_stage(1, 1); CP_COMMIT();

    const int lr = (lane & 7) + (((lane >> 3) & 1) << 3);
    const int lc = ((lane >> 4) & 1) << 3;

    for (int c = 0; c < NC; ++c) {
        CP_WAIT1();                 // stage c landed (newest group may be in flight)
        __syncthreads();            // everyone done reading stage (c-1)
        if (c + 2 < NC) load_stage(c + 2, (c + 2) % 3);   // overwrites (c-1)%3: safe
        CP_COMMIT();

        const uint32_t ab = sbase + (c % 3) * GSTAGE_BYTES;
        const uint32_t bb = ab + 128 * STR * 2;

#pragma unroll
        for (int kk = 0; kk < 32; kk += 16) {
            uint32_t a[2][4], b[4][4];
#pragma unroll
            for (int mi = 0; mi < 2; mi++)
                ldm4(ab + ((wm * 32 + mi * 16 + lr) * STR + kk + lc) * 2,
                     a[mi][0], a[mi][1], a[mi][2], a[mi][3]);
#pragma unroll
            for (int nb = 0; nb < 4; nb++)
                ldm4(bb + ((wn * 64 + nb * 16 + lr) * STR + kk + lc) * 2,
                     b[nb][0], b[nb][1], b[nb][2], b[nb][3]);
#pragma unroll
            for (int mi = 0; mi < 2; mi++)
#pragma unroll
                for (int j = 0; j < 8; j++) {
                    int nb = j >> 1, hi = j & 1;
                    mma16816<FP16>(acc[mi][j], a[mi], b[nb][hi], b[nb][2 + hi]);
                }
        }
    }

    // epilogue
    const int rq = lane >> 2, cq = (lane & 3) * 2;
#pragma unroll
    for (int mi = 0; mi < 2; mi++)
#pragma unroll
        for (int j = 0; j < 8; j++)
#pragma unroll
            for (int half = 0; half < 2; half++) {
                int row = m0 + wm * 32 + mi * 16 + rq + half * 8;
                int col = n0 + wn * 64 + j * 8 + cq;
                float v0 = acc[mi][j][half * 2 + 0] + bias[col];
                float v1 = acc[mi][j][half * 2 + 1] + bias[col + 1];
                if (EPI == 0) {
                    *(float2*)(C + (size_t)row * ldc + col) = make_float2(v0, v1);
                } else {
                    int seg = col >> 10;            // 0=q 1=k 2=v
                    int ch  = col & 1023;
                    int z   = ((row >> 11) << 4) + (ch >> 6);
                    size_t dst = ((size_t)z * SEQ + (row & 2047)) * HDIM + (ch & 63);
                    if (seg == 0) { v0 *= ATTN_SCALE; v1 *= ATTN_SCALE; }
                    __half2 h = __floats2half2_rn(v0, v1);
                    __half* o = (seg == 0 ? oq : (seg == 1 ? ok : ov));
                    *(__half2*)(o + dst) = h;
                }
            }
}

// ---------------------------------------------------------------------------
// Flash attention (fp16 mma, fp32 accum/softmax).
// CTA = 128 q rows of one (b,h); 8 warps x 16 rows; key blocks of 64,
// double-buffered, ONE barrier per block (wait -> sync -> prefetch -> compute).
// Writes O split into bf16 hi/lo (for out-proj x3 GEMM).
// ---------------------------------------------------------------------------
#define STRF 72                 // halves per smem row (64 data + 8 pad)
#define FQ_BYTES (128 * STRF * 2)
#define FT_BYTES (64 * STRF * 2)
#define FLASH_SMEM (FQ_BYTES + 2 * 2 * FT_BYTES)   // Q + 2 stages x (K,V)

__global__ __launch_bounds__(256) void flash_kernel(
    const __half* __restrict__ q16, const __half* __restrict__ k16,
    const __half* __restrict__ v16,
    __nv_bfloat16* __restrict__ ah, __nv_bfloat16* __restrict__ al)
{
    extern __shared__ __align__(16) ushort_t smf[];
    const uint32_t qs = smem_u32(smf);
    const uint32_t kv0 = qs + FQ_BYTES;            // stage s: K at kv0+s*2*FT, V next

    const int tid = threadIdx.x, lane = tid & 31, wid = tid >> 5;
    const int q0 = blockIdx.x * 128;
    const int z  = blockIdx.y;
    const __half* Qg = q16 + (size_t)z * SEQ * HDIM;
    const __half* Kg = k16 + (size_t)z * SEQ * HDIM;
    const __half* Vg = v16 + (size_t)z * SEQ * HDIM;

    // ---- prologue: Q (4 chunks/thread) + KV block 0, one group
    {
#pragma unroll
        for (int i = 0; i < 4; i++) {
            int cid = tid + i * 256;                 // 1024 chunks
            int r = cid >> 3, ccol = cid & 7;
            cp16(qs + (r * STRF + ccol * 8) * 2, Qg + (size_t)(q0 + r) * HDIM + ccol * 8);
        }
        int r = tid >> 2, ccol = (tid & 3) * 2;      // 64 rows x 8 chunks, 2/thread
        uint32_t kd = kv0, vd = kv0 + FT_BYTES;
        cp16(kd + (r * STRF + ccol * 8) * 2, Kg + (size_t)r * HDIM + ccol * 8);
        cp16(kd + (r * STRF + (ccol + 1) * 8) * 2, Kg + (size_t)r * HDIM + (ccol + 1) * 8);
        cp16(vd + (r * STRF + ccol * 8) * 2, Vg + (size_t)r * HDIM + ccol * 8);
        cp16(vd + (r * STRF + (ccol + 1) * 8) * 2, Vg + (size_t)r * HDIM + (ccol + 1) * 8);
        CP_COMMIT();
    }

    float o[8][4];
#pragma unroll
    for (int j = 0; j < 8; j++)
#pragma unroll
        for (int r = 0; r < 4; r++) o[j][r] = 0.f;
    float m0 = -1e30f, m1 = -1e30f, l0 = 0.f, l1 = 0.f;

    const int lr = (lane & 7) + (((lane >> 3) & 1) << 3);
    const int lc = ((lane >> 4) & 1) << 3;
    const int qrow = wid * 16;                       // warp's 16 q rows

    const int NKB = SEQ / 64;
    for (int kb = 0; kb < NKB; ++kb) {
        CP_WAIT0();                 // KV block kb landed
        __syncthreads();            // everyone done reading block kb-1
        if (kb + 1 < NKB) {         // prefetch kb+1 into (kb+1)&1: safe after sync
            int r = tid >> 2, ccol = (tid & 3) * 2;
            uint32_t kd = kv0 + ((kb + 1) & 1) * 2 * FT_BYTES;
            uint32_t vd = kd + FT_BYTES;
            const __half* Kn = Kg + (size_t)((kb + 1) * 64 + r) * HDIM;
            const __half* Vn = Vg + (size_t)((kb + 1) * 64 + r) * HDIM;
            cp16(kd + (r * STRF + ccol * 8) * 2, Kn + ccol * 8);
            cp16(kd + (r * STRF + (ccol + 1) * 8) * 2, Kn + (ccol + 1) * 8);
            cp16(vd + (r * STRF + ccol * 8) * 2, Vn + ccol * 8);
            cp16(vd + (r * STRF + (ccol + 1) * 8) * 2, Vn + (ccol + 1) * 8);
        }
        CP_COMMIT();

        const uint32_t kbuf = kv0 + (kb & 1) * 2 * FT_BYTES;
        const uint32_t vbuf = kbuf + FT_BYTES;

        // ---- S = Q @ K^T (16 x 64 per warp)
        float s[8][4];
#pragma unroll
        for (int j = 0; j < 8; j++)
#pragma unroll
            for (int r = 0; r < 4; r++) s[j][r] = 0.f;
#pragma unroll
        for (int t = 0; t < 4; t++) {                // k-steps over d
            uint32_t a[4], b[4][4];
            ldm4(qs + ((qrow + lr) * STRF + t * 16 + lc) * 2, a[0], a[1], a[2], a[3]);
#pragma unroll
            for (int nb = 0; nb < 4; nb++)
                ldm4(kbuf + ((nb * 16 + lr) * STRF + t * 16 + lc) * 2,
                     b[nb][0], b[nb][1], b[nb][2], b[nb][3]);
#pragma unroll
            for (int j = 0; j < 8; j++) {
                int nb = j >> 1, hi = j & 1;
                mma16816<true>(s[j], a, b[nb][hi], b[nb][2 + hi]);
            }
        }

        // ---- online softmax (rows r0 = lane>>2, r1 = r0+8)
        float mx0 = -1e30f, mx1 = -1e30f;
#pragma unroll
        for (int j = 0; j < 8; j++) {
            mx0 = fmaxf(mx0, fmaxf(s[j][0], s[j][1]));
            mx1 = fmaxf(mx1, fmaxf(s[j][2], s[j][3]));
        }
        mx0 = fmaxf(mx0, __shfl_xor_sync(0xffffffffu, mx0, 1));
        mx0 = fmaxf(mx0, __shfl_xor_sync(0xffffffffu, mx0, 2));
        mx1 = fmaxf(mx1, __shfl_xor_sync(0xffffffffu, mx1, 1));
        mx1 = fmaxf(mx1, __shfl_xor_sync(0xffffffffu, mx1, 2));
        float mn0 = fmaxf(m0, mx0), mn1 = fmaxf(m1, mx1);
        float al0 = __expf(m0 - mn0), al1 = __expf(m1 - mn1);
        m0 = mn0; m1 = mn1;
        float sum0 = 0.f, sum1 = 0.f;
#pragma unroll
        for (int j = 0; j < 8; j++) {
            s[j][0] = __expf(s[j][0] - mn0);
            s[j][1] = __expf(s[j][1] - mn0);
            s[j][2] = __expf(s[j][2] - mn1);
            s[j][3] = __expf(s[j][3] - mn1);
            sum0 += s[j][0] + s[j][1];
            sum1 += s[j][2] + s[j][3];
        }
        sum0 += __shfl_xor_sync(0xffffffffu, sum0, 1);
        sum0 += __shfl_xor_sync(0xffffffffu, sum0, 2);
        sum1 += __shfl_xor_sync(0xffffffffu, sum1, 1);
        sum1 += __shfl_xor_sync(0xffffffffu, sum1, 2);
        l0 = l0 * al0 + sum0;
        l1 = l1 * al1 + sum1;
#pragma unroll
        for (int j = 0; j < 8; j++) {
            o[j][0] *= al0; o[j][1] *= al0;
            o[j][2] *= al1; o[j][3] *= al1;
        }

        // ---- O += P @ V  (P from S frags, V via ldmatrix.trans)
#pragma unroll
        for (int t = 0; t < 4; t++) {                // k-steps over keys
            uint32_t a[4];
            {
                __half2 p0 = __floats2half2_rn(s[2 * t][0], s[2 * t][1]);
                __half2 p1 = __floats2half2_rn(s[2 * t][2], s[2 * t][3]);
                __half2 p2 = __floats2half2_rn(s[2 * t + 1][0], s[2 * t + 1][1]);
                __half2 p3 = __floats2half2_rn(s[2 * t + 1][2], s[2 * t + 1][3]);
                a[0] = *(uint32_t*)&p0; a[1] = *(uint32_t*)&p1;
                a[2] = *(uint32_t*)&p2; a[3] = *(uint32_t*)&p3;
            }
#pragma unroll
            for (int db = 0; db < 4; db++) {
                uint32_t r0, r1, r2, r3;
                ldm4t(vbuf + ((t * 16 + (lane & 15)) * STRF +
                              db * 16 + ((lane >> 4) & 1) * 8) * 2,
                      r0, r1, r2, r3);
                mma16816<true>(o[2 * db],     a, r0, r1);
                mma16816<true>(o[2 * db + 1], a, r2, r3);
            }
        }
    }

    // ---- epilogue: O/l -> bf16 hi/lo split, att[token][h*64+d]
    const float inv0 = 1.0f / l0, inv1 = 1.0f / l1;
    const int b = z >> 4, h = z & 15;
    const int row0 = b * SEQ + q0 + qrow + (lane >> 2);
    const int colb = h * HDIM + (lane & 3) * 2;
#pragma unroll
    for (int j = 0; j < 8; j++) {
        float v00 = o[j][0] * inv0, v01 = o[j][1] * inv0;
        float v10 = o[j][2] * inv1, v11 = o[j][3] * inv1;
        __nv_bfloat16 h00 = __float2bfloat16(v00), h01 = __float2bfloat16(v01);
        __nv_bfloat16 h10 = __float2bfloat16(v10), h11 = __float2bfloat16(v11);
        __nv_bfloat162 hh0; hh0.x = h00; hh0.y = h01;
        __nv_bfloat162 hh1; hh1.x = h10; hh1.y = h11;
        __nv_bfloat162 ll0;
        ll0.x = __float2bfloat16(v00 - __bfloat162float(h00));
        ll0.y = __float2bfloat16(v01 - __bfloat162float(h01));
        __nv_bfloat162 ll1;
        ll1.x = __float2bfloat16(v10 - __bfloat162float(h10));
        ll1.y = __float2bfloat16(v11 - __bfloat162float(h11));
        size_t o0 = (size_t)row0 * DMODEL + colb + j * 8;
        size_t o1 = (size_t)(row0 + 8) * DMODEL + colb + j * 8;
        *(__nv_bfloat162*)(ah + o0) = hh0;
        *(__nv_bfloat162*)(al + o0) = ll0;
        *(__nv_bfloat162*)(ah + o1) = hh1;
        *(__nv_bfloat162*)(al + o1) = ll1;
    }
}

// ---------------------------------------------------------------------------
// Conversion kernels
// ---------------------------------------------------------------------------
__global__ void to_fp16_kernel(const float* __restrict__ x,
                               __half* __restrict__ y, size_t n)
{
    for (size_t i = (size_t)blockIdx.x * blockDim.x + threadIdx.x; i < n;
         i += (size_t)gridDim.x * blockDim.x)
        y[i] = __float2half(x[i]);
}

// W[K][N] -> Wt fp16 [N][K]
__global__ void wtrans_f16_kernel(const float* __restrict__ W,
                                  __half* __restrict__ T, int K, int N)
{
    __shared__ float t[32][33];
    int kx = blockIdx.y * 32, nx = blockIdx.x * 32;
    int tx = threadIdx.x, ty = threadIdx.y;   // (32, 8)
#pragma unroll
    for (int i = 0; i < 4; i++)
        t[ty + 8 * i][tx] = W[(size_t)(kx + ty + 8 * i) * N + nx + tx];
    __syncthreads();
#pragma unroll
    for (int i = 0; i < 4; i++) {
        int nl = ty + 8 * i;
        T[(size_t)(nx + nl) * K + kx + tx] = __float2half(t[tx][nl]);
    }
}

// W[K][N] -> Wt hi/lo bf16 [N][K]
__global__ void wtrans_split_kernel(const float* __restrict__ W,
                                    __nv_bfloat16* __restrict__ Th,
                                    __nv_bfloat16* __restrict__ Tl, int K, int N)
{
    __shared__ float t[32][33];
    int kx = blockIdx.y * 32, nx = blockIdx.x * 32;
    int tx = threadIdx.x, ty = threadIdx.y;   // (32, 8)
#pragma unroll
    for (int i = 0; i < 4; i++)
        t[ty + 8 * i][tx] = W[(size_t)(kx + ty + 8 * i) * N + nx + tx];
    __syncthreads();
#pragma unroll
    for (int i = 0; i < 4; i++) {
        int nl = ty + 8 * i;
        float v = t[tx][nl];
        __nv_bfloat16 hi = __float2bfloat16(v);
        size_t o = (size_t)(nx + nl) * K + kx + tx;
        Th[o] = hi;
        Tl[o] = __float2bfloat16(v - __bfloat162float(hi));
    }
}

// ---------------------------------------------------------------------------
// Launch
// ---------------------------------------------------------------------------
extern "C" void kernel_launch(void* const* d_in, const int* in_sizes, int n_in,
                              void* d_out, int out_size)
{
    const float* x     = (const float*)d_in[0];
    const float* W_qkv = (const float*)d_in[1];
    const float* b_qkv = (const float*)d_in[2];
    const float* W_out = (const float*)d_in[3];
    const float* b_out = (const float*)d_in[4];
    float* out = (float*)d_out;

    __nv_bfloat16 *woh, *wol, *ah, *al;
    __half *x16, *wq16, *q16, *k16, *v16;
    cudaGetSymbolAddress((void**)&x16, g_x16);
    cudaGetSymbolAddress((void**)&wq16, g_wq16);
    cudaGetSymbolAddress((void**)&woh, g_wot_h); cudaGetSymbolAddress((void**)&wol, g_wot_l);
    cudaGetSymbolAddress((void**)&q16, g_q16);   cudaGetSymbolAddress((void**)&k16, g_k16);
    cudaGetSymbolAddress((void**)&v16, g_v16);
    cudaGetSymbolAddress((void**)&ah, g_ah);     cudaGetSymbolAddress((void**)&al, g_al);

    cudaFuncSetAttribute((const void*)mma_gemm<true, 1, 1>,
                         cudaFuncAttributeMaxDynamicSharedMemorySize, GEMM_SMEM);
    cudaFuncSetAttribute((const void*)mma_gemm<false, 0, 3>,
                         cudaFuncAttributeMaxDynamicSharedMemorySize, GEMM_SMEM);
    cudaFuncSetAttribute((const void*)flash_kernel,
                         cudaFuncAttributeMaxDynamicSharedMemorySize, FLASH_SMEM);

    // 1. x -> fp16
    to_fp16_kernel<<<2048, 256>>>(x, x16, (size_t)MTOK * DMODEL);
    // 2. W_qkv^T -> fp16 ; W_out^T -> bf16 hi/lo
    wtrans_f16_kernel<<<dim3(3 * DMODEL / 32, DMODEL / 32), dim3(32, 8)>>>(
        W_qkv, wq16, DMODEL, 3 * DMODEL);
    wtrans_split_kernel<<<dim3(DMODEL / 32, DMODEL / 32), dim3(32, 8)>>>(
        W_out, woh, wol, DMODEL, DMODEL);
    // 3. QKV projection (fp16 single pass) with fused per-head fp16 scatter
    mma_gemm<true, 1, 1><<<dim3(3 * DMODEL / 128, MTOK / 128), 256, GEMM_SMEM>>>(
        (const ushort_t*)x16, (const ushort_t*)x16, (const ushort_t*)x16,
        (const ushort_t*)wq16, (const ushort_t*)wq16, (const ushort_t*)wq16,
        nullptr, b_qkv, q16, k16, v16, DMODEL, 0);
    // 4. flash attention -> att bf16 hi/lo
    flash_kernel<<<dim3(SEQ / 128, NBH), 256, FLASH_SMEM>>>(q16, k16, v16, ah, al);
    // 5. out = att @ W_out + b_out (bf16 x3)
    mma_gemm<false, 0, 3><<<dim3(DMODEL / 128, MTOK / 128), 256, GEMM_SMEM>>>(
        (const ushort_t*)ah, (const ushort_t*)al, (const ushort_t*)ah,
        (const ushort_t*)woh, (const ushort_t*)woh, (const ushort_t*)wol,
        out, b_out, nullptr, nullptr, nullptr, DMODEL, DMODEL);
}

// round 10
// speedup vs baseline: 6.1270x; 1.2930x over previous
#include <cuda_runtime.h>
#include <cuda_bf16.h>
#include <cuda_fp16.h>
#include <cstdint>

// ---------------------------------------------------------------------------
// Problem constants
// ---------------------------------------------------------------------------
#define BATCH 4
#define SEQ   2048
#define NHEAD 16
#define HDIM  64
#define DMODEL 1024
#define MTOK  (BATCH * SEQ)              // 8192
#define NBH   (BATCH * NHEAD)            // 64
#define ATTN_SCALE 0.125f

typedef unsigned short ushort_t;

// ---------------------------------------------------------------------------
// Scratch (static device globals; no allocations allowed)
// ---------------------------------------------------------------------------
__device__ __half g_x16[(size_t)MTOK * DMODEL];              // x fp16
__device__ __half g_wq16[(size_t)3 * DMODEL * DMODEL];       // W_qkv^T fp16
__device__ __half g_wo16[(size_t)DMODEL * DMODEL];           // W_out^T fp16
__device__ __half g_q16[(size_t)NBH * SEQ * HDIM];           // Q*scale fp16
__device__ __half g_k16[(size_t)NBH * SEQ * HDIM];           // K fp16
__device__ __half g_v16[(size_t)NBH * SEQ * HDIM];           // V fp16
__device__ __half g_a16[(size_t)MTOK * DMODEL];              // att fp16

// ---------------------------------------------------------------------------
// PTX helpers (baseline PTX only: cp.async / ldmatrix / mma.sync)
// ---------------------------------------------------------------------------
__device__ __forceinline__ uint32_t smem_u32(const void* p) {
    uint32_t a;
    asm("{ .reg .u64 t; cvta.to.shared.u64 t, %1; cvt.u32.u64 %0, t; }" : "=r"(a) : "l"(p));
    return a;
}
__device__ __forceinline__ void cp16(uint32_t dst, const void* src) {
    asm volatile("cp.async.cg.shared.global [%0], [%1], 16;" :: "r"(dst), "l"(src) : "memory");
}
#define CP_COMMIT() asm volatile("cp.async.commit_group;" ::: "memory")
#define CP_WAIT0()  asm volatile("cp.async.wait_group 0;" ::: "memory")
#define CP_WAIT1()  asm volatile("cp.async.wait_group 1;" ::: "memory")

__device__ __forceinline__ void ldm4(uint32_t a, uint32_t& r0, uint32_t& r1,
                                     uint32_t& r2, uint32_t& r3) {
    asm volatile("ldmatrix.sync.aligned.m8n8.x4.shared.b16 {%0,%1,%2,%3}, [%4];"
                 : "=r"(r0), "=r"(r1), "=r"(r2), "=r"(r3) : "r"(a));
}
__device__ __forceinline__ void ldm4t(uint32_t a, uint32_t& r0, uint32_t& r1,
                                      uint32_t& r2, uint32_t& r3) {
    asm volatile("ldmatrix.sync.aligned.m8n8.x4.trans.shared.b16 {%0,%1,%2,%3}, [%4];"
                 : "=r"(r0), "=r"(r1), "=r"(r2), "=r"(r3) : "r"(a));
}

__device__ __forceinline__ void mma16816(float* c, const uint32_t* a,
                                         uint32_t b0, uint32_t b1) {
    asm volatile(
        "mma.sync.aligned.m16n8k16.row.col.f32.f16.f16.f32 "
        "{%0,%1,%2,%3},{%4,%5,%6,%7},{%8,%9},{%0,%1,%2,%3};"
        : "+f"(c[0]), "+f"(c[1]), "+f"(c[2]), "+f"(c[3])
        : "r"(a[0]), "r"(a[1]), "r"(a[2]), "r"(a[3]), "r"(b0), "r"(b1));
}

// ---------------------------------------------------------------------------
// mma.sync GEMM (fp16): 128x128 CTA tile, 8 warps 4(m)x2(n), warp 32x64.
// K-stage 32, 3-stage cp.async pipeline, one barrier per iteration
// (wait -> sync(publish) -> issue next loads -> compute).
//   C[M][N] = A · B^T  (A,B fp16 k-major)
//   EPI 0: C fp32 = acc + bias
//   EPI 1: qkv scatter -> q16 (scaled), k16, v16 per-head fp16
// ---------------------------------------------------------------------------
#define STR 40                  // halves per smem row (32 data + 8 pad)
#define GSTAGE_BYTES (2 * 128 * STR * 2)   // A + B per stage = 20480
#define GEMM_SMEM (3 * GSTAGE_BYTES)

template<int EPI>
__global__ __launch_bounds__(256) void mma_gemm(
    const ushort_t* __restrict__ A, const ushort_t* __restrict__ B,
    float* __restrict__ C, const float* __restrict__ bias,
    __half* __restrict__ oq, __half* __restrict__ ok, __half* __restrict__ ov,
    int K, int ldc)
{
    extern __shared__ __align__(16) ushort_t smg[];

    const int tid = threadIdx.x, lane = tid & 31, wid = tid >> 5;
    const int wm = wid & 3, wn = wid >> 2;            // 4 x 2 warps
    const int m0 = blockIdx.y * 128, n0 = blockIdx.x * 128;
    const int NC = K / 32;

    const uint32_t sbase = smem_u32(smg);

    float acc[2][8][4];
#pragma unroll
    for (int mi = 0; mi < 2; mi++)
#pragma unroll
        for (int j = 0; j < 8; j++)
#pragma unroll
            for (int r = 0; r < 4; r++) acc[mi][j][r] = 0.f;

    // cp.async: A/B each 128 rows x 32h; thread t loads 32B of one row each
    const int ldrow = tid >> 1;             // 0..127
    const int ldch  = (tid & 1) * 2;        // chunk 0/2 (+1)

    auto load_stage = [&](int s, int buf) {
        int k0 = s * 32;
        uint32_t ad = sbase + buf * GSTAGE_BYTES;
        uint32_t bd = ad + 128 * STR * 2;
        const ushort_t* ag = A + (size_t)(m0 + ldrow) * K + k0 + ldch * 8;
        const ushort_t* bg = B + (size_t)(n0 + ldrow) * K + k0 + ldch * 8;
        uint32_t as_ = ad + (ldrow * STR + ldch * 8) * 2;
        uint32_t bs_ = bd + (ldrow * STR + ldch * 8) * 2;
        cp16(as_, ag);          cp16(as_ + 16, ag + 8);
        cp16(bs_, bg);          cp16(bs_ + 16, bg + 8);
    };

    load_stage(0, 0); CP_COMMIT();
    load_stage(1, 1); CP_COMMIT();

    const int lr = (lane & 7) + (((lane >> 3) & 1) << 3);
    const int lc = ((lane >> 4) & 1) << 3;

    for (int c = 0; c < NC; ++c) {
        CP_WAIT1();                 // stage c landed (newest group may be in flight)
        __syncthreads();            // publish + everyone done reading stage (c-1)
        if (c + 2 < NC) load_stage(c + 2, (c + 2) % 3);   // overwrites (c-1)%3: safe
        CP_COMMIT();

        const uint32_t ab = sbase + (c % 3) * GSTAGE_BYTES;
        const uint32_t bb = ab + 128 * STR * 2;

#pragma unroll
        for (int kk = 0; kk < 32; kk += 16) {
            uint32_t a[2][4], b[4][4];
#pragma unroll
            for (int mi = 0; mi < 2; mi++)
                ldm4(ab + ((wm * 32 + mi * 16 + lr) * STR + kk + lc) * 2,
                     a[mi][0], a[mi][1], a[mi][2], a[mi][3]);
#pragma unroll
            for (int nb = 0; nb < 4; nb++)
                ldm4(bb + ((wn * 64 + nb * 16 + lr) * STR + kk + lc) * 2,
                     b[nb][0], b[nb][1], b[nb][2], b[nb][3]);
#pragma unroll
            for (int mi = 0; mi < 2; mi++)
#pragma unroll
                for (int j = 0; j < 8; j++) {
                    int nb = j >> 1, hi = j & 1;
                    mma16816(acc[mi][j], a[mi], b[nb][hi], b[nb][2 + hi]);
                }
        }
    }

    // epilogue
    const int rq = lane >> 2, cq = (lane & 3) * 2;
#pragma unroll
    for (int mi = 0; mi < 2; mi++)
#pragma unroll
        for (int j = 0; j < 8; j++)
#pragma unroll
            for (int half = 0; half < 2; half++) {
                int row = m0 + wm * 32 + mi * 16 + rq + half * 8;
                int col = n0 + wn * 64 + j * 8 + cq;
                float v0 = acc[mi][j][half * 2 + 0] + bias[col];
                float v1 = acc[mi][j][half * 2 + 1] + bias[col + 1];
                if (EPI == 0) {
                    *(float2*)(C + (size_t)row * ldc + col) = make_float2(v0, v1);
                } else {
                    int seg = col >> 10;            // 0=q 1=k 2=v
                    int ch  = col & 1023;
                    int z   = ((row >> 11) << 4) + (ch >> 6);
                    size_t dst = ((size_t)z * SEQ + (row & 2047)) * HDIM + (ch & 63);
                    if (seg == 0) { v0 *= ATTN_SCALE; v1 *= ATTN_SCALE; }
                    __half2 h = __floats2half2_rn(v0, v1);
                    __half* o = (seg == 0 ? oq : (seg == 1 ? ok : ov));
                    *(__half2*)(o + dst) = h;
                }
            }
}

// ---------------------------------------------------------------------------
// Flash attention (fp16 mma, fp32 accum/softmax).
// CTA = 128 q rows of one (b,h); 8 warps x 16 rows; key blocks of 64,
// double-buffered, one barrier per block.
// Writes att fp16 [token][h*64+d] (A operand of the fp16 out-proj GEMM).
// ---------------------------------------------------------------------------
#define STRF 72                 // halves per smem row (64 data + 8 pad)
#define FQ_BYTES (128 * STRF * 2)
#define FT_BYTES (64 * STRF * 2)
#define FLASH_SMEM (FQ_BYTES + 2 * 2 * FT_BYTES)   // Q + 2 stages x (K,V)

__global__ __launch_bounds__(256) void flash_kernel(
    const __half* __restrict__ q16, const __half* __restrict__ k16,
    const __half* __restrict__ v16, __half* __restrict__ att)
{
    extern __shared__ __align__(16) ushort_t smf[];
    const uint32_t qs = smem_u32(smf);
    const uint32_t kv0 = qs + FQ_BYTES;            // stage s: K at kv0+s*2*FT, V next

    const int tid = threadIdx.x, lane = tid & 31, wid = tid >> 5;
    const int q0 = blockIdx.x * 128;
    const int z  = blockIdx.y;
    const __half* Qg = q16 + (size_t)z * SEQ * HDIM;
    const __half* Kg = k16 + (size_t)z * SEQ * HDIM;
    const __half* Vg = v16 + (size_t)z * SEQ * HDIM;

    // ---- prologue: Q (4 chunks/thread) + KV block 0, one group
    {
#pragma unroll
        for (int i = 0; i < 4; i++) {
            int cid = tid + i * 256;                 // 1024 chunks
            int r = cid >> 3, ccol = cid & 7;
            cp16(qs + (r * STRF + ccol * 8) * 2, Qg + (size_t)(q0 + r) * HDIM + ccol * 8);
        }
        int r = tid >> 2, ccol = (tid & 3) * 2;      // 64 rows x 8 chunks, 2/thread
        uint32_t kd = kv0, vd = kv0 + FT_BYTES;
        cp16(kd + (r * STRF + ccol * 8) * 2, Kg + (size_t)r * HDIM + ccol * 8);
        cp16(kd + (r * STRF + (ccol + 1) * 8) * 2, Kg + (size_t)r * HDIM + (ccol + 1) * 8);
        cp16(vd + (r * STRF + ccol * 8) * 2, Vg + (size_t)r * HDIM + ccol * 8);
        cp16(vd + (r * STRF + (ccol + 1) * 8) * 2, Vg + (size_t)r * HDIM + (ccol + 1) * 8);
        CP_COMMIT();
    }

    float o[8][4];
#pragma unroll
    for (int j = 0; j < 8; j++)
#pragma unroll
        for (int r = 0; r < 4; r++) o[j][r] = 0.f;
    float m0 = -1e30f, m1 = -1e30f, l0 = 0.f, l1 = 0.f;

    const int lr = (lane & 7) + (((lane >> 3) & 1) << 3);
    const int lc = ((lane >> 4) & 1) << 3;
    const int qrow = wid * 16;                       // warp's 16 q rows

    const int NKB = SEQ / 64;
    for (int kb = 0; kb < NKB; ++kb) {
        CP_WAIT0();                 // KV block kb landed
        __syncthreads();            // publish + everyone done reading block kb-1
        if (kb + 1 < NKB) {         // prefetch kb+1 into (kb+1)&1: safe after sync
            int r = tid >> 2, ccol = (tid & 3) * 2;
            uint32_t kd = kv0 + ((kb + 1) & 1) * 2 * FT_BYTES;
            uint32_t vd = kd + FT_BYTES;
            const __half* Kn = Kg + (size_t)((kb + 1) * 64 + r) * HDIM;
            const __half* Vn = Vg + (size_t)((kb + 1) * 64 + r) * HDIM;
            cp16(kd + (r * STRF + ccol * 8) * 2, Kn + ccol * 8);
            cp16(kd + (r * STRF + (ccol + 1) * 8) * 2, Kn + (ccol + 1) * 8);
            cp16(vd + (r * STRF + ccol * 8) * 2, Vn + ccol * 8);
            cp16(vd + (r * STRF + (ccol + 1) * 8) * 2, Vn + (ccol + 1) * 8);
        }
        CP_COMMIT();

        const uint32_t kbuf = kv0 + (kb & 1) * 2 * FT_BYTES;
        const uint32_t vbuf = kbuf + FT_BYTES;

        // ---- S = Q @ K^T (16 x 64 per warp)
        float s[8][4];
#pragma unroll
        for (int j = 0; j < 8; j++)
#pragma unroll
            for (int r = 0; r < 4; r++) s[j][r] = 0.f;
#pragma unroll
        for (int t = 0; t < 4; t++) {                // k-steps over d
            uint32_t a[4], b[4][4];
            ldm4(qs + ((qrow + lr) * STRF + t * 16 + lc) * 2, a[0], a[1], a[2], a[3]);
#pragma unroll
            for (int nb = 0; nb < 4; nb++)
                ldm4(kbuf + ((nb * 16 + lr) * STRF + t * 16 + lc) * 2,
                     b[nb][0], b[nb][1], b[nb][2], b[nb][3]);
#pragma unroll
            for (int j = 0; j < 8; j++) {
                int nb = j >> 1, hi = j & 1;
                mma16816(s[j], a, b[nb][hi], b[nb][2 + hi]);
            }
        }

        // ---- online softmax (rows r0 = lane>>2, r1 = r0+8)
        float mx0 = -1e30f, mx1 = -1e30f;
#pragma unroll
        for (int j = 0; j < 8; j++) {
            mx0 = fmaxf(mx0, fmaxf(s[j][0], s[j][1]));
            mx1 = fmaxf(mx1, fmaxf(s[j][2], s[j][3]));
        }
        mx0 = fmaxf(mx0, __shfl_xor_sync(0xffffffffu, mx0, 1));
        mx0 = fmaxf(mx0, __shfl_xor_sync(0xffffffffu, mx0, 2));
        mx1 = fmaxf(mx1, __shfl_xor_sync(0xffffffffu, mx1, 1));
        mx1 = fmaxf(mx1, __shfl_xor_sync(0xffffffffu, mx1, 2));
        float mn0 = fmaxf(m0, mx0), mn1 = fmaxf(m1, mx1);
        float al0 = __expf(m0 - mn0), al1 = __expf(m1 - mn1);
        m0 = mn0; m1 = mn1;
        float sum0 = 0.f, sum1 = 0.f;
#pragma unroll
        for (int j = 0; j < 8; j++) {
            s[j][0] = __expf(s[j][0] - mn0);
            s[j][1] = __expf(s[j][1] - mn0);
            s[j][2] = __expf(s[j][2] - mn1);
            s[j][3] = __expf(s[j][3] - mn1);
            sum0 += s[j][0] + s[j][1];
            sum1 += s[j][2] + s[j][3];
        }
        sum0 += __shfl_xor_sync(0xffffffffu, sum0, 1);
        sum0 += __shfl_xor_sync(0xffffffffu, sum0, 2);
        sum1 += __shfl_xor_sync(0xffffffffu, sum1, 1);
        sum1 += __shfl_xor_sync(0xffffffffu, sum1, 2);
        l0 = l0 * al0 + sum0;
        l1 = l1 * al1 + sum1;
#pragma unroll
        for (int j = 0; j < 8; j++) {
            o[j][0] *= al0; o[j][1] *= al0;
            o[j][2] *= al1; o[j][3] *= al1;
        }

        // ---- O += P @ V  (P from S frags, V via ldmatrix.trans)
#pragma unroll
        for (int t = 0; t < 4; t++) {                // k-steps over keys
            uint32_t a[4];
            {
                __half2 p0 = __floats2half2_rn(s[2 * t][0], s[2 * t][1]);
                __half2 p1 = __floats2half2_rn(s[2 * t][2], s[2 * t][3]);
                __half2 p2 = __floats2half2_rn(s[2 * t + 1][0], s[2 * t + 1][1]);
                __half2 p3 = __floats2half2_rn(s[2 * t + 1][2], s[2 * t + 1][3]);
                a[0] = *(uint32_t*)&p0; a[1] = *(uint32_t*)&p1;
                a[2] = *(uint32_t*)&p2; a[3] = *(uint32_t*)&p3;
            }
#pragma unroll
            for (int db = 0; db < 4; db++) {
                uint32_t r0, r1, r2, r3;
                ldm4t(vbuf + ((t * 16 + (lane & 15)) * STRF +
                              db * 16 + ((lane >> 4) & 1) * 8) * 2,
                      r0, r1, r2, r3);
                mma16816(o[2 * db],     a, r0, r1);
                mma16816(o[2 * db + 1], a, r2, r3);
            }
        }
    }

    // ---- epilogue: att fp16 [token][h*64+d]
    const float inv0 = 1.0f / l0, inv1 = 1.0f / l1;
    const int b = z >> 4, h = z & 15;
    const int row0 = b * SEQ + q0 + qrow + (lane >> 2);
    const int colb = h * HDIM + (lane & 3) * 2;
#pragma unroll
    for (int j = 0; j < 8; j++) {
        __half2 h0 = __floats2half2_rn(o[j][0] * inv0, o[j][1] * inv0);
        __half2 h1 = __floats2half2_rn(o[j][2] * inv1, o[j][3] * inv1);
        *(__half2*)(att + (size_t)row0 * DMODEL + colb + j * 8) = h0;
        *(__half2*)(att + (size_t)(row0 + 8) * DMODEL + colb + j * 8) = h1;
    }
}

// ---------------------------------------------------------------------------
// Conversion kernels
// ---------------------------------------------------------------------------
__global__ void to_fp16_kernel(const float* __restrict__ x,
                               __half* __restrict__ y, size_t n)
{
    for (size_t i = (size_t)blockIdx.x * blockDim.x + threadIdx.x; i < n;
         i += (size_t)gridDim.x * blockDim.x)
        y[i] = __float2half(x[i]);
}

// W[K][N] -> Wt fp16 [N][K]
__global__ void wtrans_f16_kernel(const float* __restrict__ W,
                                  __half* __restrict__ T, int K, int N)
{
    __shared__ float t[32][33];
    int kx = blockIdx.y * 32, nx = blockIdx.x * 32;
    int tx = threadIdx.x, ty = threadIdx.y;   // (32, 8)
#pragma unroll
    for (int i = 0; i < 4; i++)
        t[ty + 8 * i][tx] = W[(size_t)(kx + ty + 8 * i) * N + nx + tx];
    __syncthreads();
#pragma unroll
    for (int i = 0; i < 4; i++) {
        int nl = ty + 8 * i;
        T[(size_t)(nx + nl) * K + kx + tx] = __float2half(t[tx][nl]);
    }
}

// ---------------------------------------------------------------------------
// Launch
// ---------------------------------------------------------------------------
extern "C" void kernel_launch(void* const* d_in, const int* in_sizes, int n_in,
                              void* d_out, int out_size)
{
    const float* x     = (const float*)d_in[0];
    const float* W_qkv = (const float*)d_in[1];
    const float* b_qkv = (const float*)d_in[2];
    const float* W_out = (const float*)d_in[3];
    const float* b_out = (const float*)d_in[4];
    float* out = (float*)d_out;

    __half *x16, *wq16, *wo16, *q16, *k16, *v16, *a16;
    cudaGetSymbolAddress((void**)&x16, g_x16);
    cudaGetSymbolAddress((void**)&wq16, g_wq16);
    cudaGetSymbolAddress((void**)&wo16, g_wo16);
    cudaGetSymbolAddress((void**)&q16, g_q16);
    cudaGetSymbolAddress((void**)&k16, g_k16);
    cudaGetSymbolAddress((void**)&v16, g_v16);
    cudaGetSymbolAddress((void**)&a16, g_a16);

    cudaFuncSetAttribute((const void*)mma_gemm<1>,
                         cudaFuncAttributeMaxDynamicSharedMemorySize, GEMM_SMEM);
    cudaFuncSetAttribute((const void*)mma_gemm<0>,
                         cudaFuncAttributeMaxDynamicSharedMemorySize, GEMM_SMEM);
    cudaFuncSetAttribute((const void*)flash_kernel,
                         cudaFuncAttributeMaxDynamicSharedMemorySize, FLASH_SMEM);

    // 1. x -> fp16 ; weights -> fp16 transposed
    to_fp16_kernel<<<2048, 256>>>(x, x16, (size_t)MTOK * DMODEL);
    wtrans_f16_kernel<<<dim3(3 * DMODEL / 32, DMODEL / 32), dim3(32, 8)>>>(
        W_qkv, wq16, DMODEL, 3 * DMODEL);
    wtrans_f16_kernel<<<dim3(DMODEL / 32, DMODEL / 32), dim3(32, 8)>>>(
        W_out, wo16, DMODEL, DMODEL);
    // 2. QKV projection (fp16) with fused per-head scatter epilogue
    mma_gemm<1><<<dim3(3 * DMODEL / 128, MTOK / 128), 256, GEMM_SMEM>>>(
        (const ushort_t*)x16, (const ushort_t*)wq16,
        nullptr, b_qkv, q16, k16, v16, DMODEL, 0);
    // 3. flash attention -> att fp16
    flash_kernel<<<dim3(SEQ / 128, NBH), 256, FLASH_SMEM>>>(q16, k16, v16, a16);
    // 4. out = att @ W_out + b_out (fp16 single pass, fp32 epilogue)
    mma_gemm<0><<<dim3(DMODEL / 128, MTOK / 128), 256, GEMM_SMEM>>>(
        (const ushort_t*)a16, (const ushort_t*)wo16,
        out, b_out, nullptr, nullptr, nullptr, DMODEL, DMODEL);
}

// round 11
// speedup vs baseline: 6.8937x; 1.1251x over previous
#include <cuda_runtime.h>
#include <cuda_bf16.h>
#include <cuda_fp16.h>
#include <cstdint>

// ---------------------------------------------------------------------------
// Problem constants
// ---------------------------------------------------------------------------
#define BATCH 4
#define SEQ   2048
#define NHEAD 16
#define HDIM  64
#define DMODEL 1024
#define MTOK  (BATCH * SEQ)              // 8192
#define NBH   (BATCH * NHEAD)            // 64
#define ATTN_SCALE 0.125f

typedef unsigned short ushort_t;

// ---------------------------------------------------------------------------
// Scratch (static device globals; no allocations allowed)
// ---------------------------------------------------------------------------
__device__ __half g_x16[(size_t)MTOK * DMODEL];              // x fp16
__device__ __half g_wq16[(size_t)3 * DMODEL * DMODEL];       // W_qkv^T fp16
__device__ __half g_wo16[(size_t)DMODEL * DMODEL];           // W_out^T fp16
__device__ __half g_q16[(size_t)NBH * SEQ * HDIM];           // Q*scale fp16
__device__ __half g_k16[(size_t)NBH * SEQ * HDIM];           // K fp16
__device__ __half g_v16[(size_t)NBH * SEQ * HDIM];           // V fp16
__device__ __half g_a16[(size_t)MTOK * DMODEL];              // att fp16

// ---------------------------------------------------------------------------
// PTX helpers (baseline PTX only: cp.async / ldmatrix / mma.sync)
// ---------------------------------------------------------------------------
__device__ __forceinline__ uint32_t smem_u32(const void* p) {
    uint32_t a;
    asm("{ .reg .u64 t; cvta.to.shared.u64 t, %1; cvt.u32.u64 %0, t; }" : "=r"(a) : "l"(p));
    return a;
}
__device__ __forceinline__ void cp16(uint32_t dst, const void* src) {
    asm volatile("cp.async.cg.shared.global [%0], [%1], 16;" :: "r"(dst), "l"(src) : "memory");
}
#define CP_COMMIT() asm volatile("cp.async.commit_group;" ::: "memory")
#define CP_WAIT0()  asm volatile("cp.async.wait_group 0;" ::: "memory")
#define CP_WAIT1()  asm volatile("cp.async.wait_group 1;" ::: "memory")

__device__ __forceinline__ void ldm4(uint32_t a, uint32_t& r0, uint32_t& r1,
                                     uint32_t& r2, uint32_t& r3) {
    asm volatile("ldmatrix.sync.aligned.m8n8.x4.shared.b16 {%0,%1,%2,%3}, [%4];"
                 : "=r"(r0), "=r"(r1), "=r"(r2), "=r"(r3) : "r"(a));
}
__device__ __forceinline__ void ldm4t(uint32_t a, uint32_t& r0, uint32_t& r1,
                                      uint32_t& r2, uint32_t& r3) {
    asm volatile("ldmatrix.sync.aligned.m8n8.x4.trans.shared.b16 {%0,%1,%2,%3}, [%4];"
                 : "=r"(r0), "=r"(r1), "=r"(r2), "=r"(r3) : "r"(a));
}

__device__ __forceinline__ void mma16816(float* c, const uint32_t* a,
                                         uint32_t b0, uint32_t b1) {
    asm volatile(
        "mma.sync.aligned.m16n8k16.row.col.f32.f16.f16.f32 "
        "{%0,%1,%2,%3},{%4,%5,%6,%7},{%8,%9},{%0,%1,%2,%3};"
        : "+f"(c[0]), "+f"(c[1]), "+f"(c[2]), "+f"(c[3])
        : "r"(a[0]), "r"(a[1]), "r"(a[2]), "r"(a[3]), "r"(b0), "r"(b1));
}

// ---------------------------------------------------------------------------
// mma.sync GEMM (fp16): 128x128 CTA tile, 8 warps 4(m)x2(n), warp 32x64.
// K-chunk 64, 3-stage cp.async pipeline, one barrier per chunk
// (wait -> sync(publish) -> issue next loads -> compute).
//   C[M][N] = A · B^T  (A,B fp16 k-major)
//   EPI 0: C fp32 = acc + bias
//   EPI 1: qkv scatter -> q16 (scaled), k16, v16 per-head fp16
// ---------------------------------------------------------------------------
#define STRG 72                 // halves per smem row (64 data + 8 pad)
#define GSTAGE_BYTES (2 * 128 * STRG * 2)   // A + B per stage = 36864
#define GEMM_SMEM (3 * GSTAGE_BYTES)        // 110592

template<int EPI>
__global__ __launch_bounds__(256) void mma_gemm(
    const ushort_t* __restrict__ A, const ushort_t* __restrict__ B,
    float* __restrict__ C, const float* __restrict__ bias,
    __half* __restrict__ oq, __half* __restrict__ ok, __half* __restrict__ ov,
    int K, int ldc)
{
    extern __shared__ __align__(16) ushort_t smg[];

    const int tid = threadIdx.x, lane = tid & 31, wid = tid >> 5;
    const int wm = wid & 3, wn = wid >> 2;            // 4 x 2 warps
    const int m0 = blockIdx.y * 128, n0 = blockIdx.x * 128;
    const int NC = K / 64;

    const uint32_t sbase = smem_u32(smg);

    float acc[2][8][4];
#pragma unroll
    for (int mi = 0; mi < 2; mi++)
#pragma unroll
        for (int j = 0; j < 8; j++)
#pragma unroll
            for (int r = 0; r < 4; r++) acc[mi][j][r] = 0.f;

    // cp.async: A/B each 128 rows x 64 halves (8 chunks of 16B per row);
    // 1024 chunks per tensor, 4 per thread.
    auto load_stage = [&](int s, int buf) {
        int k0 = s * 64;
        uint32_t ad = sbase + buf * GSTAGE_BYTES;
        uint32_t bd = ad + 128 * STRG * 2;
#pragma unroll
        for (int i = 0; i < 4; i++) {
            int c = tid + i * 256;
            int r = c >> 3, cc = c & 7;
            cp16(ad + (r * STRG + cc * 8) * 2, A + (size_t)(m0 + r) * K + k0 + cc * 8);
            cp16(bd + (r * STRG + cc * 8) * 2, B + (size_t)(n0 + r) * K + k0 + cc * 8);
        }
    };

    load_stage(0, 0); CP_COMMIT();
    load_stage(1, 1); CP_COMMIT();

    const int lr = (lane & 7) + (((lane >> 3) & 1) << 3);
    const int lc = ((lane >> 4) & 1) << 3;

    for (int c = 0; c < NC; ++c) {
        CP_WAIT1();                 // stage c landed (newest group may be in flight)
        __syncthreads();            // publish + everyone done reading stage (c-1)
        if (c + 2 < NC) load_stage(c + 2, (c + 2) % 3);   // overwrites (c-1)%3: safe
        CP_COMMIT();

        const uint32_t ab = sbase + (c % 3) * GSTAGE_BYTES;
        const uint32_t bb = ab + 128 * STRG * 2;

#pragma unroll
        for (int kk = 0; kk < 64; kk += 16) {
            uint32_t a[2][4], b[4][4];
#pragma unroll
            for (int mi = 0; mi < 2; mi++)
                ldm4(ab + ((wm * 32 + mi * 16 + lr) * STRG + kk + lc) * 2,
                     a[mi][0], a[mi][1], a[mi][2], a[mi][3]);
#pragma unroll
            for (int nb = 0; nb < 4; nb++)
                ldm4(bb + ((wn * 64 + nb * 16 + lr) * STRG + kk + lc) * 2,
                     b[nb][0], b[nb][1], b[nb][2], b[nb][3]);
#pragma unroll
            for (int mi = 0; mi < 2; mi++)
#pragma unroll
                for (int j = 0; j < 8; j++) {
                    int nb = j >> 1, hi = j & 1;
                    mma16816(acc[mi][j], a[mi], b[nb][hi], b[nb][2 + hi]);
                }
        }
    }

    // epilogue
    const int rq = lane >> 2, cq = (lane & 3) * 2;
#pragma unroll
    for (int mi = 0; mi < 2; mi++)
#pragma unroll
        for (int j = 0; j < 8; j++)
#pragma unroll
            for (int half = 0; half < 2; half++) {
                int row = m0 + wm * 32 + mi * 16 + rq + half * 8;
                int col = n0 + wn * 64 + j * 8 + cq;
                float v0 = acc[mi][j][half * 2 + 0] + bias[col];
                float v1 = acc[mi][j][half * 2 + 1] + bias[col + 1];
                if (EPI == 0) {
                    *(float2*)(C + (size_t)row * ldc + col) = make_float2(v0, v1);
                } else {
                    int seg = col >> 10;            // 0=q 1=k 2=v
                    int ch  = col & 1023;
                    int z   = ((row >> 11) << 4) + (ch >> 6);
                    size_t dst = ((size_t)z * SEQ + (row & 2047)) * HDIM + (ch & 63);
                    if (seg == 0) { v0 *= ATTN_SCALE; v1 *= ATTN_SCALE; }
                    __half2 h = __floats2half2_rn(v0, v1);
                    __half* o = (seg == 0 ? oq : (seg == 1 ? ok : ov));
                    *(__half2*)(o + dst) = h;
                }
            }
}

// ---------------------------------------------------------------------------
// Flash attention (fp16 mma, fp32 accum/softmax).
// CTA = 128 q rows of one (b,h); 8 warps x 16 rows; key blocks of 64,
// double-buffered, one barrier per block. Q fragments hoisted to registers
// (loaded once after the prologue wait; no per-block Q ldmatrix).
// Writes att fp16 [token][h*64+d].
// ---------------------------------------------------------------------------
#define STRF 72                 // halves per smem row (64 data + 8 pad)
#define FQ_BYTES (128 * STRF * 2)
#define FT_BYTES (64 * STRF * 2)
#define FLASH_SMEM (FQ_BYTES + 2 * 2 * FT_BYTES)   // Q + 2 stages x (K,V)

__global__ __launch_bounds__(256) void flash_kernel(
    const __half* __restrict__ q16, const __half* __restrict__ k16,
    const __half* __restrict__ v16, __half* __restrict__ att)
{
    extern __shared__ __align__(16) ushort_t smf[];
    const uint32_t qs = smem_u32(smf);
    const uint32_t kv0 = qs + FQ_BYTES;            // stage s: K at kv0+s*2*FT, V next

    const int tid = threadIdx.x, lane = tid & 31, wid = tid >> 5;
    const int q0 = blockIdx.x * 128;
    const int z  = blockIdx.y;
    const __half* Qg = q16 + (size_t)z * SEQ * HDIM;
    const __half* Kg = k16 + (size_t)z * SEQ * HDIM;
    const __half* Vg = v16 + (size_t)z * SEQ * HDIM;

    // ---- prologue: Q (4 chunks/thread) + KV block 0, one group
    {
#pragma unroll
        for (int i = 0; i < 4; i++) {
            int cid = tid + i * 256;                 // 1024 chunks
            int r = cid >> 3, ccol = cid & 7;
            cp16(qs + (r * STRF + ccol * 8) * 2, Qg + (size_t)(q0 + r) * HDIM + ccol * 8);
        }
        int r = tid >> 2, ccol = (tid & 3) * 2;      // 64 rows x 8 chunks, 2/thread
        uint32_t kd = kv0, vd = kv0 + FT_BYTES;
        cp16(kd + (r * STRF + ccol * 8) * 2, Kg + (size_t)r * HDIM + ccol * 8);
        cp16(kd + (r * STRF + (ccol + 1) * 8) * 2, Kg + (size_t)r * HDIM + (ccol + 1) * 8);
        cp16(vd + (r * STRF + ccol * 8) * 2, Vg + (size_t)r * HDIM + ccol * 8);
        cp16(vd + (r * STRF + (ccol + 1) * 8) * 2, Vg + (size_t)r * HDIM + (ccol + 1) * 8);
        CP_COMMIT();
    }

    const int lr = (lane & 7) + (((lane >> 3) & 1) << 3);
    const int lc = ((lane >> 4) & 1) << 3;
    const int qrow = wid * 16;                       // warp's 16 q rows

    // ---- wait prologue, hoist Q fragments into registers (reused all blocks)
    CP_WAIT0();
    __syncthreads();
    uint32_t qreg[4][4];
#pragma unroll
    for (int t = 0; t < 4; t++)
        ldm4(qs + ((qrow + lr) * STRF + t * 16 + lc) * 2,
             qreg[t][0], qreg[t][1], qreg[t][2], qreg[t][3]);

    float o[8][4];
#pragma unroll
    for (int j = 0; j < 8; j++)
#pragma unroll
        for (int r = 0; r < 4; r++) o[j][r] = 0.f;
    float m0 = -1e30f, m1 = -1e30f, l0 = 0.f, l1 = 0.f;

    const int NKB = SEQ / 64;
    for (int kb = 0; kb < NKB; ++kb) {
        if (kb > 0) {
            CP_WAIT0();             // KV block kb landed
            __syncthreads();        // everyone done reading block kb-1
        }
        if (kb + 1 < NKB) {         // prefetch kb+1 into (kb+1)&1: safe after sync
            int r = tid >> 2, ccol = (tid & 3) * 2;
            uint32_t kd = kv0 + ((kb + 1) & 1) * 2 * FT_BYTES;
            uint32_t vd = kd + FT_BYTES;
            const __half* Kn = Kg + (size_t)((kb + 1) * 64 + r) * HDIM;
            const __half* Vn = Vg + (size_t)((kb + 1) * 64 + r) * HDIM;
            cp16(kd + (r * STRF + ccol * 8) * 2, Kn + ccol * 8);
            cp16(kd + (r * STRF + (ccol + 1) * 8) * 2, Kn + (ccol + 1) * 8);
            cp16(vd + (r * STRF + ccol * 8) * 2, Vn + ccol * 8);
            cp16(vd + (r * STRF + (ccol + 1) * 8) * 2, Vn + (ccol + 1) * 8);
        }
        CP_COMMIT();

        const uint32_t kbuf = kv0 + (kb & 1) * 2 * FT_BYTES;
        const uint32_t vbuf = kbuf + FT_BYTES;

        // ---- S = Q @ K^T (16 x 64 per warp)
        float s[8][4];
#pragma unroll
        for (int j = 0; j < 8; j++)
#pragma unroll
            for (int r = 0; r < 4; r++) s[j][r] = 0.f;
#pragma unroll
        for (int t = 0; t < 4; t++) {                // k-steps over d
            uint32_t b[4][4];
#pragma unroll
            for (int nb = 0; nb < 4; nb++)
                ldm4(kbuf + ((nb * 16 + lr) * STRF + t * 16 + lc) * 2,
                     b[nb][0], b[nb][1], b[nb][2], b[nb][3]);
#pragma unroll
            for (int j = 0; j < 8; j++) {
                int nb = j >> 1, hi = j & 1;
                mma16816(s[j], qreg[t], b[nb][hi], b[nb][2 + hi]);
            }
        }

        // ---- online softmax (rows r0 = lane>>2, r1 = r0+8)
        float mx0 = -1e30f, mx1 = -1e30f;
#pragma unroll
        for (int j = 0; j < 8; j++) {
            mx0 = fmaxf(mx0, fmaxf(s[j][0], s[j][1]));
            mx1 = fmaxf(mx1, fmaxf(s[j][2], s[j][3]));
        }
        mx0 = fmaxf(mx0, __shfl_xor_sync(0xffffffffu, mx0, 1));
        mx0 = fmaxf(mx0, __shfl_xor_sync(0xffffffffu, mx0, 2));
        mx1 = fmaxf(mx1, __shfl_xor_sync(0xffffffffu, mx1, 1));
        mx1 = fmaxf(mx1, __shfl_xor_sync(0xffffffffu, mx1, 2));
        float mn0 = fmaxf(m0, mx0), mn1 = fmaxf(m1, mx1);
        float al0 = __expf(m0 - mn0), al1 = __expf(m1 - mn1);
        m0 = mn0; m1 = mn1;
        float sum0 = 0.f, sum1 = 0.f;
#pragma unroll
        for (int j = 0; j < 8; j++) {
            s[j][0] = __expf(s[j][0] - mn0);
            s[j][1] = __expf(s[j][1] - mn0);
            s[j][2] = __expf(s[j][2] - mn1);
            s[j][3] = __expf(s[j][3] - mn1);
            sum0 += s[j][0] + s[j][1];
            sum1 += s[j][2] + s[j][3];
        }
        sum0 += __shfl_xor_sync(0xffffffffu, sum0, 1);
        sum0 += __shfl_xor_sync(0xffffffffu, sum0, 2);
        sum1 += __shfl_xor_sync(0xffffffffu, sum1, 1);
        sum1 += __shfl_xor_sync(0xffffffffu, sum1, 2);
        l0 = l0 * al0 + sum0;
        l1 = l1 * al1 + sum1;
#pragma unroll
        for (int j = 0; j < 8; j++) {
            o[j][0] *= al0; o[j][1] *= al0;
            o[j][2] *= al1; o[j][3] *= al1;
        }

        // ---- O += P @ V  (P from S frags, V via ldmatrix.trans)
#pragma unroll
        for (int t = 0; t < 4; t++) {                // k-steps over keys
            uint32_t a[4];
            {
                __half2 p0 = __floats2half2_rn(s[2 * t][0], s[2 * t][1]);
                __half2 p1 = __floats2half2_rn(s[2 * t][2], s[2 * t][3]);
                __half2 p2 = __floats2half2_rn(s[2 * t + 1][0], s[2 * t + 1][1]);
                __half2 p3 = __floats2half2_rn(s[2 * t + 1][2], s[2 * t + 1][3]);
                a[0] = *(uint32_t*)&p0; a[1] = *(uint32_t*)&p1;
                a[2] = *(uint32_t*)&p2; a[3] = *(uint32_t*)&p3;
            }
#pragma unroll
            for (int db = 0; db < 4; db++) {
                uint32_t r0, r1, r2, r3;
                ldm4t(vbuf + ((t * 16 + (lane & 15)) * STRF +
                              db * 16 + ((lane >> 4) & 1) * 8) * 2,
                      r0, r1, r2, r3);
                mma16816(o[2 * db],     a, r0, r1);
                mma16816(o[2 * db + 1], a, r2, r3);
            }
        }
    }

    // ---- epilogue: att fp16 [token][h*64+d]
    const float inv0 = 1.0f / l0, inv1 = 1.0f / l1;
    const int b = z >> 4, h = z & 15;
    const int row0 = b * SEQ + q0 + qrow + (lane >> 2);
    const int colb = h * HDIM + (lane & 3) * 2;
#pragma unroll
    for (int j = 0; j < 8; j++) {
        __half2 h0 = __floats2half2_rn(o[j][0] * inv0, o[j][1] * inv0);
        __half2 h1 = __floats2half2_rn(o[j][2] * inv1, o[j][3] * inv1);
        *(__half2*)(att + (size_t)row0 * DMODEL + colb + j * 8) = h0;
        *(__half2*)(att + (size_t)(row0 + 8) * DMODEL + colb + j * 8) = h1;
    }
}

// ---------------------------------------------------------------------------
// Conversion kernels
// ---------------------------------------------------------------------------
__global__ void to_fp16_kernel(const float* __restrict__ x,
                               __half* __restrict__ y, size_t n)
{
    for (size_t i = (size_t)blockIdx.x * blockDim.x + threadIdx.x; i < n;
         i += (size_t)gridDim.x * blockDim.x)
        y[i] = __float2half(x[i]);
}

// W[K][N] -> Wt fp16 [N][K]
__global__ void wtrans_f16_kernel(const float* __restrict__ W,
                                  __half* __restrict__ T, int K, int N)
{
    __shared__ float t[32][33];
    int kx = blockIdx.y * 32, nx = blockIdx.x * 32;
    int tx = threadIdx.x, ty = threadIdx.y;   // (32, 8)
#pragma unroll
    for (int i = 0; i < 4; i++)
        t[ty + 8 * i][tx] = W[(size_t)(kx + ty + 8 * i) * N + nx + tx];
    __syncthreads();
#pragma unroll
    for (int i = 0; i < 4; i++) {
        int nl = ty + 8 * i;
        T[(size_t)(nx + nl) * K + kx + tx] = __float2half(t[tx][nl]);
    }
}

// ---------------------------------------------------------------------------
// Launch
// ---------------------------------------------------------------------------
extern "C" void kernel_launch(void* const* d_in, const int* in_sizes, int n_in,
                              void* d_out, int out_size)
{
    const float* x     = (const float*)d_in[0];
    const float* W_qkv = (const float*)d_in[1];
    const float* b_qkv = (const float*)d_in[2];
    const float* W_out = (const float*)d_in[3];
    const float* b_out = (const float*)d_in[4];
    float* out = (float*)d_out;

    __half *x16, *wq16, *wo16, *q16, *k16, *v16, *a16;
    cudaGetSymbolAddress((void**)&x16, g_x16);
    cudaGetSymbolAddress((void**)&wq16, g_wq16);
    cudaGetSymbolAddress((void**)&wo16, g_wo16);
    cudaGetSymbolAddress((void**)&q16, g_q16);
    cudaGetSymbolAddress((void**)&k16, g_k16);
    cudaGetSymbolAddress((void**)&v16, g_v16);
    cudaGetSymbolAddress((void**)&a16, g_a16);

    cudaFuncSetAttribute((const void*)mma_gemm<1>,
                         cudaFuncAttributeMaxDynamicSharedMemorySize, GEMM_SMEM);
    cudaFuncSetAttribute((const void*)mma_gemm<0>,
                         cudaFuncAttributeMaxDynamicSharedMemorySize, GEMM_SMEM);
    cudaFuncSetAttribute((const void*)flash_kernel,
                         cudaFuncAttributeMaxDynamicSharedMemorySize, FLASH_SMEM);

    // 1. x -> fp16 ; weights -> fp16 transposed
    to_fp16_kernel<<<2048, 256>>>(x, x16, (size_t)MTOK * DMODEL);
    wtrans_f16_kernel<<<dim3(3 * DMODEL / 32, DMODEL / 32), dim3(32, 8)>>>(
        W_qkv, wq16, DMODEL, 3 * DMODEL);
    wtrans_f16_kernel<<<dim3(DMODEL / 32, DMODEL / 32), dim3(32, 8)>>>(
        W_out, wo16, DMODEL, DMODEL);
    // 2. QKV projection (fp16) with fused per-head scatter epilogue
    mma_gemm<1><<<dim3(3 * DMODEL / 128, MTOK / 128), 256, GEMM_SMEM>>>(
        (const ushort_t*)x16, (const ushort_t*)wq16,
        nullptr, b_qkv, q16, k16, v16, DMODEL, 0);
    // 3. flash attention -> att fp16
    flash_kernel<<<dim3(SEQ / 128, NBH), 256, FLASH_SMEM>>>(q16, k16, v16, a16);
    // 4. out = att @ W_out + b_out (fp16 single pass, fp32 epilogue)
    mma_gemm<0><<<dim3(DMODEL / 128, MTOK / 128), 256, GEMM_SMEM>>>(
        (const ushort_t*)a16, (const ushort_t*)wo16,
        out, b_out, nullptr, nullptr, nullptr, DMODEL, DMODEL);
}

// round 12
// speedup vs baseline: 7.1625x; 1.0390x over previous
#include <cuda_runtime.h>
#include <cuda_bf16.h>
#include <cuda_fp16.h>
#include <cstdint>

// ---------------------------------------------------------------------------
// Problem constants
// ---------------------------------------------------------------------------
#define BATCH 4
#define SEQ   2048
#define NHEAD 16
#define HDIM  64
#define DMODEL 1024
#define MTOK  (BATCH * SEQ)              // 8192
#define NBH   (BATCH * NHEAD)            // 64
#define ATTN_SCALE 0.125f

typedef unsigned short ushort_t;

// ---------------------------------------------------------------------------
// Scratch (static device globals; no allocations allowed)
// ---------------------------------------------------------------------------
__device__ __half g_x16[(size_t)MTOK * DMODEL];              // x fp16
__device__ __half g_wq16[(size_t)3 * DMODEL * DMODEL];       // W_qkv^T fp16
__device__ __half g_wo16[(size_t)DMODEL * DMODEL];           // W_out^T fp16
__device__ __half g_q16[(size_t)NBH * SEQ * HDIM];           // Q*scale fp16
__device__ __half g_k16[(size_t)NBH * SEQ * HDIM];           // K fp16
__device__ __half g_v16[(size_t)NBH * SEQ * HDIM];           // V fp16
__device__ __half g_a16[(size_t)MTOK * DMODEL];              // att fp16

// ---------------------------------------------------------------------------
// PTX helpers (baseline PTX only: cp.async / ldmatrix / mma.sync)
// ---------------------------------------------------------------------------
__device__ __forceinline__ uint32_t smem_u32(const void* p) {
    uint32_t a;
    asm("{ .reg .u64 t; cvta.to.shared.u64 t, %1; cvt.u32.u64 %0, t; }" : "=r"(a) : "l"(p));
    return a;
}
__device__ __forceinline__ void cp16(uint32_t dst, const void* src) {
    asm volatile("cp.async.cg.shared.global [%0], [%1], 16;" :: "r"(dst), "l"(src) : "memory");
}
#define CP_COMMIT() asm volatile("cp.async.commit_group;" ::: "memory")
#define CP_WAIT0()  asm volatile("cp.async.wait_group 0;" ::: "memory")
#define CP_WAIT1()  asm volatile("cp.async.wait_group 1;" ::: "memory")

__device__ __forceinline__ void ldm4(uint32_t a, uint32_t& r0, uint32_t& r1,
                                     uint32_t& r2, uint32_t& r3) {
    asm volatile("ldmatrix.sync.aligned.m8n8.x4.shared.b16 {%0,%1,%2,%3}, [%4];"
                 : "=r"(r0), "=r"(r1), "=r"(r2), "=r"(r3) : "r"(a));
}
__device__ __forceinline__ void ldm4t(uint32_t a, uint32_t& r0, uint32_t& r1,
                                      uint32_t& r2, uint32_t& r3) {
    asm volatile("ldmatrix.sync.aligned.m8n8.x4.trans.shared.b16 {%0,%1,%2,%3}, [%4];"
                 : "=r"(r0), "=r"(r1), "=r"(r2), "=r"(r3) : "r"(a));
}

__device__ __forceinline__ void mma16816(float* c, const uint32_t* a,
                                         uint32_t b0, uint32_t b1) {
    asm volatile(
        "mma.sync.aligned.m16n8k16.row.col.f32.f16.f16.f32 "
        "{%0,%1,%2,%3},{%4,%5,%6,%7},{%8,%9},{%0,%1,%2,%3};"
        : "+f"(c[0]), "+f"(c[1]), "+f"(c[2]), "+f"(c[3])
        : "r"(a[0]), "r"(a[1]), "r"(a[2]), "r"(a[3]), "r"(b0), "r"(b1));
}

// pack two floats to half2 and apply 2^x elementwise (approx, fp16)
__device__ __forceinline__ uint32_t ex2h2(float x, float y) {
    __half2 h = __floats2half2_rn(x, y);
    uint32_t u = *(uint32_t*)&h;
    uint32_t r;
    asm("ex2.approx.f16x2 %0, %1;" : "=r"(r) : "r"(u));
    return r;
}

// ---------------------------------------------------------------------------
// mma.sync GEMM (fp16): 128x128 CTA tile, 8 warps 4(m)x2(n), warp 32x64.
// K-chunk 64, 3-stage cp.async pipeline, one barrier per chunk.
//   EPI 0: C fp32 = acc + bias
//   EPI 1: qkv scatter -> q16 (scaled), k16, v16 per-head fp16
// ---------------------------------------------------------------------------
#define STRG 72                 // halves per smem row (64 data + 8 pad)
#define GSTAGE_BYTES (2 * 128 * STRG * 2)   // A + B per stage = 36864
#define GEMM_SMEM (3 * GSTAGE_BYTES)        // 110592

template<int EPI>
__global__ __launch_bounds__(256) void mma_gemm(
    const ushort_t* __restrict__ A, const ushort_t* __restrict__ B,
    float* __restrict__ C, const float* __restrict__ bias,
    __half* __restrict__ oq, __half* __restrict__ ok, __half* __restrict__ ov,
    int K, int ldc)
{
    extern __shared__ __align__(16) ushort_t smg[];

    const int tid = threadIdx.x, lane = tid & 31, wid = tid >> 5;
    const int wm = wid & 3, wn = wid >> 2;            // 4 x 2 warps
    const int m0 = blockIdx.y * 128, n0 = blockIdx.x * 128;
    const int NC = K / 64;

    const uint32_t sbase = smem_u32(smg);

    float acc[2][8][4];
#pragma unroll
    for (int mi = 0; mi < 2; mi++)
#pragma unroll
        for (int j = 0; j < 8; j++)
#pragma unroll
            for (int r = 0; r < 4; r++) acc[mi][j][r] = 0.f;

    auto load_stage = [&](int s, int buf) {
        int k0 = s * 64;
        uint32_t ad = sbase + buf * GSTAGE_BYTES;
        uint32_t bd = ad + 128 * STRG * 2;
#pragma unroll
        for (int i = 0; i < 4; i++) {
            int c = tid + i * 256;
            int r = c >> 3, cc = c & 7;
            cp16(ad + (r * STRG + cc * 8) * 2, A + (size_t)(m0 + r) * K + k0 + cc * 8);
            cp16(bd + (r * STRG + cc * 8) * 2, B + (size_t)(n0 + r) * K + k0 + cc * 8);
        }
    };

    load_stage(0, 0); CP_COMMIT();
    load_stage(1, 1); CP_COMMIT();

    const int lr = (lane & 7) + (((lane >> 3) & 1) << 3);
    const int lc = ((lane >> 4) & 1) << 3;

    for (int c = 0; c < NC; ++c) {
        CP_WAIT1();
        __syncthreads();
        if (c + 2 < NC) load_stage(c + 2, (c + 2) % 3);
        CP_COMMIT();

        const uint32_t ab = sbase + (c % 3) * GSTAGE_BYTES;
        const uint32_t bb = ab + 128 * STRG * 2;

#pragma unroll
        for (int kk = 0; kk < 64; kk += 16) {
            uint32_t a[2][4], b[4][4];
#pragma unroll
            for (int mi = 0; mi < 2; mi++)
                ldm4(ab + ((wm * 32 + mi * 16 + lr) * STRG + kk + lc) * 2,
                     a[mi][0], a[mi][1], a[mi][2], a[mi][3]);
#pragma unroll
            for (int nb = 0; nb < 4; nb++)
                ldm4(bb + ((wn * 64 + nb * 16 + lr) * STRG + kk + lc) * 2,
                     b[nb][0], b[nb][1], b[nb][2], b[nb][3]);
#pragma unroll
            for (int mi = 0; mi < 2; mi++)
#pragma unroll
                for (int j = 0; j < 8; j++) {
                    int nb = j >> 1, hi = j & 1;
                    mma16816(acc[mi][j], a[mi], b[nb][hi], b[nb][2 + hi]);
                }
        }
    }

    const int rq = lane >> 2, cq = (lane & 3) * 2;
#pragma unroll
    for (int mi = 0; mi < 2; mi++)
#pragma unroll
        for (int j = 0; j < 8; j++)
#pragma unroll
            for (int half = 0; half < 2; half++) {
                int row = m0 + wm * 32 + mi * 16 + rq + half * 8;
                int col = n0 + wn * 64 + j * 8 + cq;
                float v0 = acc[mi][j][half * 2 + 0] + bias[col];
                float v1 = acc[mi][j][half * 2 + 1] + bias[col + 1];
                if (EPI == 0) {
                    *(float2*)(C + (size_t)row * ldc + col) = make_float2(v0, v1);
                } else {
                    int seg = col >> 10;            // 0=q 1=k 2=v
                    int ch  = col & 1023;
                    int z   = ((row >> 11) << 4) + (ch >> 6);
                    size_t dst = ((size_t)z * SEQ + (row & 2047)) * HDIM + (ch & 63);
                    if (seg == 0) { v0 *= ATTN_SCALE; v1 *= ATTN_SCALE; }
                    __half2 h = __floats2half2_rn(v0, v1);
                    __half* o = (seg == 0 ? oq : (seg == 1 ? ok : ov));
                    *(__half2*)(o + dst) = h;
                }
            }
}

// ---------------------------------------------------------------------------
// Flash attention (fp16 mma, fp32 accum; exp via ex2.approx.f16x2;
// row-sum l accumulated by MMA against a ones-column appended to V).
// CTA = 128 q rows of one (b,h); 8 warps x 16 rows; key blocks of 64,
// double-buffered, one barrier per block. Q fragments hoisted to registers.
// Writes att fp16 [token][h*64+d].
// ---------------------------------------------------------------------------
#define STRF 88                 // halves per smem row (64 data + ones/zeros + pad)
#define FQ_BYTES (128 * STRF * 2)
#define FT_BYTES (64 * STRF * 2)
#define FLASH_SMEM (FQ_BYTES + 2 * 2 * FT_BYTES)   // Q + 2 stages x (K,V)

__global__ __launch_bounds__(256) void flash_kernel(
    const __half* __restrict__ q16, const __half* __restrict__ k16,
    const __half* __restrict__ v16, __half* __restrict__ att)
{
    extern __shared__ __align__(16) ushort_t smf[];
    const uint32_t qs = smem_u32(smf);
    const uint32_t kv0 = qs + FQ_BYTES;            // stage s: K at kv0+s*2*FT, V next

    const int tid = threadIdx.x, lane = tid & 31, wid = tid >> 5;
    const int q0 = blockIdx.x * 128;
    const int z  = blockIdx.y;
    const __half* Qg = q16 + (size_t)z * SEQ * HDIM;
    const __half* Kg = k16 + (size_t)z * SEQ * HDIM;
    const __half* Vg = v16 + (size_t)z * SEQ * HDIM;

    // ---- ones column for V (both stages): col 64 = 1, cols 65..79 = 0.
    // cp.async fills only cols 0..63, so this survives all iterations.
    for (int i = tid; i < 2 * 64; i += 256) {
        int st = i >> 6, row = i & 63;
        ushort_t* vrow = smf + (FQ_BYTES + (st * 2 + 1) * FT_BYTES) / 2 + row * STRF;
        vrow[64] = 0x3C00;                       // 1.0h
#pragma unroll
        for (int c2 = 65; c2 < 80; c2++) vrow[c2] = 0;
    }

    // ---- prologue: Q (4 chunks/thread) + KV block 0, one group
    {
#pragma unroll
        for (int i = 0; i < 4; i++) {
            int cid = tid + i * 256;                 // 1024 chunks
            int r = cid >> 3, ccol = cid & 7;
            cp16(qs + (r * STRF + ccol * 8) * 2, Qg + (size_t)(q0 + r) * HDIM + ccol * 8);
        }
        int r = tid >> 2, ccol = (tid & 3) * 2;      // 64 rows x 8 chunks, 2/thread
        uint32_t kd = kv0, vd = kv0 + FT_BYTES;
        cp16(kd + (r * STRF + ccol * 8) * 2, Kg + (size_t)r * HDIM + ccol * 8);
        cp16(kd + (r * STRF + (ccol + 1) * 8) * 2, Kg + (size_t)r * HDIM + (ccol + 1) * 8);
        cp16(vd + (r * STRF + ccol * 8) * 2, Vg + (size_t)r * HDIM + ccol * 8);
        cp16(vd + (r * STRF + (ccol + 1) * 8) * 2, Vg + (size_t)r * HDIM + (ccol + 1) * 8);
        CP_COMMIT();
    }

    const int lr = (lane & 7) + (((lane >> 3) & 1) << 3);
    const int lc = ((lane >> 4) & 1) << 3;
    const int qrow = wid * 16;                       // warp's 16 q rows

    // ---- wait prologue, hoist Q fragments into registers
    CP_WAIT0();
    __syncthreads();
    uint32_t qreg[4][4];
#pragma unroll
    for (int t = 0; t < 4; t++)
        ldm4(qs + ((qrow + lr) * STRF + t * 16 + lc) * 2,
             qreg[t][0], qreg[t][1], qreg[t][2], qreg[t][3]);

    float o[8][4], o_l[4];
#pragma unroll
    for (int j = 0; j < 8; j++)
#pragma unroll
        for (int r = 0; r < 4; r++) o[j][r] = 0.f;
#pragma unroll
    for (int r = 0; r < 4; r++) o_l[r] = 0.f;
    float m0 = -1e30f, m1 = -1e30f;

    const float L2E = 1.44269504f;
    const int NKB = SEQ / 64;
    for (int kb = 0; kb < NKB; ++kb) {
        if (kb > 0) {
            CP_WAIT0();
            __syncthreads();
        }
        if (kb + 1 < NKB) {
            int r = tid >> 2, ccol = (tid & 3) * 2;
            uint32_t kd = kv0 + ((kb + 1) & 1) * 2 * FT_BYTES;
            uint32_t vd = kd + FT_BYTES;
            const __half* Kn = Kg + (size_t)((kb + 1) * 64 + r) * HDIM;
            const __half* Vn = Vg + (size_t)((kb + 1) * 64 + r) * HDIM;
            cp16(kd + (r * STRF + ccol * 8) * 2, Kn + ccol * 8);
            cp16(kd + (r * STRF + (ccol + 1) * 8) * 2, Kn + (ccol + 1) * 8);
            cp16(vd + (r * STRF + ccol * 8) * 2, Vn + ccol * 8);
            cp16(vd + (r * STRF + (ccol + 1) * 8) * 2, Vn + (ccol + 1) * 8);
        }
        CP_COMMIT();

        const uint32_t kbuf = kv0 + (kb & 1) * 2 * FT_BYTES;
        const uint32_t vbuf = kbuf + FT_BYTES;

        // ---- S = Q @ K^T (16 x 64 per warp)
        float s[8][4];
#pragma unroll
        for (int j = 0; j < 8; j++)
#pragma unroll
            for (int r = 0; r < 4; r++) s[j][r] = 0.f;
#pragma unroll
        for (int t = 0; t < 4; t++) {
            uint32_t b[4][4];
#pragma unroll
            for (int nb = 0; nb < 4; nb++)
                ldm4(kbuf + ((nb * 16 + lr) * STRF + t * 16 + lc) * 2,
                     b[nb][0], b[nb][1], b[nb][2], b[nb][3]);
#pragma unroll
            for (int j = 0; j < 8; j++) {
                int nb = j >> 1, hi = j & 1;
                mma16816(s[j], qreg[t], b[nb][hi], b[nb][2 + hi]);
            }
        }

        // ---- online max update (rows r0 = lane>>2, r1 = r0+8)
        float mx0 = -1e30f, mx1 = -1e30f;
#pragma unroll
        for (int j = 0; j < 8; j++) {
            mx0 = fmaxf(mx0, fmaxf(s[j][0], s[j][1]));
            mx1 = fmaxf(mx1, fmaxf(s[j][2], s[j][3]));
        }
        mx0 = fmaxf(mx0, __shfl_xor_sync(0xffffffffu, mx0, 1));
        mx0 = fmaxf(mx0, __shfl_xor_sync(0xffffffffu, mx0, 2));
        mx1 = fmaxf(mx1, __shfl_xor_sync(0xffffffffu, mx1, 1));
        mx1 = fmaxf(mx1, __shfl_xor_sync(0xffffffffu, mx1, 2));
        float mn0 = fmaxf(m0, mx0), mn1 = fmaxf(m1, mx1);
        float al0 = __expf(m0 - mn0), al1 = __expf(m1 - mn1);
        m0 = mn0; m1 = mn1;
#pragma unroll
        for (int j = 0; j < 8; j++) {
            o[j][0] *= al0; o[j][1] *= al0;
            o[j][2] *= al1; o[j][3] *= al1;
        }
        o_l[0] *= al0; o_l[1] *= al0;
        o_l[2] *= al1; o_l[3] *= al1;

        // ---- O += P @ [V | 1]  (P = 2^((s-m)*log2e) in fp16, built inline)
        const float c0 = mn0 * L2E, c1 = mn1 * L2E;
#pragma unroll
        for (int t = 0; t < 4; t++) {
            uint32_t a[4];
            a[0] = ex2h2(s[2 * t][0] * L2E - c0, s[2 * t][1] * L2E - c0);
            a[1] = ex2h2(s[2 * t][2] * L2E - c1, s[2 * t][3] * L2E - c1);
            a[2] = ex2h2(s[2 * t + 1][0] * L2E - c0, s[2 * t + 1][1] * L2E - c0);
            a[3] = ex2h2(s[2 * t + 1][2] * L2E - c1, s[2 * t + 1][3] * L2E - c1);
#pragma unroll
            for (int db = 0; db < 4; db++) {
                uint32_t r0, r1, r2, r3;
                ldm4t(vbuf + ((t * 16 + (lane & 15)) * STRF +
                              db * 16 + ((lane >> 4) & 1) * 8) * 2,
                      r0, r1, r2, r3);
                mma16816(o[2 * db],     a, r0, r1);
                mma16816(o[2 * db + 1], a, r2, r3);
            }
            // ones column (cols 64..79): row sums into o_l
            {
                uint32_t r0, r1, r2, r3;
                ldm4t(vbuf + ((t * 16 + (lane & 15)) * STRF +
                              64 + ((lane >> 4) & 1) * 8) * 2,
                      r0, r1, r2, r3);
                mma16816(o_l, a, r0, r1);
            }
        }
    }

    // ---- epilogue: l lives in o_l col 64 (lanes with lane%4==0); broadcast
    float l0 = __shfl_sync(0xffffffffu, o_l[0], lane & 28);
    float l1 = __shfl_sync(0xffffffffu, o_l[2], lane & 28);
    const float inv0 = 1.0f / l0, inv1 = 1.0f / l1;
    const int b = z >> 4, h = z & 15;
    const int row0 = b * SEQ + q0 + qrow + (lane >> 2);
    const int colb = h * HDIM + (lane & 3) * 2;
#pragma unroll
    for (int j = 0; j < 8; j++) {
        __half2 h0 = __floats2half2_rn(o[j][0] * inv0, o[j][1] * inv0);
        __half2 h1 = __floats2half2_rn(o[j][2] * inv1, o[j][3] * inv1);
        *(__half2*)(att + (size_t)row0 * DMODEL + colb + j * 8) = h0;
        *(__half2*)(att + (size_t)(row0 + 8) * DMODEL + colb + j * 8) = h1;
    }
}

// ---------------------------------------------------------------------------
// Conversion kernels
// ---------------------------------------------------------------------------
__global__ void to_fp16_kernel(const float* __restrict__ x,
                               __half* __restrict__ y, size_t n)
{
    for (size_t i = (size_t)blockIdx.x * blockDim.x + threadIdx.x; i < n;
         i += (size_t)gridDim.x * blockDim.x)
        y[i] = __float2half(x[i]);
}

// W[K][N] -> Wt fp16 [N][K]
__global__ void wtrans_f16_kernel(const float* __restrict__ W,
                                  __half* __restrict__ T, int K, int N)
{
    __shared__ float t[32][33];
    int kx = blockIdx.y * 32, nx = blockIdx.x * 32;
    int tx = threadIdx.x, ty = threadIdx.y;   // (32, 8)
#pragma unroll
    for (int i = 0; i < 4; i++)
        t[ty + 8 * i][tx] = W[(size_t)(kx + ty + 8 * i) * N + nx + tx];
    __syncthreads();
#pragma unroll
    for (int i = 0; i < 4; i++) {
        int nl = ty + 8 * i;
        T[(size_t)(nx + nl) * K + kx + tx] = __float2half(t[tx][nl]);
    }
}

// ---------------------------------------------------------------------------
// Launch
// ---------------------------------------------------------------------------
extern "C" void kernel_launch(void* const* d_in, const int* in_sizes, int n_in,
                              void* d_out, int out_size)
{
    const float* x     = (const float*)d_in[0];
    const float* W_qkv = (const float*)d_in[1];
    const float* b_qkv = (const float*)d_in[2];
    const float* W_out = (const float*)d_in[3];
    const float* b_out = (const float*)d_in[4];
    float* out = (float*)d_out;

    __half *x16, *wq16, *wo16, *q16, *k16, *v16, *a16;
    cudaGetSymbolAddress((void**)&x16, g_x16);
    cudaGetSymbolAddress((void**)&wq16, g_wq16);
    cudaGetSymbolAddress((void**)&wo16, g_wo16);
    cudaGetSymbolAddress((void**)&q16, g_q16);
    cudaGetSymbolAddress((void**)&k16, g_k16);
    cudaGetSymbolAddress((void**)&v16, g_v16);
    cudaGetSymbolAddress((void**)&a16, g_a16);

    cudaFuncSetAttribute((const void*)mma_gemm<1>,
                         cudaFuncAttributeMaxDynamicSharedMemorySize, GEMM_SMEM);
    cudaFuncSetAttribute((const void*)mma_gemm<0>,
                         cudaFuncAttributeMaxDynamicSharedMemorySize, GEMM_SMEM);
    cudaFuncSetAttribute((const void*)flash_kernel,
                         cudaFuncAttributeMaxDynamicSharedMemorySize, FLASH_SMEM);

    // 1. x -> fp16 ; weights -> fp16 transposed
    to_fp16_kernel<<<2048, 256>>>(x, x16, (size_t)MTOK * DMODEL);
    wtrans_f16_kernel<<<dim3(3 * DMODEL / 32, DMODEL / 32), dim3(32, 8)>>>(
        W_qkv, wq16, DMODEL, 3 * DMODEL);
    wtrans_f16_kernel<<<dim3(DMODEL / 32, DMODEL / 32), dim3(32, 8)>>>(
        W_out, wo16, DMODEL, DMODEL);
    // 2. QKV projection (fp16) with fused per-head scatter epilogue
    mma_gemm<1><<<dim3(3 * DMODEL / 128, MTOK / 128), 256, GEMM_SMEM>>>(
        (const ushort_t*)x16, (const ushort_t*)wq16,
        nullptr, b_qkv, q16, k16, v16, DMODEL, 0);
    // 3. flash attention -> att fp16
    flash_kernel<<<dim3(SEQ / 128, NBH), 256, FLASH_SMEM>>>(q16, k16, v16, a16);
    // 4. out = att @ W_out + b_out (fp16 single pass, fp32 epilogue)
    mma_gemm<0><<<dim3(DMODEL / 128, MTOK / 128), 256, GEMM_SMEM>>>(
        (const ushort_t*)a16, (const ushort_t*)wo16,
        out, b_out, nullptr, nullptr, nullptr, DMODEL, DMODEL);
}

// round 13
// speedup vs baseline: 7.5797x; 1.0582x over previous
#include <cuda_runtime.h>
#include <cuda_bf16.h>
#include <cuda_fp16.h>
#include <cstdint>

// ---------------------------------------------------------------------------
// Problem constants
// ---------------------------------------------------------------------------
#define BATCH 4
#define SEQ   2048
#define NHEAD 16
#define HDIM  64
#define DMODEL 1024
#define MTOK  (BATCH * SEQ)              // 8192
#define NBH   (BATCH * NHEAD)            // 64
#define ATTN_SCALE 0.125f

typedef unsigned short ushort_t;

// ---------------------------------------------------------------------------
// Scratch (static device globals; no allocations allowed)
// ---------------------------------------------------------------------------
__device__ __half g_x16[(size_t)MTOK * DMODEL];              // x fp16
__device__ __half g_wq16[(size_t)3 * DMODEL * DMODEL];       // W_qkv^T fp16
__device__ __half g_wo16[(size_t)DMODEL * DMODEL];           // W_out^T fp16
__device__ __half g_q16[(size_t)NBH * SEQ * HDIM];           // Q*scale fp16
__device__ __half g_k16[(size_t)NBH * SEQ * HDIM];           // K fp16
__device__ __half g_v16[(size_t)NBH * SEQ * HDIM];           // V fp16
__device__ __half g_a16[(size_t)MTOK * DMODEL];              // att fp16

// ---------------------------------------------------------------------------
// PTX helpers (baseline PTX only: cp.async / ldmatrix / mma.sync)
// ---------------------------------------------------------------------------
__device__ __forceinline__ uint32_t smem_u32(const void* p) {
    uint32_t a;
    asm("{ .reg .u64 t; cvta.to.shared.u64 t, %1; cvt.u32.u64 %0, t; }" : "=r"(a) : "l"(p));
    return a;
}
__device__ __forceinline__ void cp16(uint32_t dst, const void* src) {
    asm volatile("cp.async.cg.shared.global [%0], [%1], 16;" :: "r"(dst), "l"(src) : "memory");
}
#define CP_COMMIT() asm volatile("cp.async.commit_group;" ::: "memory")
#define CP_WAIT0()  asm volatile("cp.async.wait_group 0;" ::: "memory")
#define CP_WAIT1()  asm volatile("cp.async.wait_group 1;" ::: "memory")

__device__ __forceinline__ void ldm4(uint32_t a, uint32_t& r0, uint32_t& r1,
                                     uint32_t& r2, uint32_t& r3) {
    asm volatile("ldmatrix.sync.aligned.m8n8.x4.shared.b16 {%0,%1,%2,%3}, [%4];"
                 : "=r"(r0), "=r"(r1), "=r"(r2), "=r"(r3) : "r"(a));
}
__device__ __forceinline__ void ldm4t(uint32_t a, uint32_t& r0, uint32_t& r1,
                                      uint32_t& r2, uint32_t& r3) {
    asm volatile("ldmatrix.sync.aligned.m8n8.x4.trans.shared.b16 {%0,%1,%2,%3}, [%4];"
                 : "=r"(r0), "=r"(r1), "=r"(r2), "=r"(r3) : "r"(a));
}

__device__ __forceinline__ void mma16816(float* c, const uint32_t* a,
                                         uint32_t b0, uint32_t b1) {
    asm volatile(
        "mma.sync.aligned.m16n8k16.row.col.f32.f16.f16.f32 "
        "{%0,%1,%2,%3},{%4,%5,%6,%7},{%8,%9},{%0,%1,%2,%3};"
        : "+f"(c[0]), "+f"(c[1]), "+f"(c[2]), "+f"(c[3])
        : "r"(a[0]), "r"(a[1]), "r"(a[2]), "r"(a[3]), "r"(b0), "r"(b1));
}

// pack two floats to half2 and apply 2^x elementwise (approx, fp16)
__device__ __forceinline__ uint32_t ex2h2(float x, float y) {
    __half2 h = __floats2half2_rn(x, y);
    uint32_t u = *(uint32_t*)&h;
    uint32_t r;
    asm("ex2.approx.f16x2 %0, %1;" : "=r"(r) : "r"(u));
    return r;
}

// ---------------------------------------------------------------------------
// mma.sync GEMM (fp16): 128x128 CTA tile, 8 warps 4(m)x2(n), warp 32x64.
// K-chunk 64, 3-stage cp.async pipeline, one barrier per chunk.
// First k-step fragments are loaded BEFORE the prefetch burst so the LDSM
// latency shadow absorbs the cp.async issue cost.
//   EPI 0: C fp32 = acc + bias
//   EPI 1: qkv scatter -> q16 (scaled), k16, v16 per-head fp16
// ---------------------------------------------------------------------------
#define STRG 72                 // halves per smem row (64 data + 8 pad)
#define GSTAGE_BYTES (2 * 128 * STRG * 2)   // A + B per stage = 36864
#define GEMM_SMEM (3 * GSTAGE_BYTES)        // 110592

template<int EPI>
__global__ __launch_bounds__(256) void mma_gemm(
    const ushort_t* __restrict__ A, const ushort_t* __restrict__ B,
    float* __restrict__ C, const float* __restrict__ bias,
    __half* __restrict__ oq, __half* __restrict__ ok, __half* __restrict__ ov,
    int K, int ldc)
{
    extern __shared__ __align__(16) ushort_t smg[];

    const int tid = threadIdx.x, lane = tid & 31, wid = tid >> 5;
    const int wm = wid & 3, wn = wid >> 2;            // 4 x 2 warps
    const int m0 = blockIdx.y * 128, n0 = blockIdx.x * 128;
    const int NC = K / 64;

    const uint32_t sbase = smem_u32(smg);

    float acc[2][8][4];
#pragma unroll
    for (int mi = 0; mi < 2; mi++)
#pragma unroll
        for (int j = 0; j < 8; j++)
#pragma unroll
            for (int r = 0; r < 4; r++) acc[mi][j][r] = 0.f;

    auto load_stage = [&](int s, int buf) {
        int k0 = s * 64;
        uint32_t ad = sbase + buf * GSTAGE_BYTES;
        uint32_t bd = ad + 128 * STRG * 2;
#pragma unroll
        for (int i = 0; i < 4; i++) {
            int c = tid + i * 256;
            int r = c >> 3, cc = c & 7;
            cp16(ad + (r * STRG + cc * 8) * 2, A + (size_t)(m0 + r) * K + k0 + cc * 8);
            cp16(bd + (r * STRG + cc * 8) * 2, B + (size_t)(n0 + r) * K + k0 + cc * 8);
        }
    };

    load_stage(0, 0); CP_COMMIT();
    load_stage(1, 1); CP_COMMIT();

    const int lr = (lane & 7) + (((lane >> 3) & 1) << 3);
    const int lc = ((lane >> 4) & 1) << 3;

    int cur = 0, pre = 2;
    for (int c = 0; c < NC; ++c) {
        CP_WAIT1();
        __syncthreads();

        const uint32_t ab = sbase + cur * GSTAGE_BYTES;
        const uint32_t bb = ab + 128 * STRG * 2;

        // peel kk = 0 fragment loads (issue before the prefetch burst)
        uint32_t a0[2][4], b0[4][4];
#pragma unroll
        for (int mi = 0; mi < 2; mi++)
            ldm4(ab + ((wm * 32 + mi * 16 + lr) * STRG + lc) * 2,
                 a0[mi][0], a0[mi][1], a0[mi][2], a0[mi][3]);
#pragma unroll
        for (int nb = 0; nb < 4; nb++)
            ldm4(bb + ((wn * 64 + nb * 16 + lr) * STRG + lc) * 2,
                 b0[nb][0], b0[nb][1], b0[nb][2], b0[nb][3]);

        if (c + 2 < NC) load_stage(c + 2, pre);
        CP_COMMIT();

        // mma kk = 0
#pragma unroll
        for (int mi = 0; mi < 2; mi++)
#pragma unroll
            for (int j = 0; j < 8; j++) {
                int nb = j >> 1, hi = j & 1;
                mma16816(acc[mi][j], a0[mi], b0[nb][hi], b0[nb][2 + hi]);
            }

        // kk = 16, 32, 48
#pragma unroll
        for (int kk = 16; kk < 64; kk += 16) {
            uint32_t a[2][4], b[4][4];
#pragma unroll
            for (int mi = 0; mi < 2; mi++)
                ldm4(ab + ((wm * 32 + mi * 16 + lr) * STRG + kk + lc) * 2,
                     a[mi][0], a[mi][1], a[mi][2], a[mi][3]);
#pragma unroll
            for (int nb = 0; nb < 4; nb++)
                ldm4(bb + ((wn * 64 + nb * 16 + lr) * STRG + kk + lc) * 2,
                     b[nb][0], b[nb][1], b[nb][2], b[nb][3]);
#pragma unroll
            for (int mi = 0; mi < 2; mi++)
#pragma unroll
                for (int j = 0; j < 8; j++) {
                    int nb = j >> 1, hi = j & 1;
                    mma16816(acc[mi][j], a[mi], b[nb][hi], b[nb][2 + hi]);
                }
        }
        cur = (cur == 2) ? 0 : cur + 1;
        pre = (pre == 2) ? 0 : pre + 1;
    }

    const int rq = lane >> 2, cq = (lane & 3) * 2;
#pragma unroll
    for (int mi = 0; mi < 2; mi++)
#pragma unroll
        for (int j = 0; j < 8; j++)
#pragma unroll
            for (int half = 0; half < 2; half++) {
                int row = m0 + wm * 32 + mi * 16 + rq + half * 8;
                int col = n0 + wn * 64 + j * 8 + cq;
                float v0 = acc[mi][j][half * 2 + 0] + bias[col];
                float v1 = acc[mi][j][half * 2 + 1] + bias[col + 1];
                if (EPI == 0) {
                    *(float2*)(C + (size_t)row * ldc + col) = make_float2(v0, v1);
                } else {
                    int seg = col >> 10;            // 0=q 1=k 2=v
                    int ch  = col & 1023;
                    int z   = ((row >> 11) << 4) + (ch >> 6);
                    size_t dst = ((size_t)z * SEQ + (row & 2047)) * HDIM + (ch & 63);
                    if (seg == 0) { v0 *= ATTN_SCALE; v1 *= ATTN_SCALE; }
                    __half2 h = __floats2half2_rn(v0, v1);
                    __half* o = (seg == 0 ? oq : (seg == 1 ? ok : ov));
                    *(__half2*)(o + dst) = h;
                }
            }
}

// ---------------------------------------------------------------------------
// Flash attention (fp16 mma, fp32 accum; exp via ex2.approx.f16x2;
// row-sum l via ones-column MMA; alpha-rescale skipped when max unchanged).
// CTA = 128 q rows of one (b,h); 8 warps x 16 rows; key blocks of 64,
// double-buffered, one barrier per block. Q fragments hoisted to registers.
// Writes att fp16 [token][h*64+d].
// ---------------------------------------------------------------------------
#define STRF 88                 // halves per smem row (64 data + ones/zeros + pad)
#define FQ_BYTES (128 * STRF * 2)
#define FT_BYTES (64 * STRF * 2)
#define FLASH_SMEM (FQ_BYTES + 2 * 2 * FT_BYTES)   // Q + 2 stages x (K,V)

__global__ __launch_bounds__(256) void flash_kernel(
    const __half* __restrict__ q16, const __half* __restrict__ k16,
    const __half* __restrict__ v16, __half* __restrict__ att)
{
    extern __shared__ __align__(16) ushort_t smf[];
    const uint32_t qs = smem_u32(smf);
    const uint32_t kv0 = qs + FQ_BYTES;            // stage s: K at kv0+s*2*FT, V next

    const int tid = threadIdx.x, lane = tid & 31, wid = tid >> 5;
    const int q0 = blockIdx.x * 128;
    const int z  = blockIdx.y;
    const __half* Qg = q16 + (size_t)z * SEQ * HDIM;
    const __half* Kg = k16 + (size_t)z * SEQ * HDIM;
    const __half* Vg = v16 + (size_t)z * SEQ * HDIM;

    // ---- ones column for V (both stages): col 64 = 1, cols 65..79 = 0.
    for (int i = tid; i < 2 * 64; i += 256) {
        int st = i >> 6, row = i & 63;
        ushort_t* vrow = smf + (FQ_BYTES + (st * 2 + 1) * FT_BYTES) / 2 + row * STRF;
        vrow[64] = 0x3C00;                       // 1.0h
#pragma unroll
        for (int c2 = 65; c2 < 80; c2++) vrow[c2] = 0;
    }

    // ---- prologue: Q (4 chunks/thread) + KV block 0, one group
    {
#pragma unroll
        for (int i = 0; i < 4; i++) {
            int cid = tid + i * 256;                 // 1024 chunks
            int r = cid >> 3, ccol = cid & 7;
            cp16(qs + (r * STRF + ccol * 8) * 2, Qg + (size_t)(q0 + r) * HDIM + ccol * 8);
        }
        int r = tid >> 2, ccol = (tid & 3) * 2;      // 64 rows x 8 chunks, 2/thread
        uint32_t kd = kv0, vd = kv0 + FT_BYTES;
        cp16(kd + (r * STRF + ccol * 8) * 2, Kg + (size_t)r * HDIM + ccol * 8);
        cp16(kd + (r * STRF + (ccol + 1) * 8) * 2, Kg + (size_t)r * HDIM + (ccol + 1) * 8);
        cp16(vd + (r * STRF + ccol * 8) * 2, Vg + (size_t)r * HDIM + ccol * 8);
        cp16(vd + (r * STRF + (ccol + 1) * 8) * 2, Vg + (size_t)r * HDIM + (ccol + 1) * 8);
        CP_COMMIT();
    }

    const int lr = (lane & 7) + (((lane >> 3) & 1) << 3);
    const int lc = ((lane >> 4) & 1) << 3;
    const int qrow = wid * 16;                       // warp's 16 q rows

    // ---- wait prologue, hoist Q fragments into registers
    CP_WAIT0();
    __syncthreads();
    uint32_t qreg[4][4];
#pragma unroll
    for (int t = 0; t < 4; t++)
        ldm4(qs + ((qrow + lr) * STRF + t * 16 + lc) * 2,
             qreg[t][0], qreg[t][1], qreg[t][2], qreg[t][3]);

    float o[8][4], o_l[4];
#pragma unroll
    for (int j = 0; j < 8; j++)
#pragma unroll
        for (int r = 0; r < 4; r++) o[j][r] = 0.f;
#pragma unroll
    for (int r = 0; r < 4; r++) o_l[r] = 0.f;
    float m0 = -1e30f, m1 = -1e30f;

    const float L2E = 1.44269504f;
    const int NKB = SEQ / 64;
    for (int kb = 0; kb < NKB; ++kb) {
        if (kb > 0) {
            CP_WAIT0();
            __syncthreads();
        }
        const uint32_t kbuf = kv0 + (kb & 1) * 2 * FT_BYTES;
        const uint32_t vbuf = kbuf + FT_BYTES;

        // peel t = 0 K-fragment loads before prefetch burst
        uint32_t b0[4][4];
#pragma unroll
        for (int nb = 0; nb < 4; nb++)
            ldm4(kbuf + ((nb * 16 + lr) * STRF + lc) * 2,
                 b0[nb][0], b0[nb][1], b0[nb][2], b0[nb][3]);

        if (kb + 1 < NKB) {
            int r = tid >> 2, ccol = (tid & 3) * 2;
            uint32_t kd = kv0 + ((kb + 1) & 1) * 2 * FT_BYTES;
            uint32_t vd = kd + FT_BYTES;
            const __half* Kn = Kg + (size_t)((kb + 1) * 64 + r) * HDIM;
            const __half* Vn = Vg + (size_t)((kb + 1) * 64 + r) * HDIM;
            cp16(kd + (r * STRF + ccol * 8) * 2, Kn + ccol * 8);
            cp16(kd + (r * STRF + (ccol + 1) * 8) * 2, Kn + (ccol + 1) * 8);
            cp16(vd + (r * STRF + ccol * 8) * 2, Vn + ccol * 8);
            cp16(vd + (r * STRF + (ccol + 1) * 8) * 2, Vn + (ccol + 1) * 8);
        }
        CP_COMMIT();

        // ---- S = Q @ K^T (16 x 64 per warp)
        float s[8][4];
#pragma unroll
        for (int j = 0; j < 8; j++)
#pragma unroll
            for (int r = 0; r < 4; r++) s[j][r] = 0.f;
#pragma unroll
        for (int j = 0; j < 8; j++) {
            int nb = j >> 1, hi = j & 1;
            mma16816(s[j], qreg[0], b0[nb][hi], b0[nb][2 + hi]);
        }
#pragma unroll
        for (int t = 1; t < 4; t++) {
            uint32_t b[4][4];
#pragma unroll
            for (int nb = 0; nb < 4; nb++)
                ldm4(kbuf + ((nb * 16 + lr) * STRF + t * 16 + lc) * 2,
                     b[nb][0], b[nb][1], b[nb][2], b[nb][3]);
#pragma unroll
            for (int j = 0; j < 8; j++) {
                int nb = j >> 1, hi = j & 1;
                mma16816(s[j], qreg[t], b[nb][hi], b[nb][2 + hi]);
            }
        }

        // ---- online max update (rows r0 = lane>>2, r1 = r0+8)
        float mx0 = -1e30f, mx1 = -1e30f;
#pragma unroll
        for (int j = 0; j < 8; j++) {
            mx0 = fmaxf(mx0, fmaxf(s[j][0], s[j][1]));
            mx1 = fmaxf(mx1, fmaxf(s[j][2], s[j][3]));
        }
        mx0 = fmaxf(mx0, __shfl_xor_sync(0xffffffffu, mx0, 1));
        mx0 = fmaxf(mx0, __shfl_xor_sync(0xffffffffu, mx0, 2));
        mx1 = fmaxf(mx1, __shfl_xor_sync(0xffffffffu, mx1, 1));
        mx1 = fmaxf(mx1, __shfl_xor_sync(0xffffffffu, mx1, 2));
        float mn0 = fmaxf(m0, mx0), mn1 = fmaxf(m1, mx1);
        bool nochange = (mn0 == m0) && (mn1 == m1);
        if (!__all_sync(0xffffffffu, nochange)) {
            float al0 = __expf(m0 - mn0), al1 = __expf(m1 - mn1);
#pragma unroll
            for (int j = 0; j < 8; j++) {
                o[j][0] *= al0; o[j][1] *= al0;
                o[j][2] *= al1; o[j][3] *= al1;
            }
            o_l[0] *= al0; o_l[1] *= al0;
            o_l[2] *= al1; o_l[3] *= al1;
        }
        m0 = mn0; m1 = mn1;

        // ---- O += P @ [V | 1]  (P = 2^((s-m)*log2e) in fp16, built inline)
        const float c0 = mn0 * L2E, c1 = mn1 * L2E;
#pragma unroll
        for (int t = 0; t < 4; t++) {
            uint32_t a[4];
            a[0] = ex2h2(s[2 * t][0] * L2E - c0, s[2 * t][1] * L2E - c0);
            a[1] = ex2h2(s[2 * t][2] * L2E - c1, s[2 * t][3] * L2E - c1);
            a[2] = ex2h2(s[2 * t + 1][0] * L2E - c0, s[2 * t + 1][1] * L2E - c0);
            a[3] = ex2h2(s[2 * t + 1][2] * L2E - c1, s[2 * t + 1][3] * L2E - c1);
#pragma unroll
            for (int db = 0; db < 4; db++) {
                uint32_t r0, r1, r2, r3;
                ldm4t(vbuf + ((t * 16 + (lane & 15)) * STRF +
                              db * 16 + ((lane >> 4) & 1) * 8) * 2,
                      r0, r1, r2, r3);
                mma16816(o[2 * db],     a, r0, r1);
                mma16816(o[2 * db + 1], a, r2, r3);
            }
            // ones column (cols 64..79): row sums into o_l
            {
                uint32_t r0, r1, r2, r3;
                ldm4t(vbuf + ((t * 16 + (lane & 15)) * STRF +
                              64 + ((lane >> 4) & 1) * 8) * 2,
                      r0, r1, r2, r3);
                mma16816(o_l, a, r0, r1);
            }
        }
    }

    // ---- epilogue: l lives in o_l col 64 (lanes with lane%4==0); broadcast
    float l0 = __shfl_sync(0xffffffffu, o_l[0], lane & 28);
    float l1 = __shfl_sync(0xffffffffu, o_l[2], lane & 28);
    const float inv0 = 1.0f / l0, inv1 = 1.0f / l1;
    const int b = z >> 4, h = z & 15;
    const int row0 = b * SEQ + q0 + qrow + (lane >> 2);
    const int colb = h * HDIM + (lane & 3) * 2;
#pragma unroll
    for (int j = 0; j < 8; j++) {
        __half2 h0 = __floats2half2_rn(o[j][0] * inv0, o[j][1] * inv0);
        __half2 h1 = __floats2half2_rn(o[j][2] * inv1, o[j][3] * inv1);
        *(__half2*)(att + (size_t)row0 * DMODEL + colb + j * 8) = h0;
        *(__half2*)(att + (size_t)(row0 + 8) * DMODEL + colb + j * 8) = h1;
    }
}

// ---------------------------------------------------------------------------
// Conversion kernels
// ---------------------------------------------------------------------------
__global__ void to_fp16_kernel(const float* __restrict__ x,
                               __half* __restrict__ y, size_t n)
{
    const float4* x4 = (const float4*)x;
    uint2* y4 = (uint2*)y;
    for (size_t i = (size_t)blockIdx.x * blockDim.x + threadIdx.x; i < n / 4;
         i += (size_t)gridDim.x * blockDim.x) {
        float4 f = x4[i];
        __half2 a = __floats2half2_rn(f.x, f.y);
        __half2 b = __floats2half2_rn(f.z, f.w);
        uint2 u;
        u.x = *(uint32_t*)&a;
        u.y = *(uint32_t*)&b;
        y4[i] = u;
    }
}

// W[K][N] -> Wt fp16 [N][K]
__global__ void wtrans_f16_kernel(const float* __restrict__ W,
                                  __half* __restrict__ T, int K, int N)
{
    __shared__ float t[32][33];
    int kx = blockIdx.y * 32, nx = blockIdx.x * 32;
    int tx = threadIdx.x, ty = threadIdx.y;   // (32, 8)
#pragma unroll
    for (int i = 0; i < 4; i++)
        t[ty + 8 * i][tx] = W[(size_t)(kx + ty + 8 * i) * N + nx + tx];
    __syncthreads();
#pragma unroll
    for (int i = 0; i < 4; i++) {
        int nl = ty + 8 * i;
        T[(size_t)(nx + nl) * K + kx + tx] = __float2half(t[tx][nl]);
    }
}

// ---------------------------------------------------------------------------
// Launch
// ---------------------------------------------------------------------------
extern "C" void kernel_launch(void* const* d_in, const int* in_sizes, int n_in,
                              void* d_out, int out_size)
{
    const float* x     = (const float*)d_in[0];
    const float* W_qkv = (const float*)d_in[1];
    const float* b_qkv = (const float*)d_in[2];
    const float* W_out = (const float*)d_in[3];
    const float* b_out = (const float*)d_in[4];
    float* out = (float*)d_out;

    __half *x16, *wq16, *wo16, *q16, *k16, *v16, *a16;
    cudaGetSymbolAddress((void**)&x16, g_x16);
    cudaGetSymbolAddress((void**)&wq16, g_wq16);
    cudaGetSymbolAddress((void**)&wo16, g_wo16);
    cudaGetSymbolAddress((void**)&q16, g_q16);
    cudaGetSymbolAddress((void**)&k16, g_k16);
    cudaGetSymbolAddress((void**)&v16, g_v16);
    cudaGetSymbolAddress((void**)&a16, g_a16);

    cudaFuncSetAttribute((const void*)mma_gemm<1>,
                         cudaFuncAttributeMaxDynamicSharedMemorySize, GEMM_SMEM);
    cudaFuncSetAttribute((const void*)mma_gemm<0>,
                         cudaFuncAttributeMaxDynamicSharedMemorySize, GEMM_SMEM);
    cudaFuncSetAttribute((const void*)flash_kernel,
                         cudaFuncAttributeMaxDynamicSharedMemorySize, FLASH_SMEM);

    // 1. x -> fp16 ; weights -> fp16 transposed
    to_fp16_kernel<<<2048, 256>>>(x, x16, (size_t)MTOK * DMODEL);
    wtrans_f16_kernel<<<dim3(3 * DMODEL / 32, DMODEL / 32), dim3(32, 8)>>>(
        W_qkv, wq16, DMODEL, 3 * DMODEL);
    wtrans_f16_kernel<<<dim3(DMODEL / 32, DMODEL / 32), dim3(32, 8)>>>(
        W_out, wo16, DMODEL, DMODEL);
    // 2. QKV projection (fp16) with fused per-head scatter epilogue
    mma_gemm<1><<<dim3(3 * DMODEL / 128, MTOK / 128), 256, GEMM_SMEM>>>(
        (const ushort_t*)x16, (const ushort_t*)wq16,
        nullptr, b_qkv, q16, k16, v16, DMODEL, 0);
    // 3. flash attention -> att fp16
    flash_kernel<<<dim3(SEQ / 128, NBH), 256, FLASH_SMEM>>>(q16, k16, v16, a16);
    // 4. out = att @ W_out + b_out (fp16 single pass, fp32 epilogue)
    mma_gemm<0><<<dim3(DMODEL / 128, MTOK / 128), 256, GEMM_SMEM>>>(
        (const ushort_t*)a16, (const ushort_t*)wo16,
        out, b_out, nullptr, nullptr, nullptr, DMODEL, DMODEL);
}

// round 14
// speedup vs baseline: 7.7613x; 1.0240x over previous
#include <cuda_runtime.h>
#include <cuda_bf16.h>
#include <cuda_fp16.h>
#include <cstdint>

// ---------------------------------------------------------------------------
// Problem constants
// ---------------------------------------------------------------------------
#define BATCH 4
#define SEQ   2048
#define NHEAD 16
#define HDIM  64
#define DMODEL 1024
#define MTOK  (BATCH * SEQ)              // 8192
#define NBH   (BATCH * NHEAD)            // 64
#define ATTN_SCALE 0.125f

typedef unsigned short ushort_t;

// ---------------------------------------------------------------------------
// Scratch (static device globals; no allocations allowed)
// ---------------------------------------------------------------------------
__device__ __half g_x16[(size_t)MTOK * DMODEL];              // x fp16
__device__ __half g_wq16[(size_t)3 * DMODEL * DMODEL];       // W_qkv^T fp16
__device__ __half g_wo16[(size_t)DMODEL * DMODEL];           // W_out^T fp16
__device__ __half g_q16[(size_t)NBH * SEQ * HDIM];           // Q*scale fp16
__device__ __half g_k16[(size_t)NBH * SEQ * HDIM];           // K fp16
__device__ __half g_v16[(size_t)NBH * SEQ * HDIM];           // V fp16
__device__ __half g_a16[(size_t)MTOK * DMODEL];              // att fp16

// ---------------------------------------------------------------------------
// PTX helpers (baseline PTX only: cp.async / ldmatrix / mma.sync)
// ---------------------------------------------------------------------------
__device__ __forceinline__ uint32_t smem_u32(const void* p) {
    uint32_t a;
    asm("{ .reg .u64 t; cvta.to.shared.u64 t, %1; cvt.u32.u64 %0, t; }" : "=r"(a) : "l"(p));
    return a;
}
__device__ __forceinline__ void cp16(uint32_t dst, const void* src) {
    asm volatile("cp.async.cg.shared.global [%0], [%1], 16;" :: "r"(dst), "l"(src) : "memory");
}
#define CP_COMMIT() asm volatile("cp.async.commit_group;" ::: "memory")
#define CP_WAIT0()  asm volatile("cp.async.wait_group 0;" ::: "memory")
#define CP_WAIT1()  asm volatile("cp.async.wait_group 1;" ::: "memory")

__device__ __forceinline__ void ldm4(uint32_t a, uint32_t& r0, uint32_t& r1,
                                     uint32_t& r2, uint32_t& r3) {
    asm volatile("ldmatrix.sync.aligned.m8n8.x4.shared.b16 {%0,%1,%2,%3}, [%4];"
                 : "=r"(r0), "=r"(r1), "=r"(r2), "=r"(r3) : "r"(a));
}
__device__ __forceinline__ void ldm4t(uint32_t a, uint32_t& r0, uint32_t& r1,
                                      uint32_t& r2, uint32_t& r3) {
    asm volatile("ldmatrix.sync.aligned.m8n8.x4.trans.shared.b16 {%0,%1,%2,%3}, [%4];"
                 : "=r"(r0), "=r"(r1), "=r"(r2), "=r"(r3) : "r"(a));
}

__device__ __forceinline__ void mma16816(float* c, const uint32_t* a,
                                         uint32_t b0, uint32_t b1) {
    asm volatile(
        "mma.sync.aligned.m16n8k16.row.col.f32.f16.f16.f32 "
        "{%0,%1,%2,%3},{%4,%5,%6,%7},{%8,%9},{%0,%1,%2,%3};"
        : "+f"(c[0]), "+f"(c[1]), "+f"(c[2]), "+f"(c[3])
        : "r"(a[0]), "r"(a[1]), "r"(a[2]), "r"(a[3]), "r"(b0), "r"(b1));
}

// pack two floats to half2 and apply 2^x elementwise (approx, fp16)
__device__ __forceinline__ uint32_t ex2h2(float x, float y) {
    __half2 h = __floats2half2_rn(x, y);
    uint32_t u = *(uint32_t*)&h;
    uint32_t r;
    asm("ex2.approx.f16x2 %0, %1;" : "=r"(r) : "r"(u));
    return r;
}

// ---------------------------------------------------------------------------
// mma.sync GEMM (fp16): 128x128 CTA tile, 8 warps 4(m)x2(n), warp 32x64.
// K-chunk 64, 3-stage cp.async pipeline, one barrier per chunk.
// First k-step fragments are loaded BEFORE the prefetch burst.
//   EPI 0: C fp32 = acc + bias
//   EPI 1: qkv scatter -> q16 (scaled), k16, v16 per-head fp16
// ---------------------------------------------------------------------------
#define STRG 72                 // halves per smem row (64 data + 8 pad)
#define GSTAGE_BYTES (2 * 128 * STRG * 2)   // A + B per stage = 36864
#define GEMM_SMEM (3 * GSTAGE_BYTES)        // 110592

template<int EPI>
__global__ __launch_bounds__(256) void mma_gemm(
    const ushort_t* __restrict__ A, const ushort_t* __restrict__ B,
    float* __restrict__ C, const float* __restrict__ bias,
    __half* __restrict__ oq, __half* __restrict__ ok, __half* __restrict__ ov,
    int K, int ldc)
{
    extern __shared__ __align__(16) ushort_t smg[];

    const int tid = threadIdx.x, lane = tid & 31, wid = tid >> 5;
    const int wm = wid & 3, wn = wid >> 2;            // 4 x 2 warps
    const int m0 = blockIdx.y * 128, n0 = blockIdx.x * 128;
    const int NC = K / 64;

    const uint32_t sbase = smem_u32(smg);

    float acc[2][8][4];
#pragma unroll
    for (int mi = 0; mi < 2; mi++)
#pragma unroll
        for (int j = 0; j < 8; j++)
#pragma unroll
            for (int r = 0; r < 4; r++) acc[mi][j][r] = 0.f;

    auto load_stage = [&](int s, int buf) {
        int k0 = s * 64;
        uint32_t ad = sbase + buf * GSTAGE_BYTES;
        uint32_t bd = ad + 128 * STRG * 2;
#pragma unroll
        for (int i = 0; i < 4; i++) {
            int c = tid + i * 256;
            int r = c >> 3, cc = c & 7;
            cp16(ad + (r * STRG + cc * 8) * 2, A + (size_t)(m0 + r) * K + k0 + cc * 8);
            cp16(bd + (r * STRG + cc * 8) * 2, B + (size_t)(n0 + r) * K + k0 + cc * 8);
        }
    };

    load_stage(0, 0); CP_COMMIT();
    load_stage(1, 1); CP_COMMIT();

    const int lr = (lane & 7) + (((lane >> 3) & 1) << 3);
    const int lc = ((lane >> 4) & 1) << 3;

    int cur = 0, pre = 2;
    for (int c = 0; c < NC; ++c) {
        CP_WAIT1();
        __syncthreads();

        const uint32_t ab = sbase + cur * GSTAGE_BYTES;
        const uint32_t bb = ab + 128 * STRG * 2;

        // peel kk = 0 fragment loads (issue before the prefetch burst)
        uint32_t a0[2][4], b0[4][4];
#pragma unroll
        for (int mi = 0; mi < 2; mi++)
            ldm4(ab + ((wm * 32 + mi * 16 + lr) * STRG + lc) * 2,
                 a0[mi][0], a0[mi][1], a0[mi][2], a0[mi][3]);
#pragma unroll
        for (int nb = 0; nb < 4; nb++)
            ldm4(bb + ((wn * 64 + nb * 16 + lr) * STRG + lc) * 2,
                 b0[nb][0], b0[nb][1], b0[nb][2], b0[nb][3]);

        if (c + 2 < NC) load_stage(c + 2, pre);
        CP_COMMIT();

        // mma kk = 0
#pragma unroll
        for (int mi = 0; mi < 2; mi++)
#pragma unroll
            for (int j = 0; j < 8; j++) {
                int nb = j >> 1, hi = j & 1;
                mma16816(acc[mi][j], a0[mi], b0[nb][hi], b0[nb][2 + hi]);
            }

        // kk = 16, 32, 48
#pragma unroll
        for (int kk = 16; kk < 64; kk += 16) {
            uint32_t a[2][4], b[4][4];
#pragma unroll
            for (int mi = 0; mi < 2; mi++)
                ldm4(ab + ((wm * 32 + mi * 16 + lr) * STRG + kk + lc) * 2,
                     a[mi][0], a[mi][1], a[mi][2], a[mi][3]);
#pragma unroll
            for (int nb = 0; nb < 4; nb++)
                ldm4(bb + ((wn * 64 + nb * 16 + lr) * STRG + kk + lc) * 2,
                     b[nb][0], b[nb][1], b[nb][2], b[nb][3]);
#pragma unroll
            for (int mi = 0; mi < 2; mi++)
#pragma unroll
                for (int j = 0; j < 8; j++) {
                    int nb = j >> 1, hi = j & 1;
                    mma16816(acc[mi][j], a[mi], b[nb][hi], b[nb][2 + hi]);
                }
        }
        cur = (cur == 2) ? 0 : cur + 1;
        pre = (pre == 2) ? 0 : pre + 1;
    }

    const int rq = lane >> 2, cq = (lane & 3) * 2;
#pragma unroll
    for (int mi = 0; mi < 2; mi++)
#pragma unroll
        for (int j = 0; j < 8; j++)
#pragma unroll
            for (int half = 0; half < 2; half++) {
                int row = m0 + wm * 32 + mi * 16 + rq + half * 8;
                int col = n0 + wn * 64 + j * 8 + cq;
                float v0 = acc[mi][j][half * 2 + 0] + bias[col];
                float v1 = acc[mi][j][half * 2 + 1] + bias[col + 1];
                if (EPI == 0) {
                    *(float2*)(C + (size_t)row * ldc + col) = make_float2(v0, v1);
                } else {
                    int seg = col >> 10;            // 0=q 1=k 2=v
                    int ch  = col & 1023;
                    int z   = ((row >> 11) << 4) + (ch >> 6);
                    size_t dst = ((size_t)z * SEQ + (row & 2047)) * HDIM + (ch & 63);
                    if (seg == 0) { v0 *= ATTN_SCALE; v1 *= ATTN_SCALE; }
                    __half2 h = __floats2half2_rn(v0, v1);
                    __half* o = (seg == 0 ? oq : (seg == 1 ? ok : ov));
                    *(__half2*)(o + dst) = h;
                }
            }
}

// ---------------------------------------------------------------------------
// Flash attention (fp16 mma, fp32 accum; exp via ex2.approx.f16x2;
// row-sum l via ones-column MMA; alpha-rescale skipped when max unchanged).
// CTA = 128 q rows of one (b,h); 8 warps x 16 rows.
// KV pipeline stage = 128 keys, processed as TWO 64-key sub-blocks per
// barrier (halves barrier count vs 64-key stages). Double-buffered.
// Q fragments hoisted to registers. Writes att fp16 [token][h*64+d].
// ---------------------------------------------------------------------------
#define STRF 88                 // halves per smem row (64 data + ones/zeros + pad)
#define FQ_BYTES (128 * STRF * 2)
#define FT2_BYTES (128 * STRF * 2)             // 128-key K or V tile
#define FLASH_SMEM (FQ_BYTES + 2 * 2 * FT2_BYTES)  // Q + 2 stages x (K,V) = 112640

__global__ __launch_bounds__(256) void flash_kernel(
    const __half* __restrict__ q16, const __half* __restrict__ k16,
    const __half* __restrict__ v16, __half* __restrict__ att)
{
    extern __shared__ __align__(16) ushort_t smf[];
    const uint32_t qs = smem_u32(smf);
    const uint32_t kv0 = qs + FQ_BYTES;        // stage s: K at kv0+s*2*FT2, V next

    const int tid = threadIdx.x, lane = tid & 31, wid = tid >> 5;
    const int q0 = blockIdx.x * 128;
    const int z  = blockIdx.y;
    const __half* Qg = q16 + (size_t)z * SEQ * HDIM;
    const __half* Kg = k16 + (size_t)z * SEQ * HDIM;
    const __half* Vg = v16 + (size_t)z * SEQ * HDIM;

    // ---- ones column for V (both stages, 128 rows each): col 64 = 1, 65..79 = 0.
    // cp.async fills only cols 0..63, so this survives all iterations.
    for (int i = tid; i < 2 * 128; i += 256) {
        int st = i >> 7, row = i & 127;
        ushort_t* vrow = smf + (FQ_BYTES + (st * 2 + 1) * FT2_BYTES) / 2 + row * STRF;
        vrow[64] = 0x3C00;                     // 1.0h
#pragma unroll
        for (int c2 = 65; c2 < 80; c2++) vrow[c2] = 0;
    }

    // ---- prologue: Q (4 chunks/thread) + KV stage 0 (128 keys), one group
    {
#pragma unroll
        for (int i = 0; i < 4; i++) {
            int cid = tid + i * 256;               // 1024 chunks
            int r = cid >> 3, ccol = cid & 7;
            cp16(qs + (r * STRF + ccol * 8) * 2, Qg + (size_t)(q0 + r) * HDIM + ccol * 8);
        }
        uint32_t kd = kv0, vd = kv0 + FT2_BYTES;
#pragma unroll
        for (int i = 0; i < 4; i++) {
            int cid = tid + i * 256;               // 1024 chunks (128 rows x 8)
            int r = cid >> 3, ccol = cid & 7;
            cp16(kd + (r * STRF + ccol * 8) * 2, Kg + (size_t)r * HDIM + ccol * 8);
            cp16(vd + (r * STRF + ccol * 8) * 2, Vg + (size_t)r * HDIM + ccol * 8);
        }
        CP_COMMIT();
    }

    const int lr = (lane & 7) + (((lane >> 3) & 1) << 3);
    const int lc = ((lane >> 4) & 1) << 3;
    const int qrow = wid * 16;                     // warp's 16 q rows

    // ---- wait prologue, hoist Q fragments into registers
    CP_WAIT0();
    __syncthreads();
    uint32_t qreg[4][4];
#pragma unroll
    for (int t = 0; t < 4; t++)
        ldm4(qs + ((qrow + lr) * STRF + t * 16 + lc) * 2,
             qreg[t][0], qreg[t][1], qreg[t][2], qreg[t][3]);

    float o[8][4], o_l[4];
#pragma unroll
    for (int j = 0; j < 8; j++)
#pragma unroll
        for (int r = 0; r < 4; r++) o[j][r] = 0.f;
#pragma unroll
    for (int r = 0; r < 4; r++) o_l[r] = 0.f;
    float m0 = -1e30f, m1 = -1e30f;

    const float L2E = 1.44269504f;
    const int NKB = SEQ / 128;                     // 16 stages
    for (int kb = 0; kb < NKB; ++kb) {
        if (kb > 0) {
            CP_WAIT0();
            __syncthreads();
        }
        const uint32_t kbuf = kv0 + (kb & 1) * 2 * FT2_BYTES;
        const uint32_t vbuf = kbuf + FT2_BYTES;

        // peel sub-block 0, t = 0 K-fragment loads before prefetch burst
        uint32_t bp[4][4];
#pragma unroll
        for (int nb = 0; nb < 4; nb++)
            ldm4(kbuf + ((nb * 16 + lr) * STRF + lc) * 2,
                 bp[nb][0], bp[nb][1], bp[nb][2], bp[nb][3]);

        if (kb + 1 < NKB) {                        // prefetch next 128-key stage
            uint32_t kd = kv0 + ((kb + 1) & 1) * 2 * FT2_BYTES;
            uint32_t vd = kd + FT2_BYTES;
            const __half* Kn = Kg + (size_t)(kb + 1) * 128 * HDIM;
            const __half* Vn = Vg + (size_t)(kb + 1) * 128 * HDIM;
#pragma unroll
            for (int i = 0; i < 4; i++) {
                int cid = tid + i * 256;
                int r = cid >> 3, ccol = cid & 7;
                cp16(kd + (r * STRF + ccol * 8) * 2, Kn + (size_t)r * HDIM + ccol * 8);
                cp16(vd + (r * STRF + ccol * 8) * 2, Vn + (size_t)r * HDIM + ccol * 8);
            }
        }
        CP_COMMIT();

#pragma unroll
        for (int sb = 0; sb < 2; sb++) {
            const int ro = sb * 64;                // key-row offset within stage

            // ---- S = Q @ K^T (16 x 64 per warp)
            float s[8][4];
#pragma unroll
            for (int j = 0; j < 8; j++)
#pragma unroll
                for (int r = 0; r < 4; r++) s[j][r] = 0.f;
            if (sb == 0) {
#pragma unroll
                for (int j = 0; j < 8; j++) {
                    int nb = j >> 1, hi = j & 1;
                    mma16816(s[j], qreg[0], bp[nb][hi], bp[nb][2 + hi]);
                }
            } else {
                uint32_t b[4][4];
#pragma unroll
                for (int nb = 0; nb < 4; nb++)
                    ldm4(kbuf + ((ro + nb * 16 + lr) * STRF + lc) * 2,
                         b[nb][0], b[nb][1], b[nb][2], b[nb][3]);
#pragma unroll
                for (int j = 0; j < 8; j++) {
                    int nb = j >> 1, hi = j & 1;
                    mma16816(s[j], qreg[0], b[nb][hi], b[nb][2 + hi]);
                }
            }
#pragma unroll
            for (int t = 1; t < 4; t++) {
                uint32_t b[4][4];
#pragma unroll
                for (int nb = 0; nb < 4; nb++)
                    ldm4(kbuf + ((ro + nb * 16 + lr) * STRF + t * 16 + lc) * 2,
                         b[nb][0], b[nb][1], b[nb][2], b[nb][3]);
#pragma unroll
                for (int j = 0; j < 8; j++) {
                    int nb = j >> 1, hi = j & 1;
                    mma16816(s[j], qreg[t], b[nb][hi], b[nb][2 + hi]);
                }
            }

            // ---- online max update (rows r0 = lane>>2, r1 = r0+8)
            float mx0 = -1e30f, mx1 = -1e30f;
#pragma unroll
            for (int j = 0; j < 8; j++) {
                mx0 = fmaxf(mx0, fmaxf(s[j][0], s[j][1]));
                mx1 = fmaxf(mx1, fmaxf(s[j][2], s[j][3]));
            }
            mx0 = fmaxf(mx0, __shfl_xor_sync(0xffffffffu, mx0, 1));
            mx0 = fmaxf(mx0, __shfl_xor_sync(0xffffffffu, mx0, 2));
            mx1 = fmaxf(mx1, __shfl_xor_sync(0xffffffffu, mx1, 1));
            mx1 = fmaxf(mx1, __shfl_xor_sync(0xffffffffu, mx1, 2));
            float mn0 = fmaxf(m0, mx0), mn1 = fmaxf(m1, mx1);
            bool nochange = (mn0 == m0) && (mn1 == m1);
            if (!__all_sync(0xffffffffu, nochange)) {
                float al0 = __expf(m0 - mn0), al1 = __expf(m1 - mn1);
#pragma unroll
                for (int j = 0; j < 8; j++) {
                    o[j][0] *= al0; o[j][1] *= al0;
                    o[j][2] *= al1; o[j][3] *= al1;
                }
                o_l[0] *= al0; o_l[1] *= al0;
                o_l[2] *= al1; o_l[3] *= al1;
            }
            m0 = mn0; m1 = mn1;

            // ---- O += P @ [V | 1]  (P = 2^((s-m)*log2e) in fp16, built inline)
            const float c0 = mn0 * L2E, c1 = mn1 * L2E;
#pragma unroll
            for (int t = 0; t < 4; t++) {
                uint32_t a[4];
                a[0] = ex2h2(s[2 * t][0] * L2E - c0, s[2 * t][1] * L2E - c0);
                a[1] = ex2h2(s[2 * t][2] * L2E - c1, s[2 * t][3] * L2E - c1);
                a[2] = ex2h2(s[2 * t + 1][0] * L2E - c0, s[2 * t + 1][1] * L2E - c0);
                a[3] = ex2h2(s[2 * t + 1][2] * L2E - c1, s[2 * t + 1][3] * L2E - c1);
#pragma unroll
                for (int db = 0; db < 4; db++) {
                    uint32_t r0, r1, r2, r3;
                    ldm4t(vbuf + ((ro + t * 16 + (lane & 15)) * STRF +
                                  db * 16 + ((lane >> 4) & 1) * 8) * 2,
                          r0, r1, r2, r3);
                    mma16816(o[2 * db],     a, r0, r1);
                    mma16816(o[2 * db + 1], a, r2, r3);
                }
                // ones column (cols 64..79): row sums into o_l
                {
                    uint32_t r0, r1, r2, r3;
                    ldm4t(vbuf + ((ro + t * 16 + (lane & 15)) * STRF +
                                  64 + ((lane >> 4) & 1) * 8) * 2,
                          r0, r1, r2, r3);
                    mma16816(o_l, a, r0, r1);
                }
            }
        }
    }

    // ---- epilogue: l lives in o_l col 64 (lanes with lane%4==0); broadcast
    float l0 = __shfl_sync(0xffffffffu, o_l[0], lane & 28);
    float l1 = __shfl_sync(0xffffffffu, o_l[2], lane & 28);
    const float inv0 = 1.0f / l0, inv1 = 1.0f / l1;
    const int b = z >> 4, h = z & 15;
    const int row0 = b * SEQ + q0 + qrow + (lane >> 2);
    const int colb = h * HDIM + (lane & 3) * 2;
#pragma unroll
    for (int j = 0; j < 8; j++) {
        __half2 h0 = __floats2half2_rn(o[j][0] * inv0, o[j][1] * inv0);
        __half2 h1 = __floats2half2_rn(o[j][2] * inv1, o[j][3] * inv1);
        *(__half2*)(att + (size_t)row0 * DMODEL + colb + j * 8) = h0;
        *(__half2*)(att + (size_t)(row0 + 8) * DMODEL + colb + j * 8) = h1;
    }
}

// ---------------------------------------------------------------------------
// Conversion kernels
// ---------------------------------------------------------------------------
__global__ void to_fp16_kernel(const float* __restrict__ x,
                               __half* __restrict__ y, size_t n)
{
    const float4* x4 = (const float4*)x;
    uint2* y4 = (uint2*)y;
    for (size_t i = (size_t)blockIdx.x * blockDim.x + threadIdx.x; i < n / 4;
         i += (size_t)gridDim.x * blockDim.x) {
        float4 f = x4[i];
        __half2 a = __floats2half2_rn(f.x, f.y);
        __half2 b = __floats2half2_rn(f.z, f.w);
        uint2 u;
        u.x = *(uint32_t*)&a;
        u.y = *(uint32_t*)&b;
        y4[i] = u;
    }
}

// W[K][N] -> Wt fp16 [N][K]
__global__ void wtrans_f16_kernel(const float* __restrict__ W,
                                  __half* __restrict__ T, int K, int N)
{
    __shared__ float t[32][33];
    int kx = blockIdx.y * 32, nx = blockIdx.x * 32;
    int tx = threadIdx.x, ty = threadIdx.y;   // (32, 8)
#pragma unroll
    for (int i = 0; i < 4; i++)
        t[ty + 8 * i][tx] = W[(size_t)(kx + ty + 8 * i) * N + nx + tx];
    __syncthreads();
#pragma unroll
    for (int i = 0; i < 4; i++) {
        int nl = ty + 8 * i;
        T[(size_t)(nx + nl) * K + kx + tx] = __float2half(t[tx][nl]);
    }
}

// ---------------------------------------------------------------------------
// Launch
// ---------------------------------------------------------------------------
extern "C" void kernel_launch(void* const* d_in, const int* in_sizes, int n_in,
                              void* d_out, int out_size)
{
    const float* x     = (const float*)d_in[0];
    const float* W_qkv = (const float*)d_in[1];
    const float* b_qkv = (const float*)d_in[2];
    const float* W_out = (const float*)d_in[3];
    const float* b_out = (const float*)d_in[4];
    float* out = (float*)d_out;

    __half *x16, *wq16, *wo16, *q16, *k16, *v16, *a16;
    cudaGetSymbolAddress((void**)&x16, g_x16);
    cudaGetSymbolAddress((void**)&wq16, g_wq16);
    cudaGetSymbolAddress((void**)&wo16, g_wo16);
    cudaGetSymbolAddress((void**)&q16, g_q16);
    cudaGetSymbolAddress((void**)&k16, g_k16);
    cudaGetSymbolAddress((void**)&v16, g_v16);
    cudaGetSymbolAddress((void**)&a16, g_a16);

    cudaFuncSetAttribute((const void*)mma_gemm<1>,
                         cudaFuncAttributeMaxDynamicSharedMemorySize, GEMM_SMEM);
    cudaFuncSetAttribute((const void*)mma_gemm<0>,
                         cudaFuncAttributeMaxDynamicSharedMemorySize, GEMM_SMEM);
    cudaFuncSetAttribute((const void*)flash_kernel,
                         cudaFuncAttributeMaxDynamicSharedMemorySize, FLASH_SMEM);

    // 1. x -> fp16 ; weights -> fp16 transposed
    to_fp16_kernel<<<2048, 256>>>(x, x16, (size_t)MTOK * DMODEL);
    wtrans_f16_kernel<<<dim3(3 * DMODEL / 32, DMODEL / 32), dim3(32, 8)>>>(
        W_qkv, wq16, DMODEL, 3 * DMODEL);
    wtrans_f16_kernel<<<dim3(DMODEL / 32, DMODEL / 32), dim3(32, 8)>>>(
        W_out, wo16, DMODEL, DMODEL);
    // 2. QKV projection (fp16) with fused per-head scatter epilogue
    mma_gemm<1><<<dim3(3 * DMODEL / 128, MTOK / 128), 256, GEMM_SMEM>>>(
        (const ushort_t*)x16, (const ushort_t*)wq16,
        nullptr, b_qkv, q16, k16, v16, DMODEL, 0);
    // 3. flash attention -> att fp16
    flash_kernel<<<dim3(SEQ / 128, NBH), 256, FLASH_SMEM>>>(q16, k16, v16, a16);
    // 4. out = att @ W_out + b_out (fp16 single pass, fp32 epilogue)
    mma_gemm<0><<<dim3(DMODEL / 128, MTOK / 128), 256, GEMM_SMEM>>>(
        (const ushort_t*)a16, (const ushort_t*)wo16,
        out, b_out, nullptr, nullptr, nullptr, DMODEL, DMODEL);
}

// round 15
// speedup vs baseline: 8.0632x; 1.0389x over previous
#include <cuda_runtime.h>
#include <cuda_bf16.h>
#include <cuda_fp16.h>
#include <cstdint>

// ---------------------------------------------------------------------------
// Problem constants
// ---------------------------------------------------------------------------
#define BATCH 4
#define SEQ   2048
#define NHEAD 16
#define HDIM  64
#define DMODEL 1024
#define MTOK  (BATCH * SEQ)              // 8192
#define NBH   (BATCH * NHEAD)            // 64
#define ATTN_SCALE 0.125f

typedef unsigned short ushort_t;

// ---------------------------------------------------------------------------
// Scratch (static device globals; no allocations allowed)
// ---------------------------------------------------------------------------
__device__ __half g_x16[(size_t)MTOK * DMODEL];              // x fp16
__device__ __half g_wq16[(size_t)3 * DMODEL * DMODEL];       // W_qkv^T fp16
__device__ __half g_wo16[(size_t)DMODEL * DMODEL];           // W_out^T fp16
__device__ __half g_q16[(size_t)NBH * SEQ * HDIM];           // Q*scale fp16
__device__ __half g_k16[(size_t)NBH * SEQ * HDIM];           // K fp16
__device__ __half g_v16[(size_t)NBH * SEQ * HDIM];           // V fp16
__device__ __half g_a16[(size_t)MTOK * DMODEL];              // att fp16

// ---------------------------------------------------------------------------
// PTX helpers (baseline PTX only: cp.async / ldmatrix / mma.sync)
// ---------------------------------------------------------------------------
__device__ __forceinline__ uint32_t smem_u32(const void* p) {
    uint32_t a;
    asm("{ .reg .u64 t; cvta.to.shared.u64 t, %1; cvt.u32.u64 %0, t; }" : "=r"(a) : "l"(p));
    return a;
}
__device__ __forceinline__ void cp16(uint32_t dst, const void* src) {
    asm volatile("cp.async.cg.shared.global [%0], [%1], 16;" :: "r"(dst), "l"(src) : "memory");
}
#define CP_COMMIT() asm volatile("cp.async.commit_group;" ::: "memory")
#define CP_WAIT0()  asm volatile("cp.async.wait_group 0;" ::: "memory")
#define CP_WAIT1()  asm volatile("cp.async.wait_group 1;" ::: "memory")

__device__ __forceinline__ void ldm4(uint32_t a, uint32_t& r0, uint32_t& r1,
                                     uint32_t& r2, uint32_t& r3) {
    asm volatile("ldmatrix.sync.aligned.m8n8.x4.shared.b16 {%0,%1,%2,%3}, [%4];"
                 : "=r"(r0), "=r"(r1), "=r"(r2), "=r"(r3) : "r"(a));
}
__device__ __forceinline__ void ldm4t(uint32_t a, uint32_t& r0, uint32_t& r1,
                                      uint32_t& r2, uint32_t& r3) {
    asm volatile("ldmatrix.sync.aligned.m8n8.x4.trans.shared.b16 {%0,%1,%2,%3}, [%4];"
                 : "=r"(r0), "=r"(r1), "=r"(r2), "=r"(r3) : "r"(a));
}

__device__ __forceinline__ void mma16816(float* c, const uint32_t* a,
                                         uint32_t b0, uint32_t b1) {
    asm volatile(
        "mma.sync.aligned.m16n8k16.row.col.f32.f16.f16.f32 "
        "{%0,%1,%2,%3},{%4,%5,%6,%7},{%8,%9},{%0,%1,%2,%3};"
        : "+f"(c[0]), "+f"(c[1]), "+f"(c[2]), "+f"(c[3])
        : "r"(a[0]), "r"(a[1]), "r"(a[2]), "r"(a[3]), "r"(b0), "r"(b1));
}

// pack two floats to half2 and apply 2^x elementwise (approx, fp16)
__device__ __forceinline__ uint32_t ex2h2(float x, float y) {
    __half2 h = __floats2half2_rn(x, y);
    uint32_t u = *(uint32_t*)&h;
    uint32_t r;
    asm("ex2.approx.f16x2 %0, %1;" : "=r"(r) : "r"(u));
    return r;
}

// ---------------------------------------------------------------------------
// mma.sync GEMM (fp16): 128x128 CTA tile, 8 warps 4(m)x2(n), warp 32x64.
// K-chunk 64, 3-stage cp.async pipeline, one barrier per chunk.
// Prefetch burst SPREAD across the four k-steps (2 cp16 per step) so the
// LSU dispatch queue never collides with the LDSM/MMA issue stream.
//   EPI 0: C fp32 = acc + bias
//   EPI 1: qkv scatter -> q16 (scaled), k16, v16 per-head fp16
// ---------------------------------------------------------------------------
#define STRG 72                 // halves per smem row (64 data + 8 pad)
#define GSTAGE_BYTES (2 * 128 * STRG * 2)   // A + B per stage = 36864
#define GEMM_SMEM (3 * GSTAGE_BYTES)        // 110592

template<int EPI>
__global__ __launch_bounds__(256) void mma_gemm(
    const ushort_t* __restrict__ A, const ushort_t* __restrict__ B,
    float* __restrict__ C, const float* __restrict__ bias,
    __half* __restrict__ oq, __half* __restrict__ ok, __half* __restrict__ ov,
    int K, int ldc)
{
    extern __shared__ __align__(16) ushort_t smg[];

    const int tid = threadIdx.x, lane = tid & 31, wid = tid >> 5;
    const int wm = wid & 3, wn = wid >> 2;            // 4 x 2 warps
    const int m0 = blockIdx.y * 128, n0 = blockIdx.x * 128;
    const int NC = K / 64;

    const uint32_t sbase = smem_u32(smg);

    float acc[2][8][4];
#pragma unroll
    for (int mi = 0; mi < 2; mi++)
#pragma unroll
        for (int j = 0; j < 8; j++)
#pragma unroll
            for (int r = 0; r < 4; r++) acc[mi][j][r] = 0.f;

    // one A + one B 16B chunk (1/4 of a stage's per-thread work)
    auto load_part = [&](int s, int buf, int i) {
        int k0 = s * 64;
        uint32_t ad = sbase + buf * GSTAGE_BYTES;
        uint32_t bd = ad + 128 * STRG * 2;
        int c = tid + i * 256;
        int r = c >> 3, cc = c & 7;
        cp16(ad + (r * STRG + cc * 8) * 2, A + (size_t)(m0 + r) * K + k0 + cc * 8);
        cp16(bd + (r * STRG + cc * 8) * 2, B + (size_t)(n0 + r) * K + k0 + cc * 8);
    };

#pragma unroll
    for (int i = 0; i < 4; i++) load_part(0, 0, i);
    CP_COMMIT();
#pragma unroll
    for (int i = 0; i < 4; i++) load_part(1, 1, i);
    CP_COMMIT();

    const int lr = (lane & 7) + (((lane >> 3) & 1) << 3);
    const int lc = ((lane >> 4) & 1) << 3;

    int cur = 0, pre = 2;
    for (int c = 0; c < NC; ++c) {
        CP_WAIT1();
        __syncthreads();

        const uint32_t ab = sbase + cur * GSTAGE_BYTES;
        const uint32_t bb = ab + 128 * STRG * 2;
        const bool pf = (c + 2 < NC);

        // peel kk = 0 fragment loads
        uint32_t a0[2][4], b0[4][4];
#pragma unroll
        for (int mi = 0; mi < 2; mi++)
            ldm4(ab + ((wm * 32 + mi * 16 + lr) * STRG + lc) * 2,
                 a0[mi][0], a0[mi][1], a0[mi][2], a0[mi][3]);
#pragma unroll
        for (int nb = 0; nb < 4; nb++)
            ldm4(bb + ((wn * 64 + nb * 16 + lr) * STRG + lc) * 2,
                 b0[nb][0], b0[nb][1], b0[nb][2], b0[nb][3]);

        if (pf) load_part(c + 2, pre, 0);     // 2 cp16 in the LDSM shadow

        // mma kk = 0
#pragma unroll
        for (int mi = 0; mi < 2; mi++)
#pragma unroll
            for (int j = 0; j < 8; j++) {
                int nb = j >> 1, hi = j & 1;
                mma16816(acc[mi][j], a0[mi], b0[nb][hi], b0[nb][2 + hi]);
            }

        // kk = 16, 32, 48 with 2 cp16 interleaved per step
#pragma unroll
        for (int kk = 16; kk < 64; kk += 16) {
            uint32_t a[2][4], b[4][4];
#pragma unroll
            for (int mi = 0; mi < 2; mi++)
                ldm4(ab + ((wm * 32 + mi * 16 + lr) * STRG + kk + lc) * 2,
                     a[mi][0], a[mi][1], a[mi][2], a[mi][3]);
#pragma unroll
            for (int nb = 0; nb < 4; nb++)
                ldm4(bb + ((wn * 64 + nb * 16 + lr) * STRG + kk + lc) * 2,
                     b[nb][0], b[nb][1], b[nb][2], b[nb][3]);
            if (pf) load_part(c + 2, pre, kk >> 4);
#pragma unroll
            for (int mi = 0; mi < 2; mi++)
#pragma unroll
                for (int j = 0; j < 8; j++) {
                    int nb = j >> 1, hi = j & 1;
                    mma16816(acc[mi][j], a[mi], b[nb][hi], b[nb][2 + hi]);
                }
        }
        CP_COMMIT();
        cur = (cur == 2) ? 0 : cur + 1;
        pre = (pre == 2) ? 0 : pre + 1;
    }

    const int rq = lane >> 2, cq = (lane & 3) * 2;
#pragma unroll
    for (int mi = 0; mi < 2; mi++)
#pragma unroll
        for (int j = 0; j < 8; j++)
#pragma unroll
            for (int half = 0; half < 2; half++) {
                int row = m0 + wm * 32 + mi * 16 + rq + half * 8;
                int col = n0 + wn * 64 + j * 8 + cq;
                float v0 = acc[mi][j][half * 2 + 0] + bias[col];
                float v1 = acc[mi][j][half * 2 + 1] + bias[col + 1];
                if (EPI == 0) {
                    *(float2*)(C + (size_t)row * ldc + col) = make_float2(v0, v1);
                } else {
                    int seg = col >> 10;            // 0=q 1=k 2=v
                    int ch  = col & 1023;
                    int z   = ((row >> 11) << 4) + (ch >> 6);
                    size_t dst = ((size_t)z * SEQ + (row & 2047)) * HDIM + (ch & 63);
                    if (seg == 0) { v0 *= ATTN_SCALE; v1 *= ATTN_SCALE; }
                    __half2 h = __floats2half2_rn(v0, v1);
                    __half* o = (seg == 0 ? oq : (seg == 1 ? ok : ov));
                    *(__half2*)(o + dst) = h;
                }
            }
}

// ---------------------------------------------------------------------------
// Flash attention (fp16 mma, fp32 accum; exp via ex2.approx.f16x2;
// row-sum l via ones-column MMA; alpha-rescale skipped when max unchanged).
// CTA = 128 q rows of one (b,h); 8 warps x 16 rows.
// KV pipeline stage = 128 keys, two 64-key sub-blocks per barrier.
// Prefetch burst spread through sub-block 0's k-steps.
// Q fragments hoisted to registers. Writes att fp16 [token][h*64+d].
// ---------------------------------------------------------------------------
#define STRF 88                 // halves per smem row (64 data + ones/zeros + pad)
#define FQ_BYTES (128 * STRF * 2)
#define FT2_BYTES (128 * STRF * 2)             // 128-key K or V tile
#define FLASH_SMEM (FQ_BYTES + 2 * 2 * FT2_BYTES)  // Q + 2 stages x (K,V) = 112640

__global__ __launch_bounds__(256) void flash_kernel(
    const __half* __restrict__ q16, const __half* __restrict__ k16,
    const __half* __restrict__ v16, __half* __restrict__ att)
{
    extern __shared__ __align__(16) ushort_t smf[];
    const uint32_t qs = smem_u32(smf);
    const uint32_t kv0 = qs + FQ_BYTES;        // stage s: K at kv0+s*2*FT2, V next

    const int tid = threadIdx.x, lane = tid & 31, wid = tid >> 5;
    const int q0 = blockIdx.x * 128;
    const int z  = blockIdx.y;
    const __half* Qg = q16 + (size_t)z * SEQ * HDIM;
    const __half* Kg = k16 + (size_t)z * SEQ * HDIM;
    const __half* Vg = v16 + (size_t)z * SEQ * HDIM;

    // ---- ones column for V (both stages, 128 rows): col 64 = 1, 65..79 = 0.
    for (int i = tid; i < 2 * 128; i += 256) {
        int st = i >> 7, row = i & 127;
        ushort_t* vrow = smf + (FQ_BYTES + (st * 2 + 1) * FT2_BYTES) / 2 + row * STRF;
        vrow[64] = 0x3C00;                     // 1.0h
#pragma unroll
        for (int c2 = 65; c2 < 80; c2++) vrow[c2] = 0;
    }

    // one K + one V 16B chunk of stage buf (1/4 of per-thread work)
    auto load_part = [&](int kb, int buf, int i) {
        uint32_t kd = kv0 + buf * 2 * FT2_BYTES;
        uint32_t vd = kd + FT2_BYTES;
        const __half* Kn = Kg + (size_t)kb * 128 * HDIM;
        const __half* Vn = Vg + (size_t)kb * 128 * HDIM;
        int cid = tid + i * 256;
        int r = cid >> 3, ccol = cid & 7;
        cp16(kd + (r * STRF + ccol * 8) * 2, Kn + (size_t)r * HDIM + ccol * 8);
        cp16(vd + (r * STRF + ccol * 8) * 2, Vn + (size_t)r * HDIM + ccol * 8);
    };

    // ---- prologue: Q (4 chunks/thread) + KV stage 0 (128 keys), one group
    {
#pragma unroll
        for (int i = 0; i < 4; i++) {
            int cid = tid + i * 256;               // 1024 chunks
            int r = cid >> 3, ccol = cid & 7;
            cp16(qs + (r * STRF + ccol * 8) * 2, Qg + (size_t)(q0 + r) * HDIM + ccol * 8);
        }
#pragma unroll
        for (int i = 0; i < 4; i++) load_part(0, 0, i);
        CP_COMMIT();
    }

    const int lr = (lane & 7) + (((lane >> 3) & 1) << 3);
    const int lc = ((lane >> 4) & 1) << 3;
    const int qrow = wid * 16;                     // warp's 16 q rows

    // ---- wait prologue, hoist Q fragments into registers
    CP_WAIT0();
    __syncthreads();
    uint32_t qreg[4][4];
#pragma unroll
    for (int t = 0; t < 4; t++)
        ldm4(qs + ((qrow + lr) * STRF + t * 16 + lc) * 2,
             qreg[t][0], qreg[t][1], qreg[t][2], qreg[t][3]);

    float o[8][4], o_l[4];
#pragma unroll
    for (int j = 0; j < 8; j++)
#pragma unroll
        for (int r = 0; r < 4; r++) o[j][r] = 0.f;
#pragma unroll
    for (int r = 0; r < 4; r++) o_l[r] = 0.f;
    float m0 = -1e30f, m1 = -1e30f;

    const float L2E = 1.44269504f;
    const int NKB = SEQ / 128;                     // 16 stages
    for (int kb = 0; kb < NKB; ++kb) {
        if (kb > 0) {
            CP_WAIT0();
            __syncthreads();
        }
        const uint32_t kbuf = kv0 + (kb & 1) * 2 * FT2_BYTES;
        const uint32_t vbuf = kbuf + FT2_BYTES;
        const bool pf = (kb + 1 < NKB);
        const int pbuf = (kb + 1) & 1;

#pragma unroll
        for (int sb = 0; sb < 2; sb++) {
            const int ro = sb * 64;                // key-row offset within stage

            // ---- S = Q @ K^T (16 x 64 per warp); prefetch spread in sb 0
            float s[8][4];
#pragma unroll
            for (int j = 0; j < 8; j++)
#pragma unroll
                for (int r = 0; r < 4; r++) s[j][r] = 0.f;
#pragma unroll
            for (int t = 0; t < 4; t++) {
                uint32_t b[4][4];
#pragma unroll
                for (int nb = 0; nb < 4; nb++)
                    ldm4(kbuf + ((ro + nb * 16 + lr) * STRF + t * 16 + lc) * 2,
                         b[nb][0], b[nb][1], b[nb][2], b[nb][3]);
                if (sb == 0 && pf) load_part(kb + 1, pbuf, t);
#pragma unroll
                for (int j = 0; j < 8; j++) {
                    int nb = j >> 1, hi = j & 1;
                    mma16816(s[j], qreg[t], b[nb][hi], b[nb][2 + hi]);
                }
            }
            if (sb == 0) CP_COMMIT();

            // ---- online max update (rows r0 = lane>>2, r1 = r0+8)
            float mx0 = -1e30f, mx1 = -1e30f;
#pragma unroll
            for (int j = 0; j < 8; j++) {
                mx0 = fmaxf(mx0, fmaxf(s[j][0], s[j][1]));
                mx1 = fmaxf(mx1, fmaxf(s[j][2], s[j][3]));
            }
            mx0 = fmaxf(mx0, __shfl_xor_sync(0xffffffffu, mx0, 1));
            mx0 = fmaxf(mx0, __shfl_xor_sync(0xffffffffu, mx0, 2));
            mx1 = fmaxf(mx1, __shfl_xor_sync(0xffffffffu, mx1, 1));
            mx1 = fmaxf(mx1, __shfl_xor_sync(0xffffffffu, mx1, 2));
            float mn0 = fmaxf(m0, mx0), mn1 = fmaxf(m1, mx1);
            bool nochange = (mn0 == m0) && (mn1 == m1);
            if (!__all_sync(0xffffffffu, nochange)) {
                float al0 = __expf(m0 - mn0), al1 = __expf(m1 - mn1);
#pragma unroll
                for (int j = 0; j < 8; j++) {
                    o[j][0] *= al0; o[j][1] *= al0;
                    o[j][2] *= al1; o[j][3] *= al1;
                }
                o_l[0] *= al0; o_l[1] *= al0;
                o_l[2] *= al1; o_l[3] *= al1;
            }
            m0 = mn0; m1 = mn1;

            // ---- O += P @ [V | 1]  (P = 2^((s-m)*log2e) in fp16, built inline)
            const float c0 = mn0 * L2E, c1 = mn1 * L2E;
#pragma unroll
            for (int t = 0; t < 4; t++) {
                uint32_t a[4];
                a[0] = ex2h2(s[2 * t][0] * L2E - c0, s[2 * t][1] * L2E - c0);
                a[1] = ex2h2(s[2 * t][2] * L2E - c1, s[2 * t][3] * L2E - c1);
                a[2] = ex2h2(s[2 * t + 1][0] * L2E - c0, s[2 * t + 1][1] * L2E - c0);
                a[3] = ex2h2(s[2 * t + 1][2] * L2E - c1, s[2 * t + 1][3] * L2E - c1);
#pragma unroll
                for (int db = 0; db < 4; db++) {
                    uint32_t r0, r1, r2, r3;
                    ldm4t(vbuf + ((ro + t * 16 + (lane & 15)) * STRF +
                                  db * 16 + ((lane >> 4) & 1) * 8) * 2,
                          r0, r1, r2, r3);
                    mma16816(o[2 * db],     a, r0, r1);
                    mma16816(o[2 * db + 1], a, r2, r3);
                }
                // ones column (cols 64..79): row sums into o_l
                {
                    uint32_t r0, r1, r2, r3;
                    ldm4t(vbuf + ((ro + t * 16 + (lane & 15)) * STRF +
                                  64 + ((lane >> 4) & 1) * 8) * 2,
                          r0, r1, r2, r3);
                    mma16816(o_l, a, r0, r1);
                }
            }
        }
    }

    // ---- epilogue: l lives in o_l col 64 (lanes with lane%4==0); broadcast
    float l0 = __shfl_sync(0xffffffffu, o_l[0], lane & 28);
    float l1 = __shfl_sync(0xffffffffu, o_l[2], lane & 28);
    const float inv0 = 1.0f / l0, inv1 = 1.0f / l1;
    const int b = z >> 4, h = z & 15;
    const int row0 = b * SEQ + q0 + qrow + (lane >> 2);
    const int colb = h * HDIM + (lane & 3) * 2;
#pragma unroll
    for (int j = 0; j < 8; j++) {
        __half2 h0 = __floats2half2_rn(o[j][0] * inv0, o[j][1] * inv0);
        __half2 h1 = __floats2half2_rn(o[j][2] * inv1, o[j][3] * inv1);
        *(__half2*)(att + (size_t)row0 * DMODEL + colb + j * 8) = h0;
        *(__half2*)(att + (size_t)(row0 + 8) * DMODEL + colb + j * 8) = h1;
    }
}

// ---------------------------------------------------------------------------
// Conversion kernels
// ---------------------------------------------------------------------------
__global__ void to_fp16_kernel(const float* __restrict__ x,
                               __half* __restrict__ y, size_t n)
{
    const float4* x4 = (const float4*)x;
    uint2* y4 = (uint2*)y;
    for (size_t i = (size_t)blockIdx.x * blockDim.x + threadIdx.x; i < n / 4;
         i += (size_t)gridDim.x * blockDim.x) {
        float4 f = x4[i];
        __half2 a = __floats2half2_rn(f.x, f.y);
        __half2 b = __floats2half2_rn(f.z, f.w);
        uint2 u;
        u.x = *(uint32_t*)&a;
        u.y = *(uint32_t*)&b;
        y4[i] = u;
    }
}

// Both weight transposes in one launch: z=0 -> W_qkv (N=3072), z=1 -> W_out
__global__ void wtrans_f16_kernel(const float* __restrict__ Wq,
                                  const float* __restrict__ Wo,
                                  __half* __restrict__ Tq,
                                  __half* __restrict__ To, int K)
{
    __shared__ float t[32][33];
    const float* W = (blockIdx.z == 0) ? Wq : Wo;
    __half* T = (blockIdx.z == 0) ? Tq : To;
    int N = (blockIdx.z == 0) ? 3 * DMODEL : DMODEL;
    if (blockIdx.x * 32 >= N) return;
    int kx = blockIdx.y * 32, nx = blockIdx.x * 32;
    int tx = threadIdx.x, ty = threadIdx.y;   // (32, 8)
#pragma unroll
    for (int i = 0; i < 4; i++)
        t[ty + 8 * i][tx] = W[(size_t)(kx + ty + 8 * i) * N + nx + tx];
    __syncthreads();
#pragma unroll
    for (int i = 0; i < 4; i++) {
        int nl = ty + 8 * i;
        T[(size_t)(nx + nl) * K + kx + tx] = __float2half(t[tx][nl]);
    }
}

// ---------------------------------------------------------------------------
// Launch
// ---------------------------------------------------------------------------
extern "C" void kernel_launch(void* const* d_in, const int* in_sizes, int n_in,
                              void* d_out, int out_size)
{
    const float* x     = (const float*)d_in[0];
    const float* W_qkv = (const float*)d_in[1];
    const float* b_qkv = (const float*)d_in[2];
    const float* W_out = (const float*)d_in[3];
    const float* b_out = (const float*)d_in[4];
    float* out = (float*)d_out;

    __half *x16, *wq16, *wo16, *q16, *k16, *v16, *a16;
    cudaGetSymbolAddress((void**)&x16, g_x16);
    cudaGetSymbolAddress((void**)&wq16, g_wq16);
    cudaGetSymbolAddress((void**)&wo16, g_wo16);
    cudaGetSymbolAddress((void**)&q16, g_q16);
    cudaGetSymbolAddress((void**)&k16, g_k16);
    cudaGetSymbolAddress((void**)&v16, g_v16);
    cudaGetSymbolAddress((void**)&a16, g_a16);

    cudaFuncSetAttribute((const void*)mma_gemm<1>,
                         cudaFuncAttributeMaxDynamicSharedMemorySize, GEMM_SMEM);
    cudaFuncSetAttribute((const void*)mma_gemm<0>,
                         cudaFuncAttributeMaxDynamicSharedMemorySize, GEMM_SMEM);
    cudaFuncSetAttribute((const void*)flash_kernel,
                         cudaFuncAttributeMaxDynamicSharedMemorySize, FLASH_SMEM);

    // 1. x -> fp16 ; weights -> fp16 transposed (one fused launch)
    to_fp16_kernel<<<2048, 256>>>(x, x16, (size_t)MTOK * DMODEL);
    wtrans_f16_kernel<<<dim3(3 * DMODEL / 32, DMODEL / 32, 2), dim3(32, 8)>>>(
        W_qkv, W_out, wq16, wo16, DMODEL);
    // 2. QKV projection (fp16) with fused per-head scatter epilogue
    mma_gemm<1><<<dim3(3 * DMODEL / 128, MTOK / 128), 256, GEMM_SMEM>>>(
        (const ushort_t*)x16, (const ushort_t*)wq16,
        nullptr, b_qkv, q16, k16, v16, DMODEL, 0);
    // 3. flash attention -> att fp16
    flash_kernel<<<dim3(SEQ / 128, NBH), 256, FLASH_SMEM>>>(q16, k16, v16, a16);
    // 4. out = att @ W_out + b_out (fp16 single pass, fp32 epilogue)
    mma_gemm<0><<<dim3(DMODEL / 128, MTOK / 128), 256, GEMM_SMEM>>>(
        (const ushort_t*)a16, (const ushort_t*)wo16,
        out, b_out, nullptr, nullptr, nullptr, DMODEL, DMODEL);
}